// round 1
// baseline (speedup 1.0000x reference)
#include <cuda_runtime.h>
#include <math.h>
#include <stdint.h>

// ---------------- problem constants ----------------
#define SEQ 128
#define BB  256
#define ED  512
#define FD  2048
#define NH  8
#define HD  64
#define NR  (SEQ*BB)   // 32768 rows

static __device__ __forceinline__ float maxnorm() { return (float)(1.0 - 1e-5); }

// ---------------- scratch (device globals; no allocation allowed) ----------------
__device__ float g_h0 [(size_t)NR*ED];
__device__ float g_q  [(size_t)NR*ED];
__device__ float g_k  [(size_t)NR*ED];
__device__ float g_v  [(size_t)NR*ED];
__device__ float g_o  [(size_t)NR*ED];
__device__ float g_h1 [(size_t)NR*ED];
__device__ float g_h2 [(size_t)NR*ED];
__device__ float g_big[(size_t)NR*FD];
__device__ float g_n0 [NR];
__device__ float g_no [NR];
__device__ float g_nh2[NR];
__device__ float g_nh3[NR];
__device__ float g_b2 [8];

#define FLAG_LOGMAP  1
#define FLAG_MOBRELU 2
#define FLAG_RESID   4

// ---------------- block reduction (double accumulate) ----------------
template <int T>
__device__ __forceinline__ double blockSum(double v) {
    __shared__ double sh[T / 32];
    #pragma unroll
    for (int o = 16; o > 0; o >>= 1) v += __shfl_xor_sync(0xffffffffu, v, o);
    int lane = threadIdx.x & 31, w = threadIdx.x >> 5;
    if (lane == 0) sh[w] = v;
    __syncthreads();
    if (threadIdx.x < 32) {
        double t = (threadIdx.x < T / 32) ? sh[threadIdx.x] : 0.0;
        #pragma unroll
        for (int o = 16; o > 0; o >>= 1) t += __shfl_xor_sync(0xffffffffu, t, o);
        if (threadIdx.x == 0) sh[0] = t;
    }
    __syncthreads();
    double r = sh[0];
    __syncthreads();
    return r;
}

// ---------------- bias squared-norm ----------------
__global__ void sqsum_kernel(const float* __restrict__ v, int n, float* __restrict__ out) {
    double s = 0.0;
    for (int i = threadIdx.x; i < n; i += 256) { double x = v[i]; s += x * x; }
    s = blockSum<256>(s);
    if (threadIdx.x == 0) *out = (float)s;
}

// ---------------- ln block: expmap0(layernorm(logmap0(x))) [+projx], stores row norm ----------------
template <int E, int T>
__global__ void __launch_bounds__(T) ln_kernel(
    const float* __restrict__ x, const float* __restrict__ g, const float* __restrict__ b,
    float* __restrict__ out, float* __restrict__ out_norm, int do_projx)
{
    constexpr int V = E / T;
    const size_t row = blockIdx.x;
    const int tid = threadIdx.x;
    const float MAXN = maxnorm();
    float v[V];
    double ss = 0.0;
    #pragma unroll
    for (int i = 0; i < V; i++) { v[i] = x[row*E + tid + i*T]; ss += (double)v[i]*v[i]; }
    float n0 = (float)sqrt(blockSum<T>(ss) + 1e-30);
    float lf = atanhf(fminf(n0, MAXN)) / n0;
    double sm = 0.0;
    #pragma unroll
    for (int i = 0; i < V; i++) { v[i] *= lf; sm += (double)v[i]; }
    float mu = (float)(blockSum<T>(sm) / (double)E);
    double vv = 0.0;
    #pragma unroll
    for (int i = 0; i < V; i++) { float d = v[i] - mu; vv += (double)d*d; }
    float var = (float)(blockSum<T>(vv) / (double)E);
    float inv = rsqrtf(var + 1e-5f);
    double s2 = 0.0;
    #pragma unroll
    for (int i = 0; i < V; i++) {
        int idx = tid + i*T;
        v[i] = (v[i] - mu) * inv * g[idx] + b[idx];
        s2 += (double)v[i]*v[i];
    }
    float ny = (float)sqrt(blockSum<T>(s2) + 1e-30);
    float ef = tanhf(ny) / ny;
    #pragma unroll
    for (int i = 0; i < V; i++) v[i] *= ef;
    if (do_projx) {
        double s3 = 0.0;
        #pragma unroll
        for (int i = 0; i < V; i++) s3 += (double)v[i]*v[i];
        float n = (float)sqrt(blockSum<T>(s3) + 1e-30);
        if (n > MAXN) { float ps = MAXN / n; 
            #pragma unroll
            for (int i = 0; i < V; i++) v[i] *= ps; }
    }
    double s4 = 0.0;
    #pragma unroll
    for (int i = 0; i < V; i++) { out[row*E + tid + i*T] = v[i]; s4 += (double)v[i]*v[i]; }
    float nf = (float)sqrt(blockSum<T>(s4) + 1e-30);
    if (tid == 0) out_norm[row] = nf;
}

// ---------------- expmap0 rows (attention output), stores row norm ----------------
template <int E, int T>
__global__ void __launch_bounds__(T) expmap_rows(float* __restrict__ x, float* __restrict__ out_norm)
{
    constexpr int V = E / T;
    const size_t row = blockIdx.x;
    const int tid = threadIdx.x;
    float v[V];
    double ss = 0.0;
    #pragma unroll
    for (int i = 0; i < V; i++) { v[i] = x[row*E + tid + i*T]; ss += (double)v[i]*v[i]; }
    float n = (float)sqrt(blockSum<T>(ss) + 1e-30);
    float ef = tanhf(n) / n;
    double s2 = 0.0;
    #pragma unroll
    for (int i = 0; i < V; i++) { v[i] *= ef; x[row*E + tid + i*T] = v[i]; s2 += (double)v[i]*v[i]; }
    float nf = (float)sqrt(blockSum<T>(s2) + 1e-30);
    if (tid == 0) out_norm[row] = nf;
}

// ---------------- man_linear epilogue (+ optional mob_relu / residual möbius-add / logmap0) ----------------
template <int E, int T>
__global__ void __launch_bounds__(T) manlin_epi(
    const float* __restrict__ mx, const float* __restrict__ xnb,
    const float* __restrict__ bias, int b2idx,
    const float* __restrict__ resid,
    float* __restrict__ out, float* __restrict__ out_norm, int flags)
{
    constexpr int V = E / T;
    const size_t row = blockIdx.x;
    const int tid = threadIdx.x;
    const float MAXN = maxnorm();
    float v[V], bv[V];
    double ss = 0.0;
    #pragma unroll
    for (int i = 0; i < V; i++) { v[i] = mx[row*E + tid + i*T]; ss += (double)v[i]*v[i]; }
    float mxn = (float)sqrt(blockSum<T>(ss) + 1e-30);
    float xn = xnb[row];
    float s = tanhf(mxn / xn * atanhf(fminf(xn, MAXN))) / mxn;
    // m = s*mx ; mobius_add(m, bias)
    double dxy = 0.0, dx2 = 0.0;
    #pragma unroll
    for (int i = 0; i < V; i++) {
        v[i] = s * v[i];
        bv[i] = bias[tid + i*T];
        dxy += (double)v[i]*bv[i];
        dx2 += (double)v[i]*v[i];
    }
    float xy = (float)blockSum<T>(dxy);
    float x2 = (float)blockSum<T>(dx2);
    float y2 = g_b2[b2idx];
    float a = 1.0f + 2.0f*xy + y2;
    float c = 1.0f - x2;
    float den = fmaxf(1.0f + 2.0f*xy + x2*y2, 1e-15f);
    float invd = 1.0f / den;
    double zz = 0.0;
    #pragma unroll
    for (int i = 0; i < V; i++) { v[i] = (a*v[i] + c*bv[i]) * invd; zz += (double)v[i]*v[i]; }
    // projx
    {
        float zn = (float)sqrt(blockSum<T>(zz) + 1e-30);
        if (zn > MAXN) { float ps = MAXN / zn;
            #pragma unroll
            for (int i = 0; i < V; i++) v[i] *= ps; }
    }
    if (flags & FLAG_MOBRELU) {
        // logmap0
        double s0 = 0.0;
        #pragma unroll
        for (int i = 0; i < V; i++) s0 += (double)v[i]*v[i];
        float n = (float)sqrt(blockSum<T>(s0) + 1e-30);
        float lf = atanhf(fminf(n, MAXN)) / n;
        // relu
        double s1 = 0.0;
        #pragma unroll
        for (int i = 0; i < V; i++) { v[i] = fmaxf(lf * v[i], 0.0f); s1 += (double)v[i]*v[i]; }
        // expmap0
        float nr = (float)sqrt(blockSum<T>(s1) + 1e-30);
        float ef = tanhf(nr) / nr;
        double s2 = 0.0;
        #pragma unroll
        for (int i = 0; i < V; i++) { v[i] *= ef; s2 += (double)v[i]*v[i]; }
        // projx
        float n2 = (float)sqrt(blockSum<T>(s2) + 1e-30);
        if (n2 > MAXN) { float ps = MAXN / n2;
            #pragma unroll
            for (int i = 0; i < V; i++) v[i] *= ps; }
    }
    if (flags & FLAG_RESID) {
        const float* rr = resid + row*E;
        float rv[V];
        double d1 = 0.0, d2 = 0.0, d3 = 0.0;
        #pragma unroll
        for (int i = 0; i < V; i++) {
            rv[i] = rr[tid + i*T];
            d1 += (double)v[i]*rv[i];
            d2 += (double)rv[i]*rv[i];
            d3 += (double)v[i]*v[i];
        }
        float rxy = (float)blockSum<T>(d1);
        float ry2 = (float)blockSum<T>(d2);
        float rx2 = (float)blockSum<T>(d3);
        float ra = 1.0f + 2.0f*rxy + ry2;
        float rc = 1.0f - rx2;
        float rden = fmaxf(1.0f + 2.0f*rxy + rx2*ry2, 1e-15f);
        float rinv = 1.0f / rden;
        double s3 = 0.0;
        #pragma unroll
        for (int i = 0; i < V; i++) { v[i] = (ra*v[i] + rc*rv[i]) * rinv; s3 += (double)v[i]*v[i]; }
        float zn = (float)sqrt(blockSum<T>(s3) + 1e-30);
        if (zn > MAXN) { float ps = MAXN / zn;
            #pragma unroll
            for (int i = 0; i < V; i++) v[i] *= ps; }
    }
    if (flags & FLAG_LOGMAP) {
        double s4 = 0.0;
        #pragma unroll
        for (int i = 0; i < V; i++) s4 += (double)v[i]*v[i];
        float n = (float)sqrt(blockSum<T>(s4) + 1e-30);
        float lf = atanhf(fminf(n, MAXN)) / n;
        #pragma unroll
        for (int i = 0; i < V; i++) v[i] *= lf;
    }
    double s5 = 0.0;
    #pragma unroll
    for (int i = 0; i < V; i++) { out[row*E + tid + i*T] = v[i]; s5 += (double)v[i]*v[i]; }
    if (out_norm) {
        float nf = (float)sqrt(blockSum<T>(s5) + 1e-30);
        if (tid == 0) out_norm[row] = nf;
    }
}

// ---------------- attention: 1 CTA per (b,h), 1 thread per query, online softmax ----------------
__global__ void __launch_bounds__(128) attn_kernel(
    const float* __restrict__ q, const float* __restrict__ k,
    const float* __restrict__ v, float* __restrict__ o)
{
    int bh = blockIdx.x;
    int b  = bh >> 3;
    int h  = bh & 7;
    int t  = threadIdx.x;          // query index 0..127
    const float scale = 0.125f;    // 1/sqrt(64)
    float qr[HD];
    size_t qbase = ((size_t)t*BB + b)*ED + (size_t)h*HD;
    #pragma unroll
    for (int d = 0; d < HD; d++) qr[d] = q[qbase + d] * scale;
    float m = -1e30f, l = 0.0f;
    float acc[HD];
    #pragma unroll
    for (int d = 0; d < HD; d++) acc[d] = 0.0f;
    __shared__ float ks[16][HD];
    __shared__ float vs[16][HD];
    for (int j0 = 0; j0 < SEQ; j0 += 16) {
        __syncthreads();
        for (int idx = t; idx < 16*HD; idx += 128) {
            int jj = idx >> 6, d = idx & 63;
            size_t g = ((size_t)(j0 + jj)*BB + b)*ED + (size_t)h*HD + d;
            ks[jj][d] = k[g];
            vs[jj][d] = v[g];
        }
        __syncthreads();
        float sc[16];
        #pragma unroll
        for (int jj = 0; jj < 16; jj++) {
            float s = 0.0f;
            #pragma unroll
            for (int d = 0; d < HD; d++) s += qr[d] * ks[jj][d];
            sc[jj] = s;
        }
        float mn = m;
        #pragma unroll
        for (int jj = 0; jj < 16; jj++) mn = fmaxf(mn, sc[jj]);
        float corr = expf(m - mn);
        l *= corr;
        #pragma unroll
        for (int d = 0; d < HD; d++) acc[d] *= corr;
        #pragma unroll
        for (int jj = 0; jj < 16; jj++) {
            float p = expf(sc[jj] - mn);
            l += p;
            #pragma unroll
            for (int d = 0; d < HD; d++) acc[d] += p * vs[jj][d];
        }
        m = mn;
    }
    float invl = 1.0f / l;
    #pragma unroll
    for (int d = 0; d < HD; d++) o[qbase + d] = acc[d] * invl;
}

// ---------------- tiled fp32 GEMM: C[M,N] = A[M,K] @ W[N,K]^T ----------------
#define GBM 128
#define GBN 128
#define GBK 8
__global__ void __launch_bounds__(256) sgemm_nt(
    const float* __restrict__ A, const float* __restrict__ W, float* __restrict__ C,
    int M, int N, int K)
{
    __shared__ float As[GBK][GBM];
    __shared__ float Bs[GBK][GBN];
    int tid = threadIdx.x;
    int bx = blockIdx.x, by = blockIdx.y;
    const float* Ab = A + (size_t)by * GBM * K;
    const float* Wb = W + (size_t)bx * GBN * K;
    int lr = tid >> 1;              // 0..127
    int lk = (tid & 1) << 2;        // 0 or 4
    int ty = tid >> 4, tx = tid & 15;
    float acc[8][8];
    #pragma unroll
    for (int i = 0; i < 8; i++)
        #pragma unroll
        for (int j = 0; j < 8; j++) acc[i][j] = 0.0f;
    for (int k0 = 0; k0 < K; k0 += GBK) {
        float4 a4 = *(const float4*)(Ab + (size_t)lr * K + k0 + lk);
        float4 b4 = *(const float4*)(Wb + (size_t)lr * K + k0 + lk);
        As[lk+0][lr] = a4.x; As[lk+1][lr] = a4.y; As[lk+2][lr] = a4.z; As[lk+3][lr] = a4.w;
        Bs[lk+0][lr] = b4.x; Bs[lk+1][lr] = b4.y; Bs[lk+2][lr] = b4.z; Bs[lk+3][lr] = b4.w;
        __syncthreads();
        #pragma unroll
        for (int kk = 0; kk < GBK; kk++) {
            float ar[8], br[8];
            *(float4*)&ar[0] = *(const float4*)&As[kk][ty*8];
            *(float4*)&ar[4] = *(const float4*)&As[kk][ty*8 + 4];
            *(float4*)&br[0] = *(const float4*)&Bs[kk][tx*8];
            *(float4*)&br[4] = *(const float4*)&Bs[kk][tx*8 + 4];
            #pragma unroll
            for (int i = 0; i < 8; i++)
                #pragma unroll
                for (int j = 0; j < 8; j++) acc[i][j] += ar[i] * br[j];
        }
        __syncthreads();
    }
    #pragma unroll
    for (int i = 0; i < 8; i++) {
        float* Cr = C + (size_t)(by*GBM + ty*8 + i) * N + bx*GBN + tx*8;
        *(float4*)&Cr[0] = *(float4*)&acc[i][0];
        *(float4*)&Cr[4] = *(float4*)&acc[i][4];
    }
}

// ---------------- launch ----------------
extern "C" void kernel_launch(void* const* d_in, const int* in_sizes, int n_in,
                              void* d_out, int out_size)
{
    const float* x    = (const float*)d_in[0];
    const float* l1g  = (const float*)d_in[1];
    const float* l1b  = (const float*)d_in[2];
    const float* l2g  = (const float*)d_in[3];
    const float* l2b  = (const float*)d_in[4];
    const float* Wq   = (const float*)d_in[5];
    const float* bq   = (const float*)d_in[6];
    const float* Wk   = (const float*)d_in[7];
    const float* bk   = (const float*)d_in[8];
    const float* Wv   = (const float*)d_in[9];
    const float* bv   = (const float*)d_in[10];
    const float* Wo   = (const float*)d_in[11];
    const float* bo   = (const float*)d_in[12];
    const float* W1   = (const float*)d_in[13];
    const float* b1   = (const float*)d_in[14];
    const float* W2   = (const float*)d_in[15];
    const float* b2   = (const float*)d_in[16];
    float* out = (float*)d_out;

    float *h0, *qb, *kb, *vb, *ob, *h1, *h2, *big, *n0, *no, *nh2, *nh3, *bsq;
    cudaGetSymbolAddress((void**)&h0,  g_h0);
    cudaGetSymbolAddress((void**)&qb,  g_q);
    cudaGetSymbolAddress((void**)&kb,  g_k);
    cudaGetSymbolAddress((void**)&vb,  g_v);
    cudaGetSymbolAddress((void**)&ob,  g_o);
    cudaGetSymbolAddress((void**)&h1,  g_h1);
    cudaGetSymbolAddress((void**)&h2,  g_h2);
    cudaGetSymbolAddress((void**)&big, g_big);
    cudaGetSymbolAddress((void**)&n0,  g_n0);
    cudaGetSymbolAddress((void**)&no,  g_no);
    cudaGetSymbolAddress((void**)&nh2, g_nh2);
    cudaGetSymbolAddress((void**)&nh3, g_nh3);
    cudaGetSymbolAddress((void**)&bsq, g_b2);

    // bias squared norms
    sqsum_kernel<<<1, 256>>>(bq, ED, bsq + 0);
    sqsum_kernel<<<1, 256>>>(bk, ED, bsq + 1);
    sqsum_kernel<<<1, 256>>>(bv, ED, bsq + 2);
    sqsum_kernel<<<1, 256>>>(bo, ED, bsq + 3);
    sqsum_kernel<<<1, 256>>>(b1, FD, bsq + 4);
    sqsum_kernel<<<1, 256>>>(b2, ED, bsq + 5);

    // ln1 (no projx in this path)
    ln_kernel<ED, 128><<<NR, 128>>>(x, l1g, l1b, h0, n0, 0);

    dim3 g512(ED / GBN, NR / GBM);
    sgemm_nt<<<g512, 256>>>(h0, Wq, qb, NR, ED, ED);
    sgemm_nt<<<g512, 256>>>(h0, Wk, kb, NR, ED, ED);
    sgemm_nt<<<g512, 256>>>(h0, Wv, vb, NR, ED, ED);
    manlin_epi<ED, 128><<<NR, 128>>>(qb, n0, bq, 0, nullptr, qb, nullptr, FLAG_LOGMAP);
    manlin_epi<ED, 128><<<NR, 128>>>(kb, n0, bk, 1, nullptr, kb, nullptr, FLAG_LOGMAP);
    manlin_epi<ED, 128><<<NR, 128>>>(vb, n0, bv, 2, nullptr, vb, nullptr, FLAG_LOGMAP);

    attn_kernel<<<BB * NH, 128>>>(qb, kb, vb, ob);
    expmap_rows<ED, 128><<<NR, 128>>>(ob, no);

    sgemm_nt<<<g512, 256>>>(ob, Wo, big, NR, ED, ED);
    manlin_epi<ED, 128><<<NR, 128>>>(big, no, bo, 3, x, h1, nullptr, FLAG_RESID);

    // ln2 (with projx)
    ln_kernel<ED, 128><<<NR, 128>>>(h1, l2g, l2b, h2, nh2, 1);

    dim3 gF(FD / GBN, NR / GBM);
    sgemm_nt<<<gF, 256>>>(h2, W1, big, NR, FD, ED);
    manlin_epi<FD, 256><<<NR, 256>>>(big, nh2, b1, 4, nullptr, big, nh3, FLAG_MOBRELU);

    sgemm_nt<<<g512, 256>>>(big, W2, qb, NR, ED, FD);
    manlin_epi<ED, 128><<<NR, 128>>>(qb, nh3, b2, 5, h1, out, nullptr, FLAG_MOBRELU | FLAG_RESID);
}

// round 2
// speedup vs baseline: 1.2598x; 1.2598x over previous
#include <cuda_runtime.h>
#include <cuda_bf16.h>
#include <math.h>
#include <stdint.h>

// ---------------- problem constants ----------------
#define SEQ 128
#define BB  256
#define ED  512
#define FD  2048
#define NH  8
#define HD  64
#define NR  (SEQ*BB)   // 32768 rows

static __device__ __forceinline__ float maxnorm() { return (float)(1.0 - 1e-5); }

// ---------------- scratch (device globals; no allocation allowed) ----------------
__device__ float g_q  [(size_t)NR*ED];
__device__ float g_k  [(size_t)NR*ED];
__device__ float g_v  [(size_t)NR*ED];
__device__ float g_o  [(size_t)NR*ED];
__device__ float g_h1 [(size_t)NR*ED];
__device__ float g_big[(size_t)NR*FD];
__device__ __nv_bfloat16 g_xh[(size_t)NR*FD];
__device__ __nv_bfloat16 g_xl[(size_t)NR*FD];
__device__ __nv_bfloat16 g_wh[(size_t)FD*ED];
__device__ __nv_bfloat16 g_wl[(size_t)FD*ED];
__device__ float g_n0 [NR];
__device__ float g_no [NR];
__device__ float g_nh2[NR];
__device__ float g_nh3[NR];
__device__ float g_b2 [8];

#define FLAG_LOGMAP  1
#define FLAG_MOBRELU 2
#define FLAG_RESID   4

// ---------------- block reduction (double accumulate) ----------------
template <int T>
__device__ __forceinline__ double blockSum(double v) {
    __shared__ double sh[T / 32];
    #pragma unroll
    for (int o = 16; o > 0; o >>= 1) v += __shfl_xor_sync(0xffffffffu, v, o);
    int lane = threadIdx.x & 31, w = threadIdx.x >> 5;
    if (lane == 0) sh[w] = v;
    __syncthreads();
    if (threadIdx.x < 32) {
        double t = (threadIdx.x < T / 32) ? sh[threadIdx.x] : 0.0;
        #pragma unroll
        for (int o = 16; o > 0; o >>= 1) t += __shfl_xor_sync(0xffffffffu, t, o);
        if (threadIdx.x == 0) sh[0] = t;
    }
    __syncthreads();
    double r = sh[0];
    __syncthreads();
    return r;
}

__device__ __forceinline__ void split1(float x, __nv_bfloat16 &h, __nv_bfloat16 &l) {
    h = __float2bfloat16(x);
    l = __float2bfloat16(x - __bfloat162float(h));
}

// ---------------- all 6 bias squared-norms in one launch ----------------
__global__ void sqsum6(const float* bq, const float* bk, const float* bv,
                       const float* bo, const float* b1, const float* b2,
                       float* __restrict__ out) {
    const float* p;
    int n;
    switch (blockIdx.x) {
        case 0: p = bq; n = ED; break;
        case 1: p = bk; n = ED; break;
        case 2: p = bv; n = ED; break;
        case 3: p = bo; n = ED; break;
        case 4: p = b1; n = FD; break;
        default: p = b2; n = ED; break;
    }
    double s = 0.0;
    for (int i = threadIdx.x; i < n; i += 256) { double x = p[i]; s += x * x; }
    s = blockSum<256>(s);
    if (threadIdx.x == 0) out[blockIdx.x] = (float)s;
}

// ---------------- weight split fp32 -> bf16 hi/lo ----------------
__global__ void split_kernel(const float* __restrict__ x, __nv_bfloat16* __restrict__ h,
                             __nv_bfloat16* __restrict__ l, int n4) {
    int i = blockIdx.x * blockDim.x + threadIdx.x;
    if (i < n4) {
        float4 v = ((const float4*)x)[i];
        __nv_bfloat16 h0,l0,h1,l1,h2,l2,h3,l3;
        split1(v.x, h0, l0); split1(v.y, h1, l1);
        split1(v.z, h2, l2); split1(v.w, h3, l3);
        __nv_bfloat162* hp = (__nv_bfloat162*)h;
        __nv_bfloat162* lp = (__nv_bfloat162*)l;
        hp[i*2]   = __nv_bfloat162(h0, h1);
        hp[i*2+1] = __nv_bfloat162(h2, h3);
        lp[i*2]   = __nv_bfloat162(l0, l1);
        lp[i*2+1] = __nv_bfloat162(l2, l3);
    }
}

// ---------------- ln block: expmap0(layernorm(logmap0(x))) [+projx] ----------------
template <int E, int T>
__global__ void __launch_bounds__(T) ln_kernel(
    const float* __restrict__ x, const float* __restrict__ g, const float* __restrict__ b,
    float* __restrict__ outf, __nv_bfloat16* __restrict__ oh, __nv_bfloat16* __restrict__ ol,
    float* __restrict__ out_norm, int do_projx)
{
    constexpr int V = E / T;
    const size_t row = blockIdx.x;
    const int tid = threadIdx.x;
    const float MAXN = maxnorm();
    float v[V];
    double ss = 0.0;
    #pragma unroll
    for (int i = 0; i < V; i++) { v[i] = x[row*E + tid + i*T]; ss += (double)v[i]*v[i]; }
    float n0 = (float)sqrt(blockSum<T>(ss) + 1e-30);
    float lf = atanhf(fminf(n0, MAXN)) / n0;
    double sm = 0.0;
    #pragma unroll
    for (int i = 0; i < V; i++) { v[i] *= lf; sm += (double)v[i]; }
    float mu = (float)(blockSum<T>(sm) / (double)E);
    double vv = 0.0;
    #pragma unroll
    for (int i = 0; i < V; i++) { float d = v[i] - mu; vv += (double)d*d; }
    float var = (float)(blockSum<T>(vv) / (double)E);
    float inv = rsqrtf(var + 1e-5f);
    double s2 = 0.0;
    #pragma unroll
    for (int i = 0; i < V; i++) {
        int idx = tid + i*T;
        v[i] = (v[i] - mu) * inv * g[idx] + b[idx];
        s2 += (double)v[i]*v[i];
    }
    float ny = (float)sqrt(blockSum<T>(s2) + 1e-30);
    float ef = tanhf(ny) / ny;
    #pragma unroll
    for (int i = 0; i < V; i++) v[i] *= ef;
    if (do_projx) {
        double s3 = 0.0;
        #pragma unroll
        for (int i = 0; i < V; i++) s3 += (double)v[i]*v[i];
        float n = (float)sqrt(blockSum<T>(s3) + 1e-30);
        if (n > MAXN) { float ps = MAXN / n;
            #pragma unroll
            for (int i = 0; i < V; i++) v[i] *= ps; }
    }
    double s4 = 0.0;
    #pragma unroll
    for (int i = 0; i < V; i++) {
        int idx = tid + i*T;
        if (outf) outf[row*E + idx] = v[i];
        if (oh) { __nv_bfloat16 hh, ll; split1(v[i], hh, ll); oh[row*E + idx] = hh; ol[row*E + idx] = ll; }
        s4 += (double)v[i]*v[i];
    }
    float nf = (float)sqrt(blockSum<T>(s4) + 1e-30);
    if (tid == 0) out_norm[row] = nf;
}

// ---------------- expmap0 rows (attention output) -> bf16 split + norm ----------------
template <int E, int T>
__global__ void __launch_bounds__(T) expmap_rows(
    const float* __restrict__ x, __nv_bfloat16* __restrict__ oh, __nv_bfloat16* __restrict__ ol,
    float* __restrict__ out_norm)
{
    constexpr int V = E / T;
    const size_t row = blockIdx.x;
    const int tid = threadIdx.x;
    float v[V];
    double ss = 0.0;
    #pragma unroll
    for (int i = 0; i < V; i++) { v[i] = x[row*E + tid + i*T]; ss += (double)v[i]*v[i]; }
    float n = (float)sqrt(blockSum<T>(ss) + 1e-30);
    float ef = tanhf(n) / n;
    double s2 = 0.0;
    #pragma unroll
    for (int i = 0; i < V; i++) {
        v[i] *= ef;
        int idx = tid + i*T;
        __nv_bfloat16 hh, ll; split1(v[i], hh, ll);
        oh[row*E + idx] = hh; ol[row*E + idx] = ll;
        s2 += (double)v[i]*v[i];
    }
    float nf = (float)sqrt(blockSum<T>(s2) + 1e-30);
    if (tid == 0) out_norm[row] = nf;
}

// ---------------- man_linear epilogue (+ mob_relu / residual / logmap0) ----------------
template <int E, int T>
__global__ void __launch_bounds__(T) manlin_epi(
    const float* __restrict__ mx, const float* __restrict__ xnb,
    const float* __restrict__ bias, int b2idx,
    const float* __restrict__ resid,
    float* __restrict__ outf, __nv_bfloat16* __restrict__ oh, __nv_bfloat16* __restrict__ ol,
    float* __restrict__ out_norm, int flags)
{
    constexpr int V = E / T;
    const size_t row = blockIdx.x;
    const int tid = threadIdx.x;
    const float MAXN = maxnorm();
    float v[V], bv[V];
    double ss = 0.0;
    #pragma unroll
    for (int i = 0; i < V; i++) { v[i] = mx[row*E + tid + i*T]; ss += (double)v[i]*v[i]; }
    float mxn = (float)sqrt(blockSum<T>(ss) + 1e-30);
    float xn = xnb[row];
    float s = tanhf(mxn / xn * atanhf(fminf(xn, MAXN))) / mxn;
    double dxy = 0.0, dx2 = 0.0;
    #pragma unroll
    for (int i = 0; i < V; i++) {
        v[i] = s * v[i];
        bv[i] = bias[tid + i*T];
        dxy += (double)v[i]*bv[i];
        dx2 += (double)v[i]*v[i];
    }
    float xy = (float)blockSum<T>(dxy);
    float x2 = (float)blockSum<T>(dx2);
    float y2 = g_b2[b2idx];
    float a = 1.0f + 2.0f*xy + y2;
    float c = 1.0f - x2;
    float den = fmaxf(1.0f + 2.0f*xy + x2*y2, 1e-15f);
    float invd = 1.0f / den;
    double zz = 0.0;
    #pragma unroll
    for (int i = 0; i < V; i++) { v[i] = (a*v[i] + c*bv[i]) * invd; zz += (double)v[i]*v[i]; }
    {
        float zn = (float)sqrt(blockSum<T>(zz) + 1e-30);
        if (zn > MAXN) { float ps = MAXN / zn;
            #pragma unroll
            for (int i = 0; i < V; i++) v[i] *= ps; }
    }
    if (flags & FLAG_MOBRELU) {
        double s0 = 0.0;
        #pragma unroll
        for (int i = 0; i < V; i++) s0 += (double)v[i]*v[i];
        float n = (float)sqrt(blockSum<T>(s0) + 1e-30);
        float lf = atanhf(fminf(n, MAXN)) / n;
        double s1 = 0.0;
        #pragma unroll
        for (int i = 0; i < V; i++) { v[i] = fmaxf(lf * v[i], 0.0f); s1 += (double)v[i]*v[i]; }
        float nr = (float)sqrt(blockSum<T>(s1) + 1e-30);
        float ef = tanhf(nr) / nr;
        double s2 = 0.0;
        #pragma unroll
        for (int i = 0; i < V; i++) { v[i] *= ef; s2 += (double)v[i]*v[i]; }
        float n2 = (float)sqrt(blockSum<T>(s2) + 1e-30);
        if (n2 > MAXN) { float ps = MAXN / n2;
            #pragma unroll
            for (int i = 0; i < V; i++) v[i] *= ps; }
    }
    if (flags & FLAG_RESID) {
        const float* rr = resid + row*E;
        float rv[V];
        double d1 = 0.0, d2 = 0.0, d3 = 0.0;
        #pragma unroll
        for (int i = 0; i < V; i++) {
            rv[i] = rr[tid + i*T];
            d1 += (double)v[i]*rv[i];
            d2 += (double)rv[i]*rv[i];
            d3 += (double)v[i]*v[i];
        }
        float rxy = (float)blockSum<T>(d1);
        float ry2 = (float)blockSum<T>(d2);
        float rx2 = (float)blockSum<T>(d3);
        float ra = 1.0f + 2.0f*rxy + ry2;
        float rc = 1.0f - rx2;
        float rden = fmaxf(1.0f + 2.0f*rxy + rx2*ry2, 1e-15f);
        float rinv = 1.0f / rden;
        double s3 = 0.0;
        #pragma unroll
        for (int i = 0; i < V; i++) { v[i] = (ra*v[i] + rc*rv[i]) * rinv; s3 += (double)v[i]*v[i]; }
        float zn = (float)sqrt(blockSum<T>(s3) + 1e-30);
        if (zn > MAXN) { float ps = MAXN / zn;
            #pragma unroll
            for (int i = 0; i < V; i++) v[i] *= ps; }
    }
    if (flags & FLAG_LOGMAP) {
        double s4 = 0.0;
        #pragma unroll
        for (int i = 0; i < V; i++) s4 += (double)v[i]*v[i];
        float n = (float)sqrt(blockSum<T>(s4) + 1e-30);
        float lf = atanhf(fminf(n, MAXN)) / n;
        #pragma unroll
        for (int i = 0; i < V; i++) v[i] *= lf;
    }
    double s5 = 0.0;
    #pragma unroll
    for (int i = 0; i < V; i++) {
        int idx = tid + i*T;
        if (outf) outf[row*E + idx] = v[i];
        if (oh) { __nv_bfloat16 hh, ll; split1(v[i], hh, ll); oh[row*E + idx] = hh; ol[row*E + idx] = ll; }
        s5 += (double)v[i]*v[i];
    }
    if (out_norm) {
        float nf = (float)sqrt(blockSum<T>(s5) + 1e-30);
        if (tid == 0) out_norm[row] = nf;
    }
}

// ---------------- attention: 1 CTA per (b,h), 1 thread per query ----------------
__global__ void __launch_bounds__(128) attn_kernel(
    const float* __restrict__ q, const float* __restrict__ k,
    const float* __restrict__ v, float* __restrict__ o)
{
    int bh = blockIdx.x;
    int b  = bh >> 3;
    int h  = bh & 7;
    int t  = threadIdx.x;
    const float scale = 0.125f;
    float qr[HD];
    size_t qbase = ((size_t)t*BB + b)*ED + (size_t)h*HD;
    #pragma unroll
    for (int d = 0; d < HD; d++) qr[d] = q[qbase + d] * scale;
    float m = -1e30f, l = 0.0f;
    float acc[HD];
    #pragma unroll
    for (int d = 0; d < HD; d++) acc[d] = 0.0f;
    __shared__ float ks[16][HD];
    __shared__ float vs[16][HD];
    for (int j0 = 0; j0 < SEQ; j0 += 16) {
        __syncthreads();
        for (int idx = t; idx < 16*HD; idx += 128) {
            int jj = idx >> 6, d = idx & 63;
            size_t g = ((size_t)(j0 + jj)*BB + b)*ED + (size_t)h*HD + d;
            ks[jj][d] = k[g];
            vs[jj][d] = v[g];
        }
        __syncthreads();
        float sc[16];
        #pragma unroll
        for (int jj = 0; jj < 16; jj++) {
            float s = 0.0f;
            #pragma unroll
            for (int d = 0; d < HD; d++) s += qr[d] * ks[jj][d];
            sc[jj] = s;
        }
        float mn = m;
        #pragma unroll
        for (int jj = 0; jj < 16; jj++) mn = fmaxf(mn, sc[jj]);
        float corr = expf(m - mn);
        l *= corr;
        #pragma unroll
        for (int d = 0; d < HD; d++) acc[d] *= corr;
        #pragma unroll
        for (int jj = 0; jj < 16; jj++) {
            float p = expf(sc[jj] - mn);
            l += p;
            #pragma unroll
            for (int d = 0; d < HD; d++) acc[d] += p * vs[jj][d];
        }
        m = mn;
    }
    float invl = 1.0f / l;
    #pragma unroll
    for (int d = 0; d < HD; d++) o[qbase + d] = acc[d] * invl;
}

// ---------------- bf16x3 tensor-core GEMM: C[M,N] = A[M,K] @ W[N,K]^T ----------------
#define BM 128
#define BN 128
#define BK 32
#define SST 40                       // smem row stride (bf16 elems), 80B: conflict-free ldmatrix
#define TEN_ELEMS (128*SST)          // elems per tensor per stage
#define STAGE_ELEMS (4*TEN_ELEMS)
#define GEMM_SMEM (2*STAGE_ELEMS*2)  // bytes = 81920

__device__ __forceinline__ void ldsm_x4(uint32_t &r0, uint32_t &r1, uint32_t &r2, uint32_t &r3, uint32_t addr) {
    asm volatile("ldmatrix.sync.aligned.m8n8.x4.shared.b16 {%0,%1,%2,%3}, [%4];"
                 : "=r"(r0), "=r"(r1), "=r"(r2), "=r"(r3) : "r"(addr));
}
__device__ __forceinline__ void ldsm_x2(uint32_t &r0, uint32_t &r1, uint32_t addr) {
    asm volatile("ldmatrix.sync.aligned.m8n8.x2.shared.b16 {%0,%1}, [%2];"
                 : "=r"(r0), "=r"(r1) : "r"(addr));
}
__device__ __forceinline__ void mma16816(float* c, const uint32_t* a, const uint32_t* b) {
    asm volatile("mma.sync.aligned.m16n8k16.row.col.f32.bf16.bf16.f32 "
                 "{%0,%1,%2,%3}, {%4,%5,%6,%7}, {%8,%9}, {%0,%1,%2,%3};"
                 : "+f"(c[0]), "+f"(c[1]), "+f"(c[2]), "+f"(c[3])
                 : "r"(a[0]), "r"(a[1]), "r"(a[2]), "r"(a[3]), "r"(b[0]), "r"(b[1]));
}
#define CP_ASYNC16(dst, src) asm volatile("cp.async.cg.shared.global [%0], [%1], 16;" :: "r"(dst), "l"(src))

__global__ void __launch_bounds__(256) gemm_bf16x3(
    const __nv_bfloat16* __restrict__ Ah, const __nv_bfloat16* __restrict__ Al,
    const __nv_bfloat16* __restrict__ Wh, const __nv_bfloat16* __restrict__ Wl,
    float* __restrict__ C, int M, int N, int K)
{
    extern __shared__ __nv_bfloat16 smbuf[];
    const int tid = threadIdx.x;
    const int lane = tid & 31, w = tid >> 5;
    const int wm = w & 1, wn = w >> 1;
    const int rowBase = blockIdx.y * BM;
    const int colBase = blockIdx.x * BN;
    uint32_t smbase = (uint32_t)__cvta_generic_to_shared(smbuf);

    float acc[4][4][4];
    #pragma unroll
    for (int i = 0; i < 4; i++)
        #pragma unroll
        for (int j = 0; j < 4; j++)
            #pragma unroll
            for (int e = 0; e < 4; e++) acc[i][j][e] = 0.0f;

    auto load_stage = [&](int st, int k0) {
        uint32_t base = smbase + st * STAGE_ELEMS * 2;
        #pragma unroll
        for (int it = 0; it < 2; it++) {
            int vv = tid + it * 256;
            int r = vv >> 2, cc = (vv & 3) * 8;
            uint32_t soff = (uint32_t)((r * SST + cc) * 2);
            size_t ga = (size_t)(rowBase + r) * K + k0 + cc;
            size_t gw = (size_t)(colBase + r) * K + k0 + cc;
            CP_ASYNC16(base + 0*TEN_ELEMS*2 + soff, Ah + ga);
            CP_ASYNC16(base + 1*TEN_ELEMS*2 + soff, Al + ga);
            CP_ASYNC16(base + 2*TEN_ELEMS*2 + soff, Wh + gw);
            CP_ASYNC16(base + 3*TEN_ELEMS*2 + soff, Wl + gw);
        }
        asm volatile("cp.async.commit_group;");
    };

    auto compute_stage = [&](int st) {
        uint32_t base = smbase + st * STAGE_ELEMS * 2;
        uint32_t aH = base;
        uint32_t aL = base + 1*TEN_ELEMS*2;
        uint32_t wH = base + 2*TEN_ELEMS*2;
        uint32_t wL = base + 3*TEN_ELEMS*2;
        const int quad = lane >> 3, r8 = lane & 7;
        #pragma unroll
        for (int kk = 0; kk < BK; kk += 16) {
            uint32_t ah[4][4], al[4][4], bh[4][2], bl[4][2];
            #pragma unroll
            for (int i = 0; i < 4; i++) {
                int row = wm*64 + i*16 + (quad & 1)*8 + r8;
                int col = kk + (quad >> 1)*8;
                uint32_t off = (uint32_t)((row * SST + col) * 2);
                ldsm_x4(ah[i][0], ah[i][1], ah[i][2], ah[i][3], aH + off);
                ldsm_x4(al[i][0], al[i][1], al[i][2], al[i][3], aL + off);
            }
            #pragma unroll
            for (int j = 0; j < 4; j++) {
                int nr = wn*32 + j*8 + (lane & 7);
                int kc = kk + ((lane >> 3) & 1)*8;
                uint32_t off = (uint32_t)((nr * SST + kc) * 2);
                ldsm_x2(bh[j][0], bh[j][1], wH + off);
                ldsm_x2(bl[j][0], bl[j][1], wL + off);
            }
            #pragma unroll
            for (int i = 0; i < 4; i++)
                #pragma unroll
                for (int j = 0; j < 4; j++) {
                    mma16816(acc[i][j], ah[i], bh[j]);
                    mma16816(acc[i][j], ah[i], bl[j]);
                    mma16816(acc[i][j], al[i], bh[j]);
                }
        }
    };

    load_stage(0, 0);
    asm volatile("cp.async.wait_group 0;");
    __syncthreads();
    int st = 0;
    for (int k0 = 0; k0 < K; k0 += BK) {
        bool nxt = (k0 + BK) < K;
        if (nxt) load_stage(st ^ 1, k0 + BK);
        compute_stage(st);
        if (nxt) asm volatile("cp.async.wait_group 0;");
        __syncthreads();
        st ^= 1;
    }

    const int g = lane >> 2, tg = lane & 3;
    #pragma unroll
    for (int i = 0; i < 4; i++) {
        int row = rowBase + wm*64 + i*16 + g;
        #pragma unroll
        for (int j = 0; j < 4; j++) {
            int col = colBase + wn*32 + j*8 + tg*2;
            *(float2*)(C + (size_t)row * N + col)       = make_float2(acc[i][j][0], acc[i][j][1]);
            *(float2*)(C + (size_t)(row + 8) * N + col) = make_float2(acc[i][j][2], acc[i][j][3]);
        }
    }
}

// ---------------- launch ----------------
extern "C" void kernel_launch(void* const* d_in, const int* in_sizes, int n_in,
                              void* d_out, int out_size)
{
    const float* x    = (const float*)d_in[0];
    const float* l1g  = (const float*)d_in[1];
    const float* l1b  = (const float*)d_in[2];
    const float* l2g  = (const float*)d_in[3];
    const float* l2b  = (const float*)d_in[4];
    const float* Wq   = (const float*)d_in[5];
    const float* bq   = (const float*)d_in[6];
    const float* Wk   = (const float*)d_in[7];
    const float* bk   = (const float*)d_in[8];
    const float* Wv   = (const float*)d_in[9];
    const float* bv   = (const float*)d_in[10];
    const float* Wo   = (const float*)d_in[11];
    const float* bo   = (const float*)d_in[12];
    const float* W1   = (const float*)d_in[13];
    const float* b1   = (const float*)d_in[14];
    const float* W2   = (const float*)d_in[15];
    const float* b2   = (const float*)d_in[16];
    float* out = (float*)d_out;

    float *qb, *kb, *vb, *ob, *h1, *big, *n0, *no, *nh2, *nh3, *bsq;
    __nv_bfloat16 *xh, *xl, *wh, *wl;
    cudaGetSymbolAddress((void**)&qb,  g_q);
    cudaGetSymbolAddress((void**)&kb,  g_k);
    cudaGetSymbolAddress((void**)&vb,  g_v);
    cudaGetSymbolAddress((void**)&ob,  g_o);
    cudaGetSymbolAddress((void**)&h1,  g_h1);
    cudaGetSymbolAddress((void**)&big, g_big);
    cudaGetSymbolAddress((void**)&xh,  g_xh);
    cudaGetSymbolAddress((void**)&xl,  g_xl);
    cudaGetSymbolAddress((void**)&wh,  g_wh);
    cudaGetSymbolAddress((void**)&wl,  g_wl);
    cudaGetSymbolAddress((void**)&n0,  g_n0);
    cudaGetSymbolAddress((void**)&no,  g_no);
    cudaGetSymbolAddress((void**)&nh2, g_nh2);
    cudaGetSymbolAddress((void**)&nh3, g_nh3);
    cudaGetSymbolAddress((void**)&bsq, g_b2);

    cudaFuncSetAttribute(gemm_bf16x3, cudaFuncAttributeMaxDynamicSharedMemorySize, GEMM_SMEM);

    dim3 gE(ED / BN, NR / BM);   // (4, 256)
    dim3 gF(FD / BN, NR / BM);   // (16, 256)
    const int sE  = (ED*ED/4 + 255) / 256;
    const int sEF = (FD*ED/4 + 255) / 256;

    // 1) bias squared norms
    sqsum6<<<6, 256>>>(bq, bk, bv, bo, b1, b2, bsq);
    // 2) ln1 -> bf16 split + norm
    ln_kernel<ED, 128><<<NR, 128>>>(x, l1g, l1b, nullptr, xh, xl, n0, 0);
    // 3-8) QKV projections
    split_kernel<<<sE, 256>>>(Wq, wh, wl, ED*ED/4);
    gemm_bf16x3<<<gE, 256, GEMM_SMEM>>>(xh, xl, wh, wl, qb, NR, ED, ED);
    split_kernel<<<sE, 256>>>(Wk, wh, wl, ED*ED/4);
    gemm_bf16x3<<<gE, 256, GEMM_SMEM>>>(xh, xl, wh, wl, kb, NR, ED, ED);   // <- ncu -s 5 lands here
    split_kernel<<<sE, 256>>>(Wv, wh, wl, ED*ED/4);
    gemm_bf16x3<<<gE, 256, GEMM_SMEM>>>(xh, xl, wh, wl, vb, NR, ED, ED);
    // q/k/v manifold epilogues (fp32 in-place; attention reads fp32)
    manlin_epi<ED, 128><<<NR, 128>>>(qb, n0, bq, 0, nullptr, qb, nullptr, nullptr, nullptr, FLAG_LOGMAP);
    manlin_epi<ED, 128><<<NR, 128>>>(kb, n0, bk, 1, nullptr, kb, nullptr, nullptr, nullptr, FLAG_LOGMAP);
    manlin_epi<ED, 128><<<NR, 128>>>(vb, n0, bv, 2, nullptr, vb, nullptr, nullptr, nullptr, FLAG_LOGMAP);
    // attention
    attn_kernel<<<BB * NH, 128>>>(qb, kb, vb, ob);
    expmap_rows<ED, 128><<<NR, 128>>>(ob, xh, xl, no);
    // output projection + residual
    split_kernel<<<sE, 256>>>(Wo, wh, wl, ED*ED/4);
    gemm_bf16x3<<<gE, 256, GEMM_SMEM>>>(xh, xl, wh, wl, big, NR, ED, ED);
    manlin_epi<ED, 128><<<NR, 128>>>(big, no, bo, 3, x, h1, nullptr, nullptr, nullptr, FLAG_RESID);
    // ln2 -> bf16 split
    ln_kernel<ED, 128><<<NR, 128>>>(h1, l2g, l2b, nullptr, xh, xl, nh2, 1);
    // fc1
    split_kernel<<<sEF, 256>>>(W1, wh, wl, FD*ED/4);
    gemm_bf16x3<<<gF, 256, GEMM_SMEM>>>(xh, xl, wh, wl, big, NR, FD, ED);
    manlin_epi<FD, 256><<<NR, 256>>>(big, nh2, b1, 4, nullptr, nullptr, xh, xl, nh3, FLAG_MOBRELU);
    // fc2
    split_kernel<<<sEF, 256>>>(W2, wh, wl, ED*FD/4);
    gemm_bf16x3<<<gE, 256, GEMM_SMEM>>>(xh, xl, wh, wl, qb, NR, ED, FD);
    manlin_epi<ED, 128><<<NR, 128>>>(qb, nh3, b2, 5, h1, out, nullptr, nullptr, nullptr, FLAG_MOBRELU | FLAG_RESID);
}

// round 3
// speedup vs baseline: 5.9342x; 4.7106x over previous
#include <cuda_runtime.h>
#include <cuda_bf16.h>
#include <math.h>
#include <stdint.h>

// ---------------- problem constants ----------------
#define SEQ 128
#define BB  256
#define ED  512
#define FD  2048
#define NH  8
#define HD  64
#define NR  (SEQ*BB)   // 32768 rows

static __device__ __forceinline__ float maxnorm() { return (float)(1.0 - 1e-5); }

// ---------------- scratch ----------------
__device__ float g_q  [(size_t)NR*ED];
__device__ float g_k  [(size_t)NR*ED];
__device__ float g_v  [(size_t)NR*ED];
__device__ float g_o  [(size_t)NR*ED];
__device__ float g_h1 [(size_t)NR*ED];
__device__ float g_big[(size_t)NR*FD];
__device__ __nv_bfloat16 g_xh[(size_t)NR*FD];
__device__ __nv_bfloat16 g_xl[(size_t)NR*FD];
__device__ __nv_bfloat16 g_wh[(size_t)FD*ED];
__device__ __nv_bfloat16 g_wl[(size_t)FD*ED];
__device__ float g_n0 [NR];
__device__ float g_no [NR];
__device__ float g_nh2[NR];
__device__ float g_nh3[NR];
__device__ float g_b2 [8];

#define FLAG_LOGMAP  1
#define FLAG_MOBRELU 2
#define FLAG_RESID   4

// ---------------- block reduction (fp32, pairwise) ----------------
template <int T>
__device__ __forceinline__ float blockSumF(float v) {
    __shared__ float sh[T / 32];
    #pragma unroll
    for (int o = 16; o > 0; o >>= 1) v += __shfl_xor_sync(0xffffffffu, v, o);
    int lane = threadIdx.x & 31, w = threadIdx.x >> 5;
    if (lane == 0) sh[w] = v;
    __syncthreads();
    if (threadIdx.x < 32) {
        float t = (threadIdx.x < T / 32) ? sh[threadIdx.x] : 0.0f;
        #pragma unroll
        for (int o = 16; o > 0; o >>= 1) t += __shfl_xor_sync(0xffffffffu, t, o);
        if (threadIdx.x == 0) sh[0] = t;
    }
    __syncthreads();
    float r = sh[0];
    __syncthreads();
    return r;
}

__device__ __forceinline__ void split1(float x, __nv_bfloat16 &h, __nv_bfloat16 &l) {
    h = __float2bfloat16(x);
    l = __float2bfloat16(x - __bfloat162float(h));
}

// ---------------- all 6 bias squared-norms in one launch ----------------
__global__ void sqsum6(const float* bq, const float* bk, const float* bv,
                       const float* bo, const float* b1, const float* b2,
                       float* __restrict__ out) {
    const float* p;
    int n;
    switch (blockIdx.x) {
        case 0: p = bq; n = ED; break;
        case 1: p = bk; n = ED; break;
        case 2: p = bv; n = ED; break;
        case 3: p = bo; n = ED; break;
        case 4: p = b1; n = FD; break;
        default: p = b2; n = ED; break;
    }
    float s = 0.0f;
    for (int i = threadIdx.x; i < n; i += 256) { float x = p[i]; s += x * x; }
    s = blockSumF<256>(s);
    if (threadIdx.x == 0) out[blockIdx.x] = s;
}

// ---------------- weight split fp32 -> bf16 hi/lo ----------------
__global__ void split_kernel(const float* __restrict__ x, __nv_bfloat16* __restrict__ h,
                             __nv_bfloat16* __restrict__ l, int n4) {
    int i = blockIdx.x * blockDim.x + threadIdx.x;
    if (i < n4) {
        float4 v = ((const float4*)x)[i];
        __nv_bfloat16 h0,l0,h1,l1,h2,l2,h3,l3;
        split1(v.x, h0, l0); split1(v.y, h1, l1);
        split1(v.z, h2, l2); split1(v.w, h3, l3);
        __nv_bfloat162* hp = (__nv_bfloat162*)h;
        __nv_bfloat162* lp = (__nv_bfloat162*)l;
        hp[i*2]   = __nv_bfloat162(h0, h1);
        hp[i*2+1] = __nv_bfloat162(h2, h3);
        lp[i*2]   = __nv_bfloat162(l0, l1);
        lp[i*2+1] = __nv_bfloat162(l2, l3);
    }
}

// vector helpers
#define VOP4(dst, expr_x, expr_y, expr_z, expr_w) do { dst.x=(expr_x); dst.y=(expr_y); dst.z=(expr_z); dst.w=(expr_w); } while(0)
__device__ __forceinline__ float dot4(float4 a, float4 b) { return a.x*b.x + a.y*b.y + a.z*b.z + a.w*b.w; }
__device__ __forceinline__ float sq4(float4 a) { return dot4(a, a); }
__device__ __forceinline__ float4 scl4(float4 a, float s) { float4 r; VOP4(r, a.x*s, a.y*s, a.z*s, a.w*s); return r; }

// ---------------- ln block: expmap0(layernorm(logmap0(x))) [+projx] ----------------
template <int E, int T>
__global__ void __launch_bounds__(T) ln_kernel(
    const float* __restrict__ x, const float* __restrict__ g, const float* __restrict__ b,
    float* __restrict__ outf, __nv_bfloat16* __restrict__ oh, __nv_bfloat16* __restrict__ ol,
    float* __restrict__ out_norm, int do_projx)
{
    constexpr int V4 = E / (T * 4);
    const size_t row = blockIdx.x;
    const int tid = threadIdx.x;
    const float MAXN = maxnorm();
    const float4* xp = (const float4*)(x + row * E);
    const float4* gp = (const float4*)g;
    const float4* bp = (const float4*)b;
    float4 v[V4];
    float ss = 0.0f;
    #pragma unroll
    for (int i = 0; i < V4; i++) { v[i] = xp[tid*V4 + i]; ss += sq4(v[i]); }
    float n0 = sqrtf(blockSumF<T>(ss) + 1e-30f);
    float lf = atanhf(fminf(n0, MAXN)) / n0;
    float sm = 0.0f;
    #pragma unroll
    for (int i = 0; i < V4; i++) { v[i] = scl4(v[i], lf); sm += v[i].x + v[i].y + v[i].z + v[i].w; }
    float mu = blockSumF<T>(sm) * (1.0f / E);
    float vv = 0.0f;
    #pragma unroll
    for (int i = 0; i < V4; i++) {
        float4 d; VOP4(d, v[i].x-mu, v[i].y-mu, v[i].z-mu, v[i].w-mu);
        vv += sq4(d);
    }
    float var = blockSumF<T>(vv) * (1.0f / E);
    float inv = rsqrtf(var + 1e-5f);
    float s2 = 0.0f;
    #pragma unroll
    for (int i = 0; i < V4; i++) {
        float4 gg = gp[tid*V4 + i], bb = bp[tid*V4 + i];
        VOP4(v[i], (v[i].x-mu)*inv*gg.x + bb.x, (v[i].y-mu)*inv*gg.y + bb.y,
                   (v[i].z-mu)*inv*gg.z + bb.z, (v[i].w-mu)*inv*gg.w + bb.w);
        s2 += sq4(v[i]);
    }
    float ny = sqrtf(blockSumF<T>(s2) + 1e-30f);
    float ef = tanhf(ny) / ny;
    #pragma unroll
    for (int i = 0; i < V4; i++) v[i] = scl4(v[i], ef);
    if (do_projx) {
        float s3 = 0.0f;
        #pragma unroll
        for (int i = 0; i < V4; i++) s3 += sq4(v[i]);
        float n = sqrtf(blockSumF<T>(s3) + 1e-30f);
        if (n > MAXN) { float ps = MAXN / n;
            #pragma unroll
            for (int i = 0; i < V4; i++) v[i] = scl4(v[i], ps); }
    }
    float s4 = 0.0f;
    #pragma unroll
    for (int i = 0; i < V4; i++) {
        if (outf) ((float4*)(outf + row*E))[tid*V4 + i] = v[i];
        if (oh) {
            __nv_bfloat16 h0,l0,h1,l1,h2,l2,h3,l3;
            split1(v[i].x,h0,l0); split1(v[i].y,h1,l1); split1(v[i].z,h2,l2); split1(v[i].w,h3,l3);
            ((__nv_bfloat162*)(oh + row*E))[tid*V4*2 + i*2]   = __nv_bfloat162(h0,h1);
            ((__nv_bfloat162*)(oh + row*E))[tid*V4*2 + i*2+1] = __nv_bfloat162(h2,h3);
            ((__nv_bfloat162*)(ol + row*E))[tid*V4*2 + i*2]   = __nv_bfloat162(l0,l1);
            ((__nv_bfloat162*)(ol + row*E))[tid*V4*2 + i*2+1] = __nv_bfloat162(l2,l3);
        }
        s4 += sq4(v[i]);
    }
    float nf = sqrtf(blockSumF<T>(s4) + 1e-30f);
    if (tid == 0) out_norm[row] = nf;
}

// ---------------- expmap0 rows -> bf16 split + norm ----------------
template <int E, int T>
__global__ void __launch_bounds__(T) expmap_rows(
    const float* __restrict__ x, __nv_bfloat16* __restrict__ oh, __nv_bfloat16* __restrict__ ol,
    float* __restrict__ out_norm)
{
    constexpr int V4 = E / (T * 4);
    const size_t row = blockIdx.x;
    const int tid = threadIdx.x;
    const float4* xp = (const float4*)(x + row * E);
    float4 v[V4];
    float ss = 0.0f;
    #pragma unroll
    for (int i = 0; i < V4; i++) { v[i] = xp[tid*V4 + i]; ss += sq4(v[i]); }
    float n = sqrtf(blockSumF<T>(ss) + 1e-30f);
    float ef = tanhf(n) / n;
    float s2 = 0.0f;
    #pragma unroll
    for (int i = 0; i < V4; i++) {
        v[i] = scl4(v[i], ef);
        __nv_bfloat16 h0,l0,h1,l1,h2,l2,h3,l3;
        split1(v[i].x,h0,l0); split1(v[i].y,h1,l1); split1(v[i].z,h2,l2); split1(v[i].w,h3,l3);
        ((__nv_bfloat162*)(oh + row*E))[tid*V4*2 + i*2]   = __nv_bfloat162(h0,h1);
        ((__nv_bfloat162*)(oh + row*E))[tid*V4*2 + i*2+1] = __nv_bfloat162(h2,h3);
        ((__nv_bfloat162*)(ol + row*E))[tid*V4*2 + i*2]   = __nv_bfloat162(l0,l1);
        ((__nv_bfloat162*)(ol + row*E))[tid*V4*2 + i*2+1] = __nv_bfloat162(l2,l3);
        s2 += sq4(v[i]);
    }
    float nf = sqrtf(blockSumF<T>(s2) + 1e-30f);
    if (tid == 0) out_norm[row] = nf;
}

// ---------------- man_linear epilogue (+ mob_relu / residual / logmap0) ----------------
template <int E, int T>
__global__ void __launch_bounds__(T) manlin_epi(
    const float* __restrict__ mx, const float* __restrict__ xnb,
    const float* __restrict__ bias, int b2idx,
    const float* __restrict__ resid,
    float* __restrict__ outf, __nv_bfloat16* __restrict__ oh, __nv_bfloat16* __restrict__ ol,
    float* __restrict__ out_norm, int flags)
{
    constexpr int V4 = E / (T * 4);
    const size_t row = blockIdx.x;
    const int tid = threadIdx.x;
    const float MAXN = maxnorm();
    const float4* mp = (const float4*)(mx + row*E);
    const float4* bp = (const float4*)bias;
    float4 v[V4], bv[V4];
    float ss = 0.0f;
    #pragma unroll
    for (int i = 0; i < V4; i++) { v[i] = mp[tid*V4 + i]; ss += sq4(v[i]); }
    float mxn = sqrtf(blockSumF<T>(ss) + 1e-30f);
    float xn = xnb[row];
    float s = tanhf(mxn / xn * atanhf(fminf(xn, MAXN))) / mxn;
    float dxy = 0.0f, dx2 = 0.0f;
    #pragma unroll
    for (int i = 0; i < V4; i++) {
        v[i] = scl4(v[i], s);
        bv[i] = bp[tid*V4 + i];
        dxy += dot4(v[i], bv[i]);
        dx2 += sq4(v[i]);
    }
    float xy = blockSumF<T>(dxy);
    float x2 = blockSumF<T>(dx2);
    float y2 = g_b2[b2idx];
    float a = 1.0f + 2.0f*xy + y2;
    float c = 1.0f - x2;
    float den = fmaxf(1.0f + 2.0f*xy + x2*y2, 1e-15f);
    float invd = 1.0f / den;
    float zz = 0.0f;
    #pragma unroll
    for (int i = 0; i < V4; i++) {
        VOP4(v[i], (a*v[i].x + c*bv[i].x)*invd, (a*v[i].y + c*bv[i].y)*invd,
                   (a*v[i].z + c*bv[i].z)*invd, (a*v[i].w + c*bv[i].w)*invd);
        zz += sq4(v[i]);
    }
    {
        float zn = sqrtf(blockSumF<T>(zz) + 1e-30f);
        if (zn > MAXN) { float ps = MAXN / zn;
            #pragma unroll
            for (int i = 0; i < V4; i++) v[i] = scl4(v[i], ps); }
    }
    if (flags & FLAG_MOBRELU) {
        float s0 = 0.0f;
        #pragma unroll
        for (int i = 0; i < V4; i++) s0 += sq4(v[i]);
        float n = sqrtf(blockSumF<T>(s0) + 1e-30f);
        float lf = atanhf(fminf(n, MAXN)) / n;
        float s1 = 0.0f;
        #pragma unroll
        for (int i = 0; i < V4; i++) {
            VOP4(v[i], fmaxf(lf*v[i].x, 0.0f), fmaxf(lf*v[i].y, 0.0f),
                       fmaxf(lf*v[i].z, 0.0f), fmaxf(lf*v[i].w, 0.0f));
            s1 += sq4(v[i]);
        }
        float nr = sqrtf(blockSumF<T>(s1) + 1e-30f);
        float ef = tanhf(nr) / nr;
        float s2 = 0.0f;
        #pragma unroll
        for (int i = 0; i < V4; i++) { v[i] = scl4(v[i], ef); s2 += sq4(v[i]); }
        float n2 = sqrtf(blockSumF<T>(s2) + 1e-30f);
        if (n2 > MAXN) { float ps = MAXN / n2;
            #pragma unroll
            for (int i = 0; i < V4; i++) v[i] = scl4(v[i], ps); }
    }
    if (flags & FLAG_RESID) {
        const float4* rp = (const float4*)(resid + row*E);
        float4 rv[V4];
        float d1 = 0.0f, d2 = 0.0f, d3 = 0.0f;
        #pragma unroll
        for (int i = 0; i < V4; i++) {
            rv[i] = rp[tid*V4 + i];
            d1 += dot4(v[i], rv[i]);
            d2 += sq4(rv[i]);
            d3 += sq4(v[i]);
        }
        float rxy = blockSumF<T>(d1);
        float ry2 = blockSumF<T>(d2);
        float rx2 = blockSumF<T>(d3);
        float ra = 1.0f + 2.0f*rxy + ry2;
        float rc = 1.0f - rx2;
        float rden = fmaxf(1.0f + 2.0f*rxy + rx2*ry2, 1e-15f);
        float rinv = 1.0f / rden;
        float s3 = 0.0f;
        #pragma unroll
        for (int i = 0; i < V4; i++) {
            VOP4(v[i], (ra*v[i].x + rc*rv[i].x)*rinv, (ra*v[i].y + rc*rv[i].y)*rinv,
                       (ra*v[i].z + rc*rv[i].z)*rinv, (ra*v[i].w + rc*rv[i].w)*rinv);
            s3 += sq4(v[i]);
        }
        float zn = sqrtf(blockSumF<T>(s3) + 1e-30f);
        if (zn > MAXN) { float ps = MAXN / zn;
            #pragma unroll
            for (int i = 0; i < V4; i++) v[i] = scl4(v[i], ps); }
    }
    if (flags & FLAG_LOGMAP) {
        float s4 = 0.0f;
        #pragma unroll
        for (int i = 0; i < V4; i++) s4 += sq4(v[i]);
        float n = sqrtf(blockSumF<T>(s4) + 1e-30f);
        float lf = atanhf(fminf(n, MAXN)) / n;
        #pragma unroll
        for (int i = 0; i < V4; i++) v[i] = scl4(v[i], lf);
    }
    float s5 = 0.0f;
    #pragma unroll
    for (int i = 0; i < V4; i++) {
        if (outf) ((float4*)(outf + row*E))[tid*V4 + i] = v[i];
        if (oh) {
            __nv_bfloat16 h0,l0,h1,l1,h2,l2,h3,l3;
            split1(v[i].x,h0,l0); split1(v[i].y,h1,l1); split1(v[i].z,h2,l2); split1(v[i].w,h3,l3);
            ((__nv_bfloat162*)(oh + row*E))[tid*V4*2 + i*2]   = __nv_bfloat162(h0,h1);
            ((__nv_bfloat162*)(oh + row*E))[tid*V4*2 + i*2+1] = __nv_bfloat162(h2,h3);
            ((__nv_bfloat162*)(ol + row*E))[tid*V4*2 + i*2]   = __nv_bfloat162(l0,l1);
            ((__nv_bfloat162*)(ol + row*E))[tid*V4*2 + i*2+1] = __nv_bfloat162(l2,l3);
        }
        s5 += sq4(v[i]);
    }
    if (out_norm) {
        float nf = sqrtf(blockSumF<T>(s5) + 1e-30f);
        if (tid == 0) out_norm[row] = nf;
    }
}

// ---------------- attention: 1 CTA per (b,h), 1 thread per query, float4 tiles ----------------
__global__ void __launch_bounds__(128) attn_kernel(
    const float* __restrict__ q, const float* __restrict__ k,
    const float* __restrict__ v, float* __restrict__ o)
{
    int bh = blockIdx.x;
    int b  = bh >> 3;
    int h  = bh & 7;
    int t  = threadIdx.x;
    const float scale = 0.125f;
    size_t qbase = ((size_t)t*BB + b)*ED + (size_t)h*HD;
    float4 q4[16], acc[16];
    const float4* qp = (const float4*)(q + qbase);
    #pragma unroll
    for (int d = 0; d < 16; d++) { q4[d] = scl4(qp[d], scale); acc[d] = make_float4(0,0,0,0); }
    float m = -1e30f, l = 0.0f;
    __shared__ float4 ks[16][16];
    __shared__ float4 vs[16][16];
    for (int j0 = 0; j0 < SEQ; j0 += 16) {
        __syncthreads();
        #pragma unroll
        for (int it = 0; it < 2; it++) {
            int idx = t + it*128;
            int jj = idx >> 4, d4 = idx & 15;
            size_t g = ((size_t)(j0 + jj)*BB + b)*ED + (size_t)h*HD + d4*4;
            ks[jj][d4] = *(const float4*)(k + g);
            vs[jj][d4] = *(const float4*)(v + g);
        }
        __syncthreads();
        float sc[16];
        #pragma unroll
        for (int jj = 0; jj < 16; jj++) {
            float s = 0.0f;
            #pragma unroll
            for (int d = 0; d < 16; d++) s += dot4(q4[d], ks[jj][d]);
            sc[jj] = s;
        }
        float mn = m;
        #pragma unroll
        for (int jj = 0; jj < 16; jj++) mn = fmaxf(mn, sc[jj]);
        float corr = expf(m - mn);
        l *= corr;
        #pragma unroll
        for (int d = 0; d < 16; d++) acc[d] = scl4(acc[d], corr);
        #pragma unroll
        for (int jj = 0; jj < 16; jj++) {
            float p = expf(sc[jj] - mn);
            l += p;
            #pragma unroll
            for (int d = 0; d < 16; d++) {
                float4 vv = vs[jj][d];
                acc[d].x += p*vv.x; acc[d].y += p*vv.y; acc[d].z += p*vv.z; acc[d].w += p*vv.w;
            }
        }
        m = mn;
    }
    float invl = 1.0f / l;
    float4* op = (float4*)(o + qbase);
    #pragma unroll
    for (int d = 0; d < 16; d++) op[d] = scl4(acc[d], invl);
}

// ---------------- bf16x3 tensor-core GEMM (unchanged) ----------------
#define BM 128
#define BN 128
#define BK 32
#define SST 40
#define TEN_ELEMS (128*SST)
#define STAGE_ELEMS (4*TEN_ELEMS)
#define GEMM_SMEM (2*STAGE_ELEMS*2)

__device__ __forceinline__ void ldsm_x4(uint32_t &r0, uint32_t &r1, uint32_t &r2, uint32_t &r3, uint32_t addr) {
    asm volatile("ldmatrix.sync.aligned.m8n8.x4.shared.b16 {%0,%1,%2,%3}, [%4];"
                 : "=r"(r0), "=r"(r1), "=r"(r2), "=r"(r3) : "r"(addr));
}
__device__ __forceinline__ void ldsm_x2(uint32_t &r0, uint32_t &r1, uint32_t addr) {
    asm volatile("ldmatrix.sync.aligned.m8n8.x2.shared.b16 {%0,%1}, [%2];"
                 : "=r"(r0), "=r"(r1) : "r"(addr));
}
__device__ __forceinline__ void mma16816(float* c, const uint32_t* a, const uint32_t* b) {
    asm volatile("mma.sync.aligned.m16n8k16.row.col.f32.bf16.bf16.f32 "
                 "{%0,%1,%2,%3}, {%4,%5,%6,%7}, {%8,%9}, {%0,%1,%2,%3};"
                 : "+f"(c[0]), "+f"(c[1]), "+f"(c[2]), "+f"(c[3])
                 : "r"(a[0]), "r"(a[1]), "r"(a[2]), "r"(a[3]), "r"(b[0]), "r"(b[1]));
}
#define CP_ASYNC16(dst, src) asm volatile("cp.async.cg.shared.global [%0], [%1], 16;" :: "r"(dst), "l"(src))

__global__ void __launch_bounds__(256) gemm_bf16x3(
    const __nv_bfloat16* __restrict__ Ah, const __nv_bfloat16* __restrict__ Al,
    const __nv_bfloat16* __restrict__ Wh, const __nv_bfloat16* __restrict__ Wl,
    float* __restrict__ C, int M, int N, int K)
{
    extern __shared__ __nv_bfloat16 smbuf[];
    const int tid = threadIdx.x;
    const int lane = tid & 31, w = tid >> 5;
    const int wm = w & 1, wn = w >> 1;
    const int rowBase = blockIdx.y * BM;
    const int colBase = blockIdx.x * BN;
    uint32_t smbase = (uint32_t)__cvta_generic_to_shared(smbuf);

    float acc[4][4][4];
    #pragma unroll
    for (int i = 0; i < 4; i++)
        #pragma unroll
        for (int j = 0; j < 4; j++)
            #pragma unroll
            for (int e = 0; e < 4; e++) acc[i][j][e] = 0.0f;

    auto load_stage = [&](int st, int k0) {
        uint32_t base = smbase + st * STAGE_ELEMS * 2;
        #pragma unroll
        for (int it = 0; it < 2; it++) {
            int vv = tid + it * 256;
            int r = vv >> 2, cc = (vv & 3) * 8;
            uint32_t soff = (uint32_t)((r * SST + cc) * 2);
            size_t ga = (size_t)(rowBase + r) * K + k0 + cc;
            size_t gw = (size_t)(colBase + r) * K + k0 + cc;
            CP_ASYNC16(base + 0*TEN_ELEMS*2 + soff, Ah + ga);
            CP_ASYNC16(base + 1*TEN_ELEMS*2 + soff, Al + ga);
            CP_ASYNC16(base + 2*TEN_ELEMS*2 + soff, Wh + gw);
            CP_ASYNC16(base + 3*TEN_ELEMS*2 + soff, Wl + gw);
        }
        asm volatile("cp.async.commit_group;");
    };

    auto compute_stage = [&](int st) {
        uint32_t base = smbase + st * STAGE_ELEMS * 2;
        uint32_t aH = base;
        uint32_t aL = base + 1*TEN_ELEMS*2;
        uint32_t wH = base + 2*TEN_ELEMS*2;
        uint32_t wL = base + 3*TEN_ELEMS*2;
        const int quad = lane >> 3, r8 = lane & 7;
        #pragma unroll
        for (int kk = 0; kk < BK; kk += 16) {
            uint32_t ah[4][4], al[4][4], bh[4][2], bl[4][2];
            #pragma unroll
            for (int i = 0; i < 4; i++) {
                int row = wm*64 + i*16 + (quad & 1)*8 + r8;
                int col = kk + (quad >> 1)*8;
                uint32_t off = (uint32_t)((row * SST + col) * 2);
                ldsm_x4(ah[i][0], ah[i][1], ah[i][2], ah[i][3], aH + off);
                ldsm_x4(al[i][0], al[i][1], al[i][2], al[i][3], aL + off);
            }
            #pragma unroll
            for (int j = 0; j < 4; j++) {
                int nr = wn*32 + j*8 + (lane & 7);
                int kc = kk + ((lane >> 3) & 1)*8;
                uint32_t off = (uint32_t)((nr * SST + kc) * 2);
                ldsm_x2(bh[j][0], bh[j][1], wH + off);
                ldsm_x2(bl[j][0], bl[j][1], wL + off);
            }
            #pragma unroll
            for (int i = 0; i < 4; i++)
                #pragma unroll
                for (int j = 0; j < 4; j++) {
                    mma16816(acc[i][j], ah[i], bh[j]);
                    mma16816(acc[i][j], ah[i], bl[j]);
                    mma16816(acc[i][j], al[i], bh[j]);
                }
        }
    };

    load_stage(0, 0);
    asm volatile("cp.async.wait_group 0;");
    __syncthreads();
    int st = 0;
    for (int k0 = 0; k0 < K; k0 += BK) {
        bool nxt = (k0 + BK) < K;
        if (nxt) load_stage(st ^ 1, k0 + BK);
        compute_stage(st);
        if (nxt) asm volatile("cp.async.wait_group 0;");
        __syncthreads();
        st ^= 1;
    }

    const int g = lane >> 2, tg = lane & 3;
    #pragma unroll
    for (int i = 0; i < 4; i++) {
        int row = rowBase + wm*64 + i*16 + g;
        #pragma unroll
        for (int j = 0; j < 4; j++) {
            int col = colBase + wn*32 + j*8 + tg*2;
            *(float2*)(C + (size_t)row * N + col)       = make_float2(acc[i][j][0], acc[i][j][1]);
            *(float2*)(C + (size_t)(row + 8) * N + col) = make_float2(acc[i][j][2], acc[i][j][3]);
        }
    }
}

// ---------------- launch ----------------
extern "C" void kernel_launch(void* const* d_in, const int* in_sizes, int n_in,
                              void* d_out, int out_size)
{
    const float* x    = (const float*)d_in[0];
    const float* l1g  = (const float*)d_in[1];
    const float* l1b  = (const float*)d_in[2];
    const float* l2g  = (const float*)d_in[3];
    const float* l2b  = (const float*)d_in[4];
    const float* Wq   = (const float*)d_in[5];
    const float* bq   = (const float*)d_in[6];
    const float* Wk   = (const float*)d_in[7];
    const float* bk   = (const float*)d_in[8];
    const float* Wv   = (const float*)d_in[9];
    const float* bv   = (const float*)d_in[10];
    const float* Wo   = (const float*)d_in[11];
    const float* bo   = (const float*)d_in[12];
    const float* W1   = (const float*)d_in[13];
    const float* b1   = (const float*)d_in[14];
    const float* W2   = (const float*)d_in[15];
    const float* b2   = (const float*)d_in[16];
    float* out = (float*)d_out;

    float *qb, *kb, *vb, *ob, *h1, *big, *n0, *no, *nh2, *nh3, *bsq;
    __nv_bfloat16 *xh, *xl, *wh, *wl;
    cudaGetSymbolAddress((void**)&qb,  g_q);
    cudaGetSymbolAddress((void**)&kb,  g_k);
    cudaGetSymbolAddress((void**)&vb,  g_v);
    cudaGetSymbolAddress((void**)&ob,  g_o);
    cudaGetSymbolAddress((void**)&h1,  g_h1);
    cudaGetSymbolAddress((void**)&big, g_big);
    cudaGetSymbolAddress((void**)&xh,  g_xh);
    cudaGetSymbolAddress((void**)&xl,  g_xl);
    cudaGetSymbolAddress((void**)&wh,  g_wh);
    cudaGetSymbolAddress((void**)&wl,  g_wl);
    cudaGetSymbolAddress((void**)&n0,  g_n0);
    cudaGetSymbolAddress((void**)&no,  g_no);
    cudaGetSymbolAddress((void**)&nh2, g_nh2);
    cudaGetSymbolAddress((void**)&nh3, g_nh3);
    cudaGetSymbolAddress((void**)&bsq, g_b2);

    cudaFuncSetAttribute(gemm_bf16x3, cudaFuncAttributeMaxDynamicSharedMemorySize, GEMM_SMEM);

    dim3 gE(ED / BN, NR / BM);
    dim3 gF(FD / BN, NR / BM);
    const int sE  = (ED*ED/4 + 255) / 256;
    const int sEF = (FD*ED/4 + 255) / 256;

    sqsum6<<<6, 256>>>(bq, bk, bv, bo, b1, b2, bsq);
    ln_kernel<ED, 128><<<NR, 128>>>(x, l1g, l1b, nullptr, xh, xl, n0, 0);

    split_kernel<<<sE, 256>>>(Wq, wh, wl, ED*ED/4);
    gemm_bf16x3<<<gE, 256, GEMM_SMEM>>>(xh, xl, wh, wl, qb, NR, ED, ED);
    split_kernel<<<sE, 256>>>(Wk, wh, wl, ED*ED/4);
    gemm_bf16x3<<<gE, 256, GEMM_SMEM>>>(xh, xl, wh, wl, kb, NR, ED, ED);
    split_kernel<<<sE, 256>>>(Wv, wh, wl, ED*ED/4);
    gemm_bf16x3<<<gE, 256, GEMM_SMEM>>>(xh, xl, wh, wl, vb, NR, ED, ED);
    manlin_epi<ED, 128><<<NR, 128>>>(qb, n0, bq, 0, nullptr, qb, nullptr, nullptr, nullptr, FLAG_LOGMAP);
    manlin_epi<ED, 128><<<NR, 128>>>(kb, n0, bk, 1, nullptr, kb, nullptr, nullptr, nullptr, FLAG_LOGMAP);
    manlin_epi<ED, 128><<<NR, 128>>>(vb, n0, bv, 2, nullptr, vb, nullptr, nullptr, nullptr, FLAG_LOGMAP);

    attn_kernel<<<BB * NH, 128>>>(qb, kb, vb, ob);
    expmap_rows<ED, 128><<<NR, 128>>>(ob, xh, xl, no);

    split_kernel<<<sE, 256>>>(Wo, wh, wl, ED*ED/4);
    gemm_bf16x3<<<gE, 256, GEMM_SMEM>>>(xh, xl, wh, wl, big, NR, ED, ED);
    manlin_epi<ED, 128><<<NR, 128>>>(big, no, bo, 3, x, h1, nullptr, nullptr, nullptr, FLAG_RESID);

    ln_kernel<ED, 128><<<NR, 128>>>(h1, l2g, l2b, nullptr, xh, xl, nh2, 1);

    split_kernel<<<sEF, 256>>>(W1, wh, wl, FD*ED/4);
    gemm_bf16x3<<<gF, 256, GEMM_SMEM>>>(xh, xl, wh, wl, big, NR, FD, ED);
    manlin_epi<FD, 256><<<NR, 256>>>(big, nh2, b1, 4, nullptr, nullptr, xh, xl, nh3, FLAG_MOBRELU);

    split_kernel<<<sEF, 256>>>(W2, wh, wl, ED*FD/4);
    gemm_bf16x3<<<gE, 256, GEMM_SMEM>>>(xh, xl, wh, wl, qb, NR, ED, FD);
    manlin_epi<ED, 128><<<NR, 128>>>(qb, nh3, b2, 5, h1, out, nullptr, nullptr, nullptr, FLAG_MOBRELU | FLAG_RESID);
}

// round 5
// speedup vs baseline: 6.6816x; 1.1259x over previous
#include <cuda_runtime.h>
#include <cuda_bf16.h>
#include <math.h>
#include <stdint.h>

// ---------------- problem constants ----------------
#define SEQ 128
#define BB  256
#define ED  512
#define FD  2048
#define NH  8
#define HD  64
#define NR  (SEQ*BB)   // 32768 rows
#define QKVW 1536      // fused qkv row width

static __device__ __forceinline__ float maxnorm() { return (float)(1.0 - 1e-5); }

// ---------------- scratch ----------------
__device__ float g_qkv[(size_t)NR*QKVW];
__device__ float g_o  [(size_t)NR*ED];
__device__ float g_h1 [(size_t)NR*ED];
__device__ float g_big[(size_t)NR*FD];
__device__ __nv_bfloat16 g_xh[(size_t)NR*FD];
__device__ __nv_bfloat16 g_xl[(size_t)NR*FD];
__device__ __nv_bfloat16 g_wh[(size_t)3*1024*1024];
__device__ __nv_bfloat16 g_wl[(size_t)3*1024*1024];
__device__ float g_n0 [NR];
__device__ float g_no [NR];
__device__ float g_nh2[NR];
__device__ float g_nh3[NR];
__device__ float g_b2 [8];

// weight element offsets inside g_wh/g_wl
#define WQ0 0
#define WK0 262144
#define WV0 524288
#define WO0 786432
#define W10 1048576
#define W20 2097152

#define FLAG_LOGMAP  1
#define FLAG_MOBRELU 2
#define FLAG_RESID   4

// ---------------- block reduction (fp32, pairwise) ----------------
template <int T>
__device__ __forceinline__ float blockSumF(float v) {
    __shared__ float sh[T / 32];
    #pragma unroll
    for (int o = 16; o > 0; o >>= 1) v += __shfl_xor_sync(0xffffffffu, v, o);
    int lane = threadIdx.x & 31, w = threadIdx.x >> 5;
    if (lane == 0) sh[w] = v;
    __syncthreads();
    if (threadIdx.x < 32) {
        float t = (threadIdx.x < T / 32) ? sh[threadIdx.x] : 0.0f;
        #pragma unroll
        for (int o = 16; o > 0; o >>= 1) t += __shfl_xor_sync(0xffffffffu, t, o);
        if (threadIdx.x == 0) sh[0] = t;
    }
    __syncthreads();
    float r = sh[0];
    __syncthreads();
    return r;
}

__device__ __forceinline__ void split1(float x, __nv_bfloat16 &h, __nv_bfloat16 &l) {
    h = __float2bfloat16(x);
    l = __float2bfloat16(x - __bfloat162float(h));
}

// ---------------- all 6 bias squared-norms ----------------
__global__ void sqsum6(const float* bq, const float* bk, const float* bv,
                       const float* bo, const float* b1, const float* b2,
                       float* __restrict__ out) {
    const float* p;
    int n;
    switch (blockIdx.x) {
        case 0: p = bq; n = ED; break;
        case 1: p = bk; n = ED; break;
        case 2: p = bv; n = ED; break;
        case 3: p = bo; n = ED; break;
        case 4: p = b1; n = FD; break;
        default: p = b2; n = ED; break;
    }
    float s = 0.0f;
    for (int i = threadIdx.x; i < n; i += 256) { float x = p[i]; s += x * x; }
    s = blockSumF<256>(s);
    if (threadIdx.x == 0) out[blockIdx.x] = s;
}

// ---------------- one launch: split all 6 weights into concat hi/lo ----------------
__global__ void split_all(const float* Wq, const float* Wk, const float* Wv,
                          const float* Wo, const float* W1, const float* W2,
                          __nv_bfloat16* __restrict__ h, __nv_bfloat16* __restrict__ l) {
    const float* src; size_t off; int n4;
    switch (blockIdx.y) {
        case 0: src = Wq; off = WQ0; n4 = 65536;  break;
        case 1: src = Wk; off = WK0; n4 = 65536;  break;
        case 2: src = Wv; off = WV0; n4 = 65536;  break;
        case 3: src = Wo; off = WO0; n4 = 65536;  break;
        case 4: src = W1; off = W10; n4 = 262144; break;
        default: src = W2; off = W20; n4 = 262144; break;
    }
    int i = blockIdx.x * 256 + threadIdx.x;
    if (i < n4) {
        float4 v = ((const float4*)src)[i];
        __nv_bfloat16 h0,l0,h1,l1,h2,l2,h3,l3;
        split1(v.x, h0, l0); split1(v.y, h1, l1);
        split1(v.z, h2, l2); split1(v.w, h3, l3);
        __nv_bfloat162* hp = (__nv_bfloat162*)(h + off);
        __nv_bfloat162* lp = (__nv_bfloat162*)(l + off);
        hp[i*2]   = __nv_bfloat162(h0, h1);
        hp[i*2+1] = __nv_bfloat162(h2, h3);
        lp[i*2]   = __nv_bfloat162(l0, l1);
        lp[i*2+1] = __nv_bfloat162(l2, l3);
    }
}

// vector helpers
#define VOP4(dst, ex, ey, ez, ew) do { dst.x=(ex); dst.y=(ey); dst.z=(ez); dst.w=(ew); } while(0)
__device__ __forceinline__ float dot4(float4 a, float4 b) { return a.x*b.x + a.y*b.y + a.z*b.z + a.w*b.w; }
__device__ __forceinline__ float sq4(float4 a) { return dot4(a, a); }
__device__ __forceinline__ float4 scl4(float4 a, float s) { float4 r; VOP4(r, a.x*s, a.y*s, a.z*s, a.w*s); return r; }

// ---------------- ln block ----------------
template <int E, int T>
__global__ void __launch_bounds__(T) ln_kernel(
    const float* __restrict__ x, const float* __restrict__ g, const float* __restrict__ b,
    float* __restrict__ outf, __nv_bfloat16* __restrict__ oh, __nv_bfloat16* __restrict__ ol,
    float* __restrict__ out_norm, int do_projx)
{
    constexpr int V4 = E / (T * 4);
    const size_t row = blockIdx.x;
    const int tid = threadIdx.x;
    const float MAXN = maxnorm();
    const float4* xp = (const float4*)(x + row * E);
    const float4* gp = (const float4*)g;
    const float4* bp = (const float4*)b;
    float4 v[V4];
    float ss = 0.0f;
    #pragma unroll
    for (int i = 0; i < V4; i++) { v[i] = xp[tid*V4 + i]; ss += sq4(v[i]); }
    float n0 = sqrtf(blockSumF<T>(ss) + 1e-30f);
    float lf = atanhf(fminf(n0, MAXN)) / n0;
    float sm = 0.0f;
    #pragma unroll
    for (int i = 0; i < V4; i++) { v[i] = scl4(v[i], lf); sm += v[i].x + v[i].y + v[i].z + v[i].w; }
    float mu = blockSumF<T>(sm) * (1.0f / E);
    float vv = 0.0f;
    #pragma unroll
    for (int i = 0; i < V4; i++) {
        float4 d; VOP4(d, v[i].x-mu, v[i].y-mu, v[i].z-mu, v[i].w-mu);
        vv += sq4(d);
    }
    float var = blockSumF<T>(vv) * (1.0f / E);
    float inv = rsqrtf(var + 1e-5f);
    float s2 = 0.0f;
    #pragma unroll
    for (int i = 0; i < V4; i++) {
        float4 gg = gp[tid*V4 + i], bb = bp[tid*V4 + i];
        VOP4(v[i], (v[i].x-mu)*inv*gg.x + bb.x, (v[i].y-mu)*inv*gg.y + bb.y,
                   (v[i].z-mu)*inv*gg.z + bb.z, (v[i].w-mu)*inv*gg.w + bb.w);
        s2 += sq4(v[i]);
    }
    float ny = sqrtf(blockSumF<T>(s2) + 1e-30f);
    float ef = tanhf(ny) / ny;
    #pragma unroll
    for (int i = 0; i < V4; i++) v[i] = scl4(v[i], ef);
    if (do_projx) {
        float s3 = 0.0f;
        #pragma unroll
        for (int i = 0; i < V4; i++) s3 += sq4(v[i]);
        float n = sqrtf(blockSumF<T>(s3) + 1e-30f);
        if (n > MAXN) { float ps = MAXN / n;
            #pragma unroll
            for (int i = 0; i < V4; i++) v[i] = scl4(v[i], ps); }
    }
    float s4 = 0.0f;
    #pragma unroll
    for (int i = 0; i < V4; i++) {
        if (outf) ((float4*)(outf + row*E))[tid*V4 + i] = v[i];
        if (oh) {
            __nv_bfloat16 h0,l0,h1,l1,h2,l2,h3,l3;
            split1(v[i].x,h0,l0); split1(v[i].y,h1,l1); split1(v[i].z,h2,l2); split1(v[i].w,h3,l3);
            ((__nv_bfloat162*)(oh + row*E))[tid*V4*2 + i*2]   = __nv_bfloat162(h0,h1);
            ((__nv_bfloat162*)(oh + row*E))[tid*V4*2 + i*2+1] = __nv_bfloat162(h2,h3);
            ((__nv_bfloat162*)(ol + row*E))[tid*V4*2 + i*2]   = __nv_bfloat162(l0,l1);
            ((__nv_bfloat162*)(ol + row*E))[tid*V4*2 + i*2+1] = __nv_bfloat162(l2,l3);
        }
        s4 += sq4(v[i]);
    }
    float nf = sqrtf(blockSumF<T>(s4) + 1e-30f);
    if (tid == 0) out_norm[row] = nf;
}

// ---------------- expmap0 rows -> bf16 split + norm ----------------
template <int E, int T>
__global__ void __launch_bounds__(T) expmap_rows(
    const float* __restrict__ x, __nv_bfloat16* __restrict__ oh, __nv_bfloat16* __restrict__ ol,
    float* __restrict__ out_norm)
{
    constexpr int V4 = E / (T * 4);
    const size_t row = blockIdx.x;
    const int tid = threadIdx.x;
    const float4* xp = (const float4*)(x + row * E);
    float4 v[V4];
    float ss = 0.0f;
    #pragma unroll
    for (int i = 0; i < V4; i++) { v[i] = xp[tid*V4 + i]; ss += sq4(v[i]); }
    float n = sqrtf(blockSumF<T>(ss) + 1e-30f);
    float ef = tanhf(n) / n;
    float s2 = 0.0f;
    #pragma unroll
    for (int i = 0; i < V4; i++) {
        v[i] = scl4(v[i], ef);
        __nv_bfloat16 h0,l0,h1,l1,h2,l2,h3,l3;
        split1(v[i].x,h0,l0); split1(v[i].y,h1,l1); split1(v[i].z,h2,l2); split1(v[i].w,h3,l3);
        ((__nv_bfloat162*)(oh + row*E))[tid*V4*2 + i*2]   = __nv_bfloat162(h0,h1);
        ((__nv_bfloat162*)(oh + row*E))[tid*V4*2 + i*2+1] = __nv_bfloat162(h2,h3);
        ((__nv_bfloat162*)(ol + row*E))[tid*V4*2 + i*2]   = __nv_bfloat162(l0,l1);
        ((__nv_bfloat162*)(ol + row*E))[tid*V4*2 + i*2+1] = __nv_bfloat162(l2,l3);
        s2 += sq4(v[i]);
    }
    float nf = sqrtf(blockSumF<T>(s2) + 1e-30f);
    if (tid == 0) out_norm[row] = nf;
}

// ---------------- man_linear epilogue (ldm = row stride of mx/outf) ----------------
template <int E, int T>
__global__ void __launch_bounds__(T) manlin_epi(
    const float* __restrict__ mx, int ldm, const float* __restrict__ xnb,
    const float* __restrict__ bias, int b2idx,
    const float* __restrict__ resid,
    float* __restrict__ outf, __nv_bfloat16* __restrict__ oh, __nv_bfloat16* __restrict__ ol,
    float* __restrict__ out_norm, int flags)
{
    constexpr int V4 = E / (T * 4);
    const size_t row = blockIdx.x;
    const int tid = threadIdx.x;
    const float MAXN = maxnorm();
    const float4* mp = (const float4*)(mx + row*(size_t)ldm);
    const float4* bp = (const float4*)bias;
    float4 v[V4], bv[V4];
    float ss = 0.0f;
    #pragma unroll
    for (int i = 0; i < V4; i++) { v[i] = mp[tid*V4 + i]; ss += sq4(v[i]); }
    float mxn = sqrtf(blockSumF<T>(ss) + 1e-30f);
    float xn = xnb[row];
    float s = tanhf(mxn / xn * atanhf(fminf(xn, MAXN))) / mxn;
    float dxy = 0.0f, dx2 = 0.0f;
    #pragma unroll
    for (int i = 0; i < V4; i++) {
        v[i] = scl4(v[i], s);
        bv[i] = bp[tid*V4 + i];
        dxy += dot4(v[i], bv[i]);
        dx2 += sq4(v[i]);
    }
    float xy = blockSumF<T>(dxy);
    float x2 = blockSumF<T>(dx2);
    float y2 = g_b2[b2idx];
    float a = 1.0f + 2.0f*xy + y2;
    float c = 1.0f - x2;
    float den = fmaxf(1.0f + 2.0f*xy + x2*y2, 1e-15f);
    float invd = 1.0f / den;
    float zz = 0.0f;
    #pragma unroll
    for (int i = 0; i < V4; i++) {
        VOP4(v[i], (a*v[i].x + c*bv[i].x)*invd, (a*v[i].y + c*bv[i].y)*invd,
                   (a*v[i].z + c*bv[i].z)*invd, (a*v[i].w + c*bv[i].w)*invd);
        zz += sq4(v[i]);
    }
    {
        float zn = sqrtf(blockSumF<T>(zz) + 1e-30f);
        if (zn > MAXN) { float ps = MAXN / zn;
            #pragma unroll
            for (int i = 0; i < V4; i++) v[i] = scl4(v[i], ps); }
    }
    if (flags & FLAG_MOBRELU) {
        float s0 = 0.0f;
        #pragma unroll
        for (int i = 0; i < V4; i++) s0 += sq4(v[i]);
        float n = sqrtf(blockSumF<T>(s0) + 1e-30f);
        float lf = atanhf(fminf(n, MAXN)) / n;
        float s1 = 0.0f;
        #pragma unroll
        for (int i = 0; i < V4; i++) {
            VOP4(v[i], fmaxf(lf*v[i].x, 0.0f), fmaxf(lf*v[i].y, 0.0f),
                       fmaxf(lf*v[i].z, 0.0f), fmaxf(lf*v[i].w, 0.0f));
            s1 += sq4(v[i]);
        }
        float nr = sqrtf(blockSumF<T>(s1) + 1e-30f);
        float ef = tanhf(nr) / nr;
        float s2 = 0.0f;
        #pragma unroll
        for (int i = 0; i < V4; i++) { v[i] = scl4(v[i], ef); s2 += sq4(v[i]); }
        float n2 = sqrtf(blockSumF<T>(s2) + 1e-30f);
        if (n2 > MAXN) { float ps = MAXN / n2;
            #pragma unroll
            for (int i = 0; i < V4; i++) v[i] = scl4(v[i], ps); }
    }
    if (flags & FLAG_RESID) {
        const float4* rp = (const float4*)(resid + row*E);
        float4 rv[V4];
        float d1 = 0.0f, d2 = 0.0f, d3 = 0.0f;
        #pragma unroll
        for (int i = 0; i < V4; i++) {
            rv[i] = rp[tid*V4 + i];
            d1 += dot4(v[i], rv[i]);
            d2 += sq4(rv[i]);
            d3 += sq4(v[i]);
        }
        float rxy = blockSumF<T>(d1);
        float ry2 = blockSumF<T>(d2);
        float rx2 = blockSumF<T>(d3);
        float ra = 1.0f + 2.0f*rxy + ry2;
        float rc = 1.0f - rx2;
        float rden = fmaxf(1.0f + 2.0f*rxy + rx2*ry2, 1e-15f);
        float rinv = 1.0f / rden;
        float s3 = 0.0f;
        #pragma unroll
        for (int i = 0; i < V4; i++) {
            VOP4(v[i], (ra*v[i].x + rc*rv[i].x)*rinv, (ra*v[i].y + rc*rv[i].y)*rinv,
                       (ra*v[i].z + rc*rv[i].z)*rinv, (ra*v[i].w + rc*rv[i].w)*rinv);
            s3 += sq4(v[i]);
        }
        float zn = sqrtf(blockSumF<T>(s3) + 1e-30f);
        if (zn > MAXN) { float ps = MAXN / zn;
            #pragma unroll
            for (int i = 0; i < V4; i++) v[i] = scl4(v[i], ps); }
    }
    if (flags & FLAG_LOGMAP) {
        float s4 = 0.0f;
        #pragma unroll
        for (int i = 0; i < V4; i++) s4 += sq4(v[i]);
        float n = sqrtf(blockSumF<T>(s4) + 1e-30f);
        float lf = atanhf(fminf(n, MAXN)) / n;
        #pragma unroll
        for (int i = 0; i < V4; i++) v[i] = scl4(v[i], lf);
    }
    float s5 = 0.0f;
    #pragma unroll
    for (int i = 0; i < V4; i++) {
        if (outf) ((float4*)(outf + row*(size_t)ldm))[tid*V4 + i] = v[i];
        if (oh) {
            __nv_bfloat16 h0,l0,h1,l1,h2,l2,h3,l3;
            split1(v[i].x,h0,l0); split1(v[i].y,h1,l1); split1(v[i].z,h2,l2); split1(v[i].w,h3,l3);
            ((__nv_bfloat162*)(oh + row*E))[tid*V4*2 + i*2]   = __nv_bfloat162(h0,h1);
            ((__nv_bfloat162*)(oh + row*E))[tid*V4*2 + i*2+1] = __nv_bfloat162(h2,h3);
            ((__nv_bfloat162*)(ol + row*E))[tid*V4*2 + i*2]   = __nv_bfloat162(l0,l1);
            ((__nv_bfloat162*)(ol + row*E))[tid*V4*2 + i*2+1] = __nv_bfloat162(l2,l3);
        }
        s5 += sq4(v[i]);
    }
    if (out_norm) {
        float nf = sqrtf(blockSumF<T>(s5) + 1e-30f);
        if (tid == 0) out_norm[row] = nf;
    }
}

// ---------------- attention (reads fused qkv buffer, stride QKVW) ----------------
__global__ void __launch_bounds__(128) attn_kernel(
    const float* __restrict__ qkv, float* __restrict__ o)
{
    int bh = blockIdx.x;
    int b  = bh >> 3;
    int h  = bh & 7;
    int t  = threadIdx.x;
    const float scale = 0.125f;
    size_t qbase = ((size_t)t*BB + b)*QKVW + (size_t)h*HD;
    float4 q4[16], acc[16];
    const float4* qp = (const float4*)(qkv + qbase);
    #pragma unroll
    for (int d = 0; d < 16; d++) { q4[d] = scl4(qp[d], scale); acc[d] = make_float4(0,0,0,0); }
    float m = -1e30f, l = 0.0f;
    __shared__ float4 ks[16][16];
    __shared__ float4 vs[16][16];
    for (int j0 = 0; j0 < SEQ; j0 += 16) {
        __syncthreads();
        #pragma unroll
        for (int it = 0; it < 2; it++) {
            int idx = t + it*128;
            int jj = idx >> 4, d4 = idx & 15;
            size_t g = ((size_t)(j0 + jj)*BB + b)*QKVW + (size_t)h*HD + d4*4;
            ks[jj][d4] = *(const float4*)(qkv + 512 + g);
            vs[jj][d4] = *(const float4*)(qkv + 1024 + g);
        }
        __syncthreads();
        float sc[16];
        #pragma unroll
        for (int jj = 0; jj < 16; jj++) {
            float s = 0.0f;
            #pragma unroll
            for (int d = 0; d < 16; d++) s += dot4(q4[d], ks[jj][d]);
            sc[jj] = s;
        }
        float mn = m;
        #pragma unroll
        for (int jj = 0; jj < 16; jj++) mn = fmaxf(mn, sc[jj]);
        float corr = expf(m - mn);
        l *= corr;
        #pragma unroll
        for (int d = 0; d < 16; d++) acc[d] = scl4(acc[d], corr);
        #pragma unroll
        for (int jj = 0; jj < 16; jj++) {
            float p = expf(sc[jj] - mn);
            l += p;
            #pragma unroll
            for (int d = 0; d < 16; d++) {
                float4 vv = vs[jj][d];
                acc[d].x += p*vv.x; acc[d].y += p*vv.y; acc[d].z += p*vv.z; acc[d].w += p*vv.w;
            }
        }
        m = mn;
    }
    float invl = 1.0f / l;
    size_t obase = ((size_t)t*BB + b)*ED + (size_t)h*HD;
    float4* op = (float4*)(o + obase);
    #pragma unroll
    for (int d = 0; d < 16; d++) op[d] = scl4(acc[d], invl);
}

// ================= bf16x3 HMMA GEMM: 3-stage pipeline, 64B swizzled rows =================
#define BM 128
#define BN 128
#define BK 32
#define TEN_B   8192                 // bytes per tensor tile: 128 rows * 64B
#define STAGE_B (4*TEN_B)            // Ah, Al, Wh, Wl = 32 KB
#define GEMM_SMEM (3*STAGE_B)        // 96 KB, 3 stages

__device__ __forceinline__ uint32_t saddr(int r, int colElem) {
    // 64B rows, XOR chunk swizzle: conflict-free ldmatrix + stores
    return (uint32_t)(r*64 + ((((colElem >> 3) ^ ((r >> 1) & 3))) << 4));
}
__device__ __forceinline__ void ldsm_x4(uint32_t &r0, uint32_t &r1, uint32_t &r2, uint32_t &r3, uint32_t addr) {
    asm volatile("ldmatrix.sync.aligned.m8n8.x4.shared.b16 {%0,%1,%2,%3}, [%4];"
                 : "=r"(r0), "=r"(r1), "=r"(r2), "=r"(r3) : "r"(addr));
}
__device__ __forceinline__ void ldsm_x2(uint32_t &r0, uint32_t &r1, uint32_t addr) {
    asm volatile("ldmatrix.sync.aligned.m8n8.x2.shared.b16 {%0,%1}, [%2];"
                 : "=r"(r0), "=r"(r1) : "r"(addr));
}
__device__ __forceinline__ void mma16816(float* c, const uint32_t* a, const uint32_t* b) {
    asm volatile("mma.sync.aligned.m16n8k16.row.col.f32.bf16.bf16.f32 "
                 "{%0,%1,%2,%3}, {%4,%5,%6,%7}, {%8,%9}, {%0,%1,%2,%3};"
                 : "+f"(c[0]), "+f"(c[1]), "+f"(c[2]), "+f"(c[3])
                 : "r"(a[0]), "r"(a[1]), "r"(a[2]), "r"(a[3]), "r"(b[0]), "r"(b[1]));
}
#define CP_ASYNC16(dst, src) asm volatile("cp.async.cg.shared.global [%0], [%1], 16;" :: "r"(dst), "l"(src))

__global__ void __launch_bounds__(256, 2) gemm_bf16x3(
    const __nv_bfloat16* __restrict__ Ah, const __nv_bfloat16* __restrict__ Al,
    const __nv_bfloat16* __restrict__ Wh, const __nv_bfloat16* __restrict__ Wl,
    float* __restrict__ C, int M, int N, int K)
{
    extern __shared__ __nv_bfloat16 smbuf[];
    const int tid = threadIdx.x;
    const int lane = tid & 31, w = tid >> 5;
    const int wm = w & 1, wn = w >> 1;
    const int rowBase = blockIdx.y * BM;
    const int colBase = blockIdx.x * BN;
    uint32_t smbase = (uint32_t)__cvta_generic_to_shared(smbuf);

    float acc[4][4][4];
    #pragma unroll
    for (int i = 0; i < 4; i++)
        #pragma unroll
        for (int j = 0; j < 4; j++)
            #pragma unroll
            for (int e = 0; e < 4; e++) acc[i][j][e] = 0.0f;

    auto load_stage = [&](int st, int k0) {
        uint32_t base = smbase + st * STAGE_B;
        #pragma unroll
        for (int it = 0; it < 8; it++) {
            int idx = tid + (it << 8);
            int tensor = idx >> 9;          // 512 chunks per tensor
            int cid = idx & 511;
            int r = cid >> 2, c = cid & 3;  // 4 x 16B chunks per 64B row
            uint32_t dst = base + tensor * TEN_B
                         + (uint32_t)(r*64 + ((c ^ ((r >> 1) & 3)) << 4));
            const __nv_bfloat16* src;
            if (tensor == 0)      src = Ah + (size_t)(rowBase + r) * K + k0 + c * 8;
            else if (tensor == 1) src = Al + (size_t)(rowBase + r) * K + k0 + c * 8;
            else if (tensor == 2) src = Wh + (size_t)(colBase + r) * K + k0 + c * 8;
            else                  src = Wl + (size_t)(colBase + r) * K + k0 + c * 8;
            CP_ASYNC16(dst, src);
        }
        asm volatile("cp.async.commit_group;");
    };

    auto compute_stage = [&](int st) {
        uint32_t base = smbase + st * STAGE_B;
        uint32_t aH = base;
        uint32_t aL = base + 1*TEN_B;
        uint32_t wH = base + 2*TEN_B;
        uint32_t wL = base + 3*TEN_B;
        const int quad = lane >> 3, r8 = lane & 7;
        #pragma unroll
        for (int kk = 0; kk < BK; kk += 16) {
            uint32_t ah[4][4], al[4][4], bh[4][2], bl[4][2];
            #pragma unroll
            for (int i = 0; i < 4; i++) {
                int row = wm*64 + i*16 + (quad & 1)*8 + r8;
                int col = kk + (quad >> 1)*8;
                uint32_t off = saddr(row, col);
                ldsm_x4(ah[i][0], ah[i][1], ah[i][2], ah[i][3], aH + off);
                ldsm_x4(al[i][0], al[i][1], al[i][2], al[i][3], aL + off);
            }
            #pragma unroll
            for (int j = 0; j < 4; j++) {
                int nr = wn*32 + j*8 + (lane & 7);
                int kc = kk + ((lane >> 3) & 1)*8;
                uint32_t off = saddr(nr, kc);
                ldsm_x2(bh[j][0], bh[j][1], wH + off);
                ldsm_x2(bl[j][0], bl[j][1], wL + off);
            }
            // pass-major: 16 independent acc chains per pass
            #pragma unroll
            for (int i = 0; i < 4; i++)
                #pragma unroll
                for (int j = 0; j < 4; j++) mma16816(acc[i][j], ah[i], bh[j]);
            #pragma unroll
            for (int i = 0; i < 4; i++)
                #pragma unroll
                for (int j = 0; j < 4; j++) mma16816(acc[i][j], ah[i], bl[j]);
            #pragma unroll
            for (int i = 0; i < 4; i++)
                #pragma unroll
                for (int j = 0; j < 4; j++) mma16816(acc[i][j], al[i], bh[j]);
        }
    };

    const int nkb = K / BK;
    load_stage(0, 0);
    load_stage(1, BK);
    for (int kb = 0; kb < nkb; kb++) {
        if (kb == nkb - 1) { asm volatile("cp.async.wait_group 0;"); }
        else               { asm volatile("cp.async.wait_group 1;"); }
        __syncthreads();
        if (kb + 2 < nkb) load_stage((kb + 2) % 3, (kb + 2) * BK);
        compute_stage(kb % 3);
    }

    const int g = lane >> 2, tg = lane & 3;
    #pragma unroll
    for (int i = 0; i < 4; i++) {
        int row = rowBase + wm*64 + i*16 + g;
        #pragma unroll
        for (int j = 0; j < 4; j++) {
            int col = colBase + wn*32 + j*8 + tg*2;
            *(float2*)(C + (size_t)row * N + col)       = make_float2(acc[i][j][0], acc[i][j][1]);
            *(float2*)(C + (size_t)(row + 8) * N + col) = make_float2(acc[i][j][2], acc[i][j][3]);
        }
    }
}

// ---------------- launch ----------------
extern "C" void kernel_launch(void* const* d_in, const int* in_sizes, int n_in,
                              void* d_out, int out_size)
{
    const float* x    = (const float*)d_in[0];
    const float* l1g  = (const float*)d_in[1];
    const float* l1b  = (const float*)d_in[2];
    const float* l2g  = (const float*)d_in[3];
    const float* l2b  = (const float*)d_in[4];
    const float* Wq   = (const float*)d_in[5];
    const float* bq   = (const float*)d_in[6];
    const float* Wk   = (const float*)d_in[7];
    const float* bk   = (const float*)d_in[8];
    const float* Wv   = (const float*)d_in[9];
    const float* bv   = (const float*)d_in[10];
    const float* Wo   = (const float*)d_in[11];
    const float* bo   = (const float*)d_in[12];
    const float* W1   = (const float*)d_in[13];
    const float* b1   = (const float*)d_in[14];
    const float* W2   = (const float*)d_in[15];
    const float* b2   = (const float*)d_in[16];
    float* out = (float*)d_out;

    float *qkv, *ob, *h1, *big, *n0, *no, *nh2, *nh3, *bsq;
    __nv_bfloat16 *xh, *xl, *wh, *wl;
    cudaGetSymbolAddress((void**)&qkv, g_qkv);
    cudaGetSymbolAddress((void**)&ob,  g_o);
    cudaGetSymbolAddress((void**)&h1,  g_h1);
    cudaGetSymbolAddress((void**)&big, g_big);
    cudaGetSymbolAddress((void**)&xh,  g_xh);
    cudaGetSymbolAddress((void**)&xl,  g_xl);
    cudaGetSymbolAddress((void**)&wh,  g_wh);
    cudaGetSymbolAddress((void**)&wl,  g_wl);
    cudaGetSymbolAddress((void**)&n0,  g_n0);
    cudaGetSymbolAddress((void**)&no,  g_no);
    cudaGetSymbolAddress((void**)&nh2, g_nh2);
    cudaGetSymbolAddress((void**)&nh3, g_nh3);
    cudaGetSymbolAddress((void**)&bsq, g_b2);

    cudaFuncSetAttribute(gemm_bf16x3, cudaFuncAttributeMaxDynamicSharedMemorySize, GEMM_SMEM);

    // 1) split all weights (one launch), bias norms, ln1
    split_all<<<dim3(1024, 6), 256>>>(Wq, Wk, Wv, Wo, W1, W2, wh, wl);
    sqsum6<<<6, 256>>>(bq, bk, bv, bo, b1, b2, bsq);
    ln_kernel<ED, 128><<<NR, 128>>>(x, l1g, l1b, nullptr, xh, xl, n0, 0);

    // 2) fused QKV projection: C[NR,1536] = x @ [Wq;Wk;Wv]^T
    gemm_bf16x3<<<dim3(QKVW/BN, NR/BM), 256, GEMM_SMEM>>>(xh, xl, wh + WQ0, wl + WQ0, qkv, NR, QKVW, ED);
    manlin_epi<ED, 128><<<NR, 128>>>(qkv + 0,    QKVW, n0, bq, 0, nullptr, qkv + 0,    nullptr, nullptr, nullptr, FLAG_LOGMAP);
    manlin_epi<ED, 128><<<NR, 128>>>(qkv + 512,  QKVW, n0, bk, 1, nullptr, qkv + 512,  nullptr, nullptr, nullptr, FLAG_LOGMAP);
    manlin_epi<ED, 128><<<NR, 128>>>(qkv + 1024, QKVW, n0, bv, 2, nullptr, qkv + 1024, nullptr, nullptr, nullptr, FLAG_LOGMAP);

    // 3) attention + expmap split
    attn_kernel<<<BB * NH, 128>>>(qkv, ob);
    expmap_rows<ED, 128><<<NR, 128>>>(ob, xh, xl, no);

    // 4) output projection + residual
    gemm_bf16x3<<<dim3(ED/BN, NR/BM), 256, GEMM_SMEM>>>(xh, xl, wh + WO0, wl + WO0, big, NR, ED, ED);
    manlin_epi<ED, 128><<<NR, 128>>>(big, ED, no, bo, 3, x, h1, nullptr, nullptr, nullptr, FLAG_RESID);

    // 5) ln2
    ln_kernel<ED, 128><<<NR, 128>>>(h1, l2g, l2b, nullptr, xh, xl, nh2, 1);

    // 6) fc1 + mob_relu
    gemm_bf16x3<<<dim3(FD/BN, NR/BM), 256, GEMM_SMEM>>>(xh, xl, wh + W10, wl + W10, big, NR, FD, ED);
    manlin_epi<FD, 256><<<NR, 256>>>(big, FD, nh2, b1, 4, nullptr, nullptr, xh, xl, nh3, FLAG_MOBRELU);

    // 7) fc2 + mob_relu + residual
    gemm_bf16x3<<<dim3(ED/BN, NR/BM), 256, GEMM_SMEM>>>(xh, xl, wh + W20, wl + W20, qkv, NR, ED, FD);
    manlin_epi<ED, 128><<<NR, 128>>>(qkv, ED, nh3, b2, 5, h1, out, nullptr, nullptr, nullptr, FLAG_MOBRELU | FLAG_RESID);
}

// round 6
// speedup vs baseline: 6.7120x; 1.0045x over previous
#include <cuda_runtime.h>
#include <cuda_bf16.h>
#include <math.h>
#include <stdint.h>

// ---------------- problem constants ----------------
#define SEQ 128
#define BB  256
#define ED  512
#define FD  2048
#define NH  8
#define HD  64
#define NR  (SEQ*BB)   // 32768 rows
#define QKVW 1536      // fused qkv row width

static __device__ __forceinline__ float maxnorm() { return (float)(1.0 - 1e-5); }

// ---------------- scratch ----------------
__device__ float g_qkv[(size_t)NR*QKVW];
__device__ float g_o  [(size_t)NR*ED];
__device__ float g_h1 [(size_t)NR*ED];
__device__ float g_big[(size_t)NR*FD];
__device__ __nv_bfloat16 g_xh[(size_t)NR*FD];
__device__ __nv_bfloat16 g_xl[(size_t)NR*FD];
__device__ __nv_bfloat16 g_wh[(size_t)3*1024*1024];
__device__ __nv_bfloat16 g_wl[(size_t)3*1024*1024];
__device__ float g_n0 [NR];
__device__ float g_no [NR];
__device__ float g_nh2[NR];
__device__ float g_nh3[NR];
__device__ float g_b2 [8];

// weight element offsets inside g_wh/g_wl
#define WQ0 0
#define WK0 262144
#define WV0 524288
#define WO0 786432
#define W10 1048576
#define W20 2097152

#define FLAG_LOGMAP  1
#define FLAG_MOBRELU 2
#define FLAG_RESID   4

// ---------------- block reduction (fp32, pairwise) ----------------
template <int T>
__device__ __forceinline__ float blockSumF(float v) {
    __shared__ float sh[T / 32];
    #pragma unroll
    for (int o = 16; o > 0; o >>= 1) v += __shfl_xor_sync(0xffffffffu, v, o);
    int lane = threadIdx.x & 31, w = threadIdx.x >> 5;
    if (lane == 0) sh[w] = v;
    __syncthreads();
    if (threadIdx.x < 32) {
        float t = (threadIdx.x < T / 32) ? sh[threadIdx.x] : 0.0f;
        #pragma unroll
        for (int o = 16; o > 0; o >>= 1) t += __shfl_xor_sync(0xffffffffu, t, o);
        if (threadIdx.x == 0) sh[0] = t;
    }
    __syncthreads();
    float r = sh[0];
    __syncthreads();
    return r;
}

__device__ __forceinline__ void split1(float x, __nv_bfloat16 &h, __nv_bfloat16 &l) {
    h = __float2bfloat16(x);
    l = __float2bfloat16(x - __bfloat162float(h));
}

// FMA-pipe exp (no MUFU): exp(x) = 2^(x*log2e), degree-7 Taylor on fractional part
__device__ __forceinline__ float fexp(float x) {
    float y = x * 1.4426950408889634f;
    y = fmaxf(y, -126.0f);
    float fl = floorf(y);
    float f = y - fl;
    float p = 1.5252734e-5f;                 // ln2^7/5040
    p = fmaf(p, f, 1.5403530e-4f);           // ln2^6/720
    p = fmaf(p, f, 1.3333558e-3f);           // ln2^5/120
    p = fmaf(p, f, 9.6181291e-3f);           // ln2^4/24
    p = fmaf(p, f, 5.5504109e-2f);           // ln2^3/6
    p = fmaf(p, f, 2.4022651e-1f);           // ln2^2/2
    p = fmaf(p, f, 6.9314718e-1f);           // ln2
    p = fmaf(p, f, 1.0f);
    return __int_as_float(__float_as_int(p) + (((int)fl) << 23));
}

// ---------------- all 6 bias squared-norms ----------------
__global__ void sqsum6(const float* bq, const float* bk, const float* bv,
                       const float* bo, const float* b1, const float* b2,
                       float* __restrict__ out) {
    const float* p;
    int n;
    switch (blockIdx.x) {
        case 0: p = bq; n = ED; break;
        case 1: p = bk; n = ED; break;
        case 2: p = bv; n = ED; break;
        case 3: p = bo; n = ED; break;
        case 4: p = b1; n = FD; break;
        default: p = b2; n = ED; break;
    }
    float s = 0.0f;
    for (int i = threadIdx.x; i < n; i += 256) { float x = p[i]; s += x * x; }
    s = blockSumF<256>(s);
    if (threadIdx.x == 0) out[blockIdx.x] = s;
}

// ---------------- one launch: split all 6 weights into concat hi/lo ----------------
__global__ void split_all(const float* Wq, const float* Wk, const float* Wv,
                          const float* Wo, const float* W1, const float* W2,
                          __nv_bfloat16* __restrict__ h, __nv_bfloat16* __restrict__ l) {
    const float* src; size_t off; int n4;
    switch (blockIdx.y) {
        case 0: src = Wq; off = WQ0; n4 = 65536;  break;
        case 1: src = Wk; off = WK0; n4 = 65536;  break;
        case 2: src = Wv; off = WV0; n4 = 65536;  break;
        case 3: src = Wo; off = WO0; n4 = 65536;  break;
        case 4: src = W1; off = W10; n4 = 262144; break;
        default: src = W2; off = W20; n4 = 262144; break;
    }
    int i = blockIdx.x * 256 + threadIdx.x;
    if (i < n4) {
        float4 v = ((const float4*)src)[i];
        __nv_bfloat16 h0,l0,h1,l1,h2,l2,h3,l3;
        split1(v.x, h0, l0); split1(v.y, h1, l1);
        split1(v.z, h2, l2); split1(v.w, h3, l3);
        __nv_bfloat162* hp = (__nv_bfloat162*)(h + off);
        __nv_bfloat162* lp = (__nv_bfloat162*)(l + off);
        hp[i*2]   = __nv_bfloat162(h0, h1);
        hp[i*2+1] = __nv_bfloat162(h2, h3);
        lp[i*2]   = __nv_bfloat162(l0, l1);
        lp[i*2+1] = __nv_bfloat162(l2, l3);
    }
}

// vector helpers
#define VOP4(dst, ex, ey, ez, ew) do { dst.x=(ex); dst.y=(ey); dst.z=(ez); dst.w=(ew); } while(0)
__device__ __forceinline__ float dot4(float4 a, float4 b) { return a.x*b.x + a.y*b.y + a.z*b.z + a.w*b.w; }
__device__ __forceinline__ float sq4(float4 a) { return dot4(a, a); }
__device__ __forceinline__ float4 scl4(float4 a, float s) { float4 r; VOP4(r, a.x*s, a.y*s, a.z*s, a.w*s); return r; }

// ---------------- ln block ----------------
template <int E, int T>
__global__ void __launch_bounds__(T) ln_kernel(
    const float* __restrict__ x, const float* __restrict__ g, const float* __restrict__ b,
    float* __restrict__ outf, __nv_bfloat16* __restrict__ oh, __nv_bfloat16* __restrict__ ol,
    float* __restrict__ out_norm, int do_projx)
{
    constexpr int V4 = E / (T * 4);
    const size_t row = blockIdx.x;
    const int tid = threadIdx.x;
    const float MAXN = maxnorm();
    const float4* xp = (const float4*)(x + row * E);
    const float4* gp = (const float4*)g;
    const float4* bp = (const float4*)b;
    float4 v[V4];
    float ss = 0.0f;
    #pragma unroll
    for (int i = 0; i < V4; i++) { v[i] = xp[tid*V4 + i]; ss += sq4(v[i]); }
    float n0 = sqrtf(blockSumF<T>(ss) + 1e-30f);
    float lf = atanhf(fminf(n0, MAXN)) / n0;
    float sm = 0.0f;
    #pragma unroll
    for (int i = 0; i < V4; i++) { v[i] = scl4(v[i], lf); sm += v[i].x + v[i].y + v[i].z + v[i].w; }
    float mu = blockSumF<T>(sm) * (1.0f / E);
    float vv = 0.0f;
    #pragma unroll
    for (int i = 0; i < V4; i++) {
        float4 d; VOP4(d, v[i].x-mu, v[i].y-mu, v[i].z-mu, v[i].w-mu);
        vv += sq4(d);
    }
    float var = blockSumF<T>(vv) * (1.0f / E);
    float inv = rsqrtf(var + 1e-5f);
    float s2 = 0.0f;
    #pragma unroll
    for (int i = 0; i < V4; i++) {
        float4 gg = gp[tid*V4 + i], bb = bp[tid*V4 + i];
        VOP4(v[i], (v[i].x-mu)*inv*gg.x + bb.x, (v[i].y-mu)*inv*gg.y + bb.y,
                   (v[i].z-mu)*inv*gg.z + bb.z, (v[i].w-mu)*inv*gg.w + bb.w);
        s2 += sq4(v[i]);
    }
    float ny = sqrtf(blockSumF<T>(s2) + 1e-30f);
    float ef = tanhf(ny) / ny;
    #pragma unroll
    for (int i = 0; i < V4; i++) v[i] = scl4(v[i], ef);
    if (do_projx) {
        float s3 = 0.0f;
        #pragma unroll
        for (int i = 0; i < V4; i++) s3 += sq4(v[i]);
        float n = sqrtf(blockSumF<T>(s3) + 1e-30f);
        if (n > MAXN) { float ps = MAXN / n;
            #pragma unroll
            for (int i = 0; i < V4; i++) v[i] = scl4(v[i], ps); }
    }
    float s4 = 0.0f;
    #pragma unroll
    for (int i = 0; i < V4; i++) {
        if (outf) ((float4*)(outf + row*E))[tid*V4 + i] = v[i];
        if (oh) {
            __nv_bfloat16 h0,l0,h1,l1,h2,l2,h3,l3;
            split1(v[i].x,h0,l0); split1(v[i].y,h1,l1); split1(v[i].z,h2,l2); split1(v[i].w,h3,l3);
            ((__nv_bfloat162*)(oh + row*E))[tid*V4*2 + i*2]   = __nv_bfloat162(h0,h1);
            ((__nv_bfloat162*)(oh + row*E))[tid*V4*2 + i*2+1] = __nv_bfloat162(h2,h3);
            ((__nv_bfloat162*)(ol + row*E))[tid*V4*2 + i*2]   = __nv_bfloat162(l0,l1);
            ((__nv_bfloat162*)(ol + row*E))[tid*V4*2 + i*2+1] = __nv_bfloat162(l2,l3);
        }
        s4 += sq4(v[i]);
    }
    float nf = sqrtf(blockSumF<T>(s4) + 1e-30f);
    if (tid == 0) out_norm[row] = nf;
}

// ---------------- expmap0 rows -> bf16 split + norm ----------------
template <int E, int T>
__global__ void __launch_bounds__(T) expmap_rows(
    const float* __restrict__ x, __nv_bfloat16* __restrict__ oh, __nv_bfloat16* __restrict__ ol,
    float* __restrict__ out_norm)
{
    constexpr int V4 = E / (T * 4);
    const size_t row = blockIdx.x;
    const int tid = threadIdx.x;
    const float4* xp = (const float4*)(x + row * E);
    float4 v[V4];
    float ss = 0.0f;
    #pragma unroll
    for (int i = 0; i < V4; i++) { v[i] = xp[tid*V4 + i]; ss += sq4(v[i]); }
    float n = sqrtf(blockSumF<T>(ss) + 1e-30f);
    float ef = tanhf(n) / n;
    float s2 = 0.0f;
    #pragma unroll
    for (int i = 0; i < V4; i++) {
        v[i] = scl4(v[i], ef);
        __nv_bfloat16 h0,l0,h1,l1,h2,l2,h3,l3;
        split1(v[i].x,h0,l0); split1(v[i].y,h1,l1); split1(v[i].z,h2,l2); split1(v[i].w,h3,l3);
        ((__nv_bfloat162*)(oh + row*E))[tid*V4*2 + i*2]   = __nv_bfloat162(h0,h1);
        ((__nv_bfloat162*)(oh + row*E))[tid*V4*2 + i*2+1] = __nv_bfloat162(h2,h3);
        ((__nv_bfloat162*)(ol + row*E))[tid*V4*2 + i*2]   = __nv_bfloat162(l0,l1);
        ((__nv_bfloat162*)(ol + row*E))[tid*V4*2 + i*2+1] = __nv_bfloat162(l2,l3);
        s2 += sq4(v[i]);
    }
    float nf = sqrtf(blockSumF<T>(s2) + 1e-30f);
    if (tid == 0) out_norm[row] = nf;
}

// ---------------- fused q/k/v manifold epilogue: grid (NR, 3), in-place, + logmap0 ----------------
__global__ void __launch_bounds__(128) manlin_qkv(
    float* __restrict__ qkv, const float* __restrict__ xnb,
    const float* __restrict__ bq, const float* __restrict__ bk, const float* __restrict__ bv)
{
    const size_t row = blockIdx.x;
    const int seg = blockIdx.y;
    const int tid = threadIdx.x;
    const float MAXN = maxnorm();
    const float* bias = (seg == 0) ? bq : (seg == 1) ? bk : bv;
    float* base = qkv + row * (size_t)QKVW + seg * 512;
    float4 v = ((const float4*)base)[tid];
    float4 bvv = ((const float4*)bias)[tid];
    float mxn = sqrtf(blockSumF<128>(sq4(v)) + 1e-30f);
    float xn = xnb[row];
    float s = tanhf(mxn / xn * atanhf(fminf(xn, MAXN))) / mxn;
    v = scl4(v, s);
    float xy = blockSumF<128>(dot4(v, bvv));
    float x2 = blockSumF<128>(sq4(v));
    float y2 = g_b2[seg];
    float a = 1.0f + 2.0f*xy + y2;
    float c = 1.0f - x2;
    float invd = 1.0f / fmaxf(1.0f + 2.0f*xy + x2*y2, 1e-15f);
    VOP4(v, (a*v.x + c*bvv.x)*invd, (a*v.y + c*bvv.y)*invd,
            (a*v.z + c*bvv.z)*invd, (a*v.w + c*bvv.w)*invd);
    // projx
    float zn = sqrtf(blockSumF<128>(sq4(v)) + 1e-30f);
    if (zn > MAXN) v = scl4(v, MAXN / zn);
    // logmap0
    float n = sqrtf(blockSumF<128>(sq4(v)) + 1e-30f);
    float lf = atanhf(fminf(n, MAXN)) / n;
    v = scl4(v, lf);
    ((float4*)base)[tid] = v;
}

// ---------------- man_linear epilogue (general) ----------------
template <int E, int T>
__global__ void __launch_bounds__(T) manlin_epi(
    const float* __restrict__ mx, int ldm, const float* __restrict__ xnb,
    const float* __restrict__ bias, int b2idx,
    const float* __restrict__ resid,
    float* __restrict__ outf, __nv_bfloat16* __restrict__ oh, __nv_bfloat16* __restrict__ ol,
    float* __restrict__ out_norm, int flags)
{
    constexpr int V4 = E / (T * 4);
    const size_t row = blockIdx.x;
    const int tid = threadIdx.x;
    const float MAXN = maxnorm();
    const float4* mp = (const float4*)(mx + row*(size_t)ldm);
    const float4* bp = (const float4*)bias;
    float4 v[V4], bv[V4];
    float ss = 0.0f;
    #pragma unroll
    for (int i = 0; i < V4; i++) { v[i] = mp[tid*V4 + i]; ss += sq4(v[i]); }
    float mxn = sqrtf(blockSumF<T>(ss) + 1e-30f);
    float xn = xnb[row];
    float s = tanhf(mxn / xn * atanhf(fminf(xn, MAXN))) / mxn;
    float dxy = 0.0f, dx2 = 0.0f;
    #pragma unroll
    for (int i = 0; i < V4; i++) {
        v[i] = scl4(v[i], s);
        bv[i] = bp[tid*V4 + i];
        dxy += dot4(v[i], bv[i]);
        dx2 += sq4(v[i]);
    }
    float xy = blockSumF<T>(dxy);
    float x2 = blockSumF<T>(dx2);
    float y2 = g_b2[b2idx];
    float a = 1.0f + 2.0f*xy + y2;
    float c = 1.0f - x2;
    float den = fmaxf(1.0f + 2.0f*xy + x2*y2, 1e-15f);
    float invd = 1.0f / den;
    float zz = 0.0f;
    #pragma unroll
    for (int i = 0; i < V4; i++) {
        VOP4(v[i], (a*v[i].x + c*bv[i].x)*invd, (a*v[i].y + c*bv[i].y)*invd,
                   (a*v[i].z + c*bv[i].z)*invd, (a*v[i].w + c*bv[i].w)*invd);
        zz += sq4(v[i]);
    }
    {
        float zn = sqrtf(blockSumF<T>(zz) + 1e-30f);
        if (zn > MAXN) { float ps = MAXN / zn;
            #pragma unroll
            for (int i = 0; i < V4; i++) v[i] = scl4(v[i], ps); }
    }
    if (flags & FLAG_MOBRELU) {
        float s0 = 0.0f;
        #pragma unroll
        for (int i = 0; i < V4; i++) s0 += sq4(v[i]);
        float n = sqrtf(blockSumF<T>(s0) + 1e-30f);
        float lf = atanhf(fminf(n, MAXN)) / n;
        float s1 = 0.0f;
        #pragma unroll
        for (int i = 0; i < V4; i++) {
            VOP4(v[i], fmaxf(lf*v[i].x, 0.0f), fmaxf(lf*v[i].y, 0.0f),
                       fmaxf(lf*v[i].z, 0.0f), fmaxf(lf*v[i].w, 0.0f));
            s1 += sq4(v[i]);
        }
        float nr = sqrtf(blockSumF<T>(s1) + 1e-30f);
        float ef = tanhf(nr) / nr;
        float s2 = 0.0f;
        #pragma unroll
        for (int i = 0; i < V4; i++) { v[i] = scl4(v[i], ef); s2 += sq4(v[i]); }
        float n2 = sqrtf(blockSumF<T>(s2) + 1e-30f);
        if (n2 > MAXN) { float ps = MAXN / n2;
            #pragma unroll
            for (int i = 0; i < V4; i++) v[i] = scl4(v[i], ps); }
    }
    if (flags & FLAG_RESID) {
        const float4* rp = (const float4*)(resid + row*E);
        float4 rv[V4];
        float d1 = 0.0f, d2 = 0.0f, d3 = 0.0f;
        #pragma unroll
        for (int i = 0; i < V4; i++) {
            rv[i] = rp[tid*V4 + i];
            d1 += dot4(v[i], rv[i]);
            d2 += sq4(rv[i]);
            d3 += sq4(v[i]);
        }
        float rxy = blockSumF<T>(d1);
        float ry2 = blockSumF<T>(d2);
        float rx2 = blockSumF<T>(d3);
        float ra = 1.0f + 2.0f*rxy + ry2;
        float rc = 1.0f - rx2;
        float rden = fmaxf(1.0f + 2.0f*rxy + rx2*ry2, 1e-15f);
        float rinv = 1.0f / rden;
        float s3 = 0.0f;
        #pragma unroll
        for (int i = 0; i < V4; i++) {
            VOP4(v[i], (ra*v[i].x + rc*rv[i].x)*rinv, (ra*v[i].y + rc*rv[i].y)*rinv,
                       (ra*v[i].z + rc*rv[i].z)*rinv, (ra*v[i].w + rc*rv[i].w)*rinv);
            s3 += sq4(v[i]);
        }
        float zn = sqrtf(blockSumF<T>(s3) + 1e-30f);
        if (zn > MAXN) { float ps = MAXN / zn;
            #pragma unroll
            for (int i = 0; i < V4; i++) v[i] = scl4(v[i], ps); }
    }
    if (flags & FLAG_LOGMAP) {
        float s4 = 0.0f;
        #pragma unroll
        for (int i = 0; i < V4; i++) s4 += sq4(v[i]);
        float n = sqrtf(blockSumF<T>(s4) + 1e-30f);
        float lf = atanhf(fminf(n, MAXN)) / n;
        #pragma unroll
        for (int i = 0; i < V4; i++) v[i] = scl4(v[i], lf);
    }
    float s5 = 0.0f;
    #pragma unroll
    for (int i = 0; i < V4; i++) {
        if (outf) ((float4*)(outf + row*(size_t)ldm))[tid*V4 + i] = v[i];
        if (oh) {
            __nv_bfloat16 h0,l0,h1,l1,h2,l2,h3,l3;
            split1(v[i].x,h0,l0); split1(v[i].y,h1,l1); split1(v[i].z,h2,l2); split1(v[i].w,h3,l3);
            ((__nv_bfloat162*)(oh + row*E))[tid*V4*2 + i*2]   = __nv_bfloat162(h0,h1);
            ((__nv_bfloat162*)(oh + row*E))[tid*V4*2 + i*2+1] = __nv_bfloat162(h2,h3);
            ((__nv_bfloat162*)(ol + row*E))[tid*V4*2 + i*2]   = __nv_bfloat162(l0,l1);
            ((__nv_bfloat162*)(ol + row*E))[tid*V4*2 + i*2+1] = __nv_bfloat162(l2,l3);
        }
        s5 += sq4(v[i]);
    }
    if (out_norm) {
        float nf = sqrtf(blockSumF<T>(s5) + 1e-30f);
        if (tid == 0) out_norm[row] = nf;
    }
}

// ---------------- attention (fused qkv input; FMA-pipe exp) ----------------
__global__ void __launch_bounds__(128) attn_kernel(
    const float* __restrict__ qkv, float* __restrict__ o)
{
    int bh = blockIdx.x;
    int b  = bh >> 3;
    int h  = bh & 7;
    int t  = threadIdx.x;
    const float scale = 0.125f;
    size_t qbase = ((size_t)t*BB + b)*QKVW + (size_t)h*HD;
    float4 q4[16], acc[16];
    const float4* qp = (const float4*)(qkv + qbase);
    #pragma unroll
    for (int d = 0; d < 16; d++) { q4[d] = scl4(qp[d], scale); acc[d] = make_float4(0,0,0,0); }
    float m = -1e30f, l = 0.0f;
    __shared__ float4 ks[16][16];
    __shared__ float4 vs[16][16];
    for (int j0 = 0; j0 < SEQ; j0 += 16) {
        __syncthreads();
        #pragma unroll
        for (int it = 0; it < 2; it++) {
            int idx = t + it*128;
            int jj = idx >> 4, d4 = idx & 15;
            size_t g = ((size_t)(j0 + jj)*BB + b)*QKVW + (size_t)h*HD + d4*4;
            ks[jj][d4] = *(const float4*)(qkv + 512 + g);
            vs[jj][d4] = *(const float4*)(qkv + 1024 + g);
        }
        __syncthreads();
        float sc[16];
        #pragma unroll
        for (int jj = 0; jj < 16; jj++) {
            float s = 0.0f;
            #pragma unroll
            for (int d = 0; d < 16; d++) s += dot4(q4[d], ks[jj][d]);
            sc[jj] = s;
        }
        float mn = m;
        #pragma unroll
        for (int jj = 0; jj < 16; jj++) mn = fmaxf(mn, sc[jj]);
        float corr = fexp(m - mn);
        l *= corr;
        #pragma unroll
        for (int d = 0; d < 16; d++) acc[d] = scl4(acc[d], corr);
        #pragma unroll
        for (int jj = 0; jj < 16; jj++) {
            float p = fexp(sc[jj] - mn);
            l += p;
            #pragma unroll
            for (int d = 0; d < 16; d++) {
                float4 vv = vs[jj][d];
                acc[d].x += p*vv.x; acc[d].y += p*vv.y; acc[d].z += p*vv.z; acc[d].w += p*vv.w;
            }
        }
        m = mn;
    }
    float invl = 1.0f / l;
    size_t obase = ((size_t)t*BB + b)*ED + (size_t)h*HD;
    float4* op = (float4*)(o + obase);
    #pragma unroll
    for (int d = 0; d < 16; d++) op[d] = scl4(acc[d], invl);
}

// ================= bf16x3 HMMA GEMM: 3-stage pipeline, 64B swizzled rows =================
#define BM 128
#define BN 128
#define BK 32
#define TEN_B   8192
#define STAGE_B (4*TEN_B)
#define GEMM_SMEM (3*STAGE_B)

__device__ __forceinline__ uint32_t saddr(int r, int colElem) {
    return (uint32_t)(r*64 + ((((colElem >> 3) ^ ((r >> 1) & 3))) << 4));
}
__device__ __forceinline__ void ldsm_x4(uint32_t &r0, uint32_t &r1, uint32_t &r2, uint32_t &r3, uint32_t addr) {
    asm volatile("ldmatrix.sync.aligned.m8n8.x4.shared.b16 {%0,%1,%2,%3}, [%4];"
                 : "=r"(r0), "=r"(r1), "=r"(r2), "=r"(r3) : "r"(addr));
}
__device__ __forceinline__ void ldsm_x2(uint32_t &r0, uint32_t &r1, uint32_t addr) {
    asm volatile("ldmatrix.sync.aligned.m8n8.x2.shared.b16 {%0,%1}, [%2];"
                 : "=r"(r0), "=r"(r1) : "r"(addr));
}
__device__ __forceinline__ void mma16816(float* c, const uint32_t* a, const uint32_t* b) {
    asm volatile("mma.sync.aligned.m16n8k16.row.col.f32.bf16.bf16.f32 "
                 "{%0,%1,%2,%3}, {%4,%5,%6,%7}, {%8,%9}, {%0,%1,%2,%3};"
                 : "+f"(c[0]), "+f"(c[1]), "+f"(c[2]), "+f"(c[3])
                 : "r"(a[0]), "r"(a[1]), "r"(a[2]), "r"(a[3]), "r"(b[0]), "r"(b[1]));
}
#define CP_ASYNC16(dst, src) asm volatile("cp.async.cg.shared.global [%0], [%1], 16;" :: "r"(dst), "l"(src))

__global__ void __launch_bounds__(256, 2) gemm_bf16x3(
    const __nv_bfloat16* __restrict__ Ah, const __nv_bfloat16* __restrict__ Al,
    const __nv_bfloat16* __restrict__ Wh, const __nv_bfloat16* __restrict__ Wl,
    float* __restrict__ C, int M, int N, int K)
{
    extern __shared__ __nv_bfloat16 smbuf[];
    const int tid = threadIdx.x;
    const int lane = tid & 31, w = tid >> 5;
    const int wm = w & 1, wn = w >> 1;
    const int rowBase = blockIdx.y * BM;
    const int colBase = blockIdx.x * BN;
    uint32_t smbase = (uint32_t)__cvta_generic_to_shared(smbuf);

    float acc[4][4][4];
    #pragma unroll
    for (int i = 0; i < 4; i++)
        #pragma unroll
        for (int j = 0; j < 4; j++)
            #pragma unroll
            for (int e = 0; e < 4; e++) acc[i][j][e] = 0.0f;

    auto load_stage = [&](int st, int k0) {
        uint32_t base = smbase + st * STAGE_B;
        #pragma unroll
        for (int it = 0; it < 8; it++) {
            int idx = tid + (it << 8);
            int tensor = idx >> 9;
            int cid = idx & 511;
            int r = cid >> 2, c = cid & 3;
            uint32_t dst = base + tensor * TEN_B
                         + (uint32_t)(r*64 + ((c ^ ((r >> 1) & 3)) << 4));
            const __nv_bfloat16* src;
            if (tensor == 0)      src = Ah + (size_t)(rowBase + r) * K + k0 + c * 8;
            else if (tensor == 1) src = Al + (size_t)(rowBase + r) * K + k0 + c * 8;
            else if (tensor == 2) src = Wh + (size_t)(colBase + r) * K + k0 + c * 8;
            else                  src = Wl + (size_t)(colBase + r) * K + k0 + c * 8;
            CP_ASYNC16(dst, src);
        }
        asm volatile("cp.async.commit_group;");
    };

    auto compute_stage = [&](int st) {
        uint32_t base = smbase + st * STAGE_B;
        uint32_t aH = base;
        uint32_t aL = base + 1*TEN_B;
        uint32_t wH = base + 2*TEN_B;
        uint32_t wL = base + 3*TEN_B;
        const int quad = lane >> 3, r8 = lane & 7;
        #pragma unroll
        for (int kk = 0; kk < BK; kk += 16) {
            uint32_t ah[4][4], al[4][4], bh[4][2], bl[4][2];
            #pragma unroll
            for (int i = 0; i < 4; i++) {
                int row = wm*64 + i*16 + (quad & 1)*8 + r8;
                int col = kk + (quad >> 1)*8;
                uint32_t off = saddr(row, col);
                ldsm_x4(ah[i][0], ah[i][1], ah[i][2], ah[i][3], aH + off);
                ldsm_x4(al[i][0], al[i][1], al[i][2], al[i][3], aL + off);
            }
            #pragma unroll
            for (int j = 0; j < 4; j++) {
                int nr = wn*32 + j*8 + (lane & 7);
                int kc = kk + ((lane >> 3) & 1)*8;
                uint32_t off = saddr(nr, kc);
                ldsm_x2(bh[j][0], bh[j][1], wH + off);
                ldsm_x2(bl[j][0], bl[j][1], wL + off);
            }
            #pragma unroll
            for (int i = 0; i < 4; i++)
                #pragma unroll
                for (int j = 0; j < 4; j++) mma16816(acc[i][j], ah[i], bh[j]);
            #pragma unroll
            for (int i = 0; i < 4; i++)
                #pragma unroll
                for (int j = 0; j < 4; j++) mma16816(acc[i][j], ah[i], bl[j]);
            #pragma unroll
            for (int i = 0; i < 4; i++)
                #pragma unroll
                for (int j = 0; j < 4; j++) mma16816(acc[i][j], al[i], bh[j]);
        }
    };

    const int nkb = K / BK;
    load_stage(0, 0);
    load_stage(1, BK);
    for (int kb = 0; kb < nkb; kb++) {
        if (kb == nkb - 1) { asm volatile("cp.async.wait_group 0;"); }
        else               { asm volatile("cp.async.wait_group 1;"); }
        __syncthreads();
        if (kb + 2 < nkb) load_stage((kb + 2) % 3, (kb + 2) * BK);
        compute_stage(kb % 3);
    }

    const int g = lane >> 2, tg = lane & 3;
    #pragma unroll
    for (int i = 0; i < 4; i++) {
        int row = rowBase + wm*64 + i*16 + g;
        #pragma unroll
        for (int j = 0; j < 4; j++) {
            int col = colBase + wn*32 + j*8 + tg*2;
            *(float2*)(C + (size_t)row * N + col)       = make_float2(acc[i][j][0], acc[i][j][1]);
            *(float2*)(C + (size_t)(row + 8) * N + col) = make_float2(acc[i][j][2], acc[i][j][3]);
        }
    }
}

// ---------------- launch ----------------
extern "C" void kernel_launch(void* const* d_in, const int* in_sizes, int n_in,
                              void* d_out, int out_size)
{
    const float* x    = (const float*)d_in[0];
    const float* l1g  = (const float*)d_in[1];
    const float* l1b  = (const float*)d_in[2];
    const float* l2g  = (const float*)d_in[3];
    const float* l2b  = (const float*)d_in[4];
    const float* Wq   = (const float*)d_in[5];
    const float* bq   = (const float*)d_in[6];
    const float* Wk   = (const float*)d_in[7];
    const float* bk   = (const float*)d_in[8];
    const float* Wv   = (const float*)d_in[9];
    const float* bv   = (const float*)d_in[10];
    const float* Wo   = (const float*)d_in[11];
    const float* bo   = (const float*)d_in[12];
    const float* W1   = (const float*)d_in[13];
    const float* b1   = (const float*)d_in[14];
    const float* W2   = (const float*)d_in[15];
    const float* b2   = (const float*)d_in[16];
    float* out = (float*)d_out;

    float *qkv, *ob, *h1, *big, *n0, *no, *nh2, *nh3, *bsq;
    __nv_bfloat16 *xh, *xl, *wh, *wl;
    cudaGetSymbolAddress((void**)&qkv, g_qkv);
    cudaGetSymbolAddress((void**)&ob,  g_o);
    cudaGetSymbolAddress((void**)&h1,  g_h1);
    cudaGetSymbolAddress((void**)&big, g_big);
    cudaGetSymbolAddress((void**)&xh,  g_xh);
    cudaGetSymbolAddress((void**)&xl,  g_xl);
    cudaGetSymbolAddress((void**)&wh,  g_wh);
    cudaGetSymbolAddress((void**)&wl,  g_wl);
    cudaGetSymbolAddress((void**)&n0,  g_n0);
    cudaGetSymbolAddress((void**)&no,  g_no);
    cudaGetSymbolAddress((void**)&nh2, g_nh2);
    cudaGetSymbolAddress((void**)&nh3, g_nh3);
    cudaGetSymbolAddress((void**)&bsq, g_b2);

    cudaFuncSetAttribute(gemm_bf16x3, cudaFuncAttributeMaxDynamicSharedMemorySize, GEMM_SMEM);

    split_all<<<dim3(1024, 6), 256>>>(Wq, Wk, Wv, Wo, W1, W2, wh, wl);
    sqsum6<<<6, 256>>>(bq, bk, bv, bo, b1, b2, bsq);
    ln_kernel<ED, 128><<<NR, 128>>>(x, l1g, l1b, nullptr, xh, xl, n0, 0);

    gemm_bf16x3<<<dim3(QKVW/BN, NR/BM), 256, GEMM_SMEM>>>(xh, xl, wh + WQ0, wl + WQ0, qkv, NR, QKVW, ED);
    manlin_qkv<<<dim3(NR, 3), 128>>>(qkv, n0, bq, bk, bv);

    attn_kernel<<<BB * NH, 128>>>(qkv, ob);
    expmap_rows<ED, 128><<<NR, 128>>>(ob, xh, xl, no);

    gemm_bf16x3<<<dim3(ED/BN, NR/BM), 256, GEMM_SMEM>>>(xh, xl, wh + WO0, wl + WO0, big, NR, ED, ED);
    manlin_epi<ED, 128><<<NR, 128>>>(big, ED, no, bo, 3, x, h1, nullptr, nullptr, nullptr, FLAG_RESID);

    ln_kernel<ED, 128><<<NR, 128>>>(h1, l2g, l2b, nullptr, xh, xl, nh2, 1);

    gemm_bf16x3<<<dim3(FD/BN, NR/BM), 256, GEMM_SMEM>>>(xh, xl, wh + W10, wl + W10, big, NR, FD, ED);
    manlin_epi<FD, 256><<<NR, 256>>>(big, FD, nh2, b1, 4, nullptr, nullptr, xh, xl, nh3, FLAG_MOBRELU);

    gemm_bf16x3<<<dim3(ED/BN, NR/BM), 256, GEMM_SMEM>>>(xh, xl, wh + W20, wl + W20, qkv, NR, ED, FD);
    manlin_epi<ED, 128><<<NR, 128>>>(qkv, ED, nh3, b2, 5, h1, out, nullptr, nullptr, nullptr, FLAG_MOBRELU | FLAG_RESID);
}

// round 7
// speedup vs baseline: 7.5481x; 1.1246x over previous
#include <cuda_runtime.h>
#include <cuda_bf16.h>
#include <math.h>
#include <stdint.h>

// ---------------- problem constants ----------------
#define SEQ 128
#define BB  256
#define ED  512
#define FD  2048
#define NH  8
#define HD  64
#define NR  (SEQ*BB)   // 32768 rows
#define QKVW 1536      // fused qkv row width

static __device__ __forceinline__ float maxnorm() { return (float)(1.0 - 1e-5); }

// ---------------- scratch ----------------
__device__ float g_qkv[(size_t)NR*QKVW];
__device__ float g_o  [(size_t)NR*ED];
__device__ float g_h1 [(size_t)NR*ED];
__device__ float g_big[(size_t)NR*FD];
__device__ __nv_bfloat16 g_xh[(size_t)NR*FD];
__device__ __nv_bfloat16 g_xl[(size_t)NR*FD];
__device__ __nv_bfloat16 g_wh[(size_t)3*1024*1024];
__device__ __nv_bfloat16 g_wl[(size_t)3*1024*1024];
__device__ float g_n0 [NR];
__device__ float g_no [NR];
__device__ float g_nh2[NR];
__device__ float g_nh3[NR];
__device__ float g_b2 [8];

// weight element offsets inside g_wh/g_wl
#define WQ0 0
#define WK0 262144
#define WV0 524288
#define WO0 786432
#define W10 1048576
#define W20 2097152

#define FLAG_LOGMAP  1
#define FLAG_MOBRELU 2
#define FLAG_RESID   4

// ---------------- block reduction (fp32, pairwise) ----------------
template <int T>
__device__ __forceinline__ float blockSumF(float v) {
    __shared__ float sh[T / 32];
    #pragma unroll
    for (int o = 16; o > 0; o >>= 1) v += __shfl_xor_sync(0xffffffffu, v, o);
    int lane = threadIdx.x & 31, w = threadIdx.x >> 5;
    if (lane == 0) sh[w] = v;
    __syncthreads();
    if (threadIdx.x < 32) {
        float t = (threadIdx.x < T / 32) ? sh[threadIdx.x] : 0.0f;
        #pragma unroll
        for (int o = 16; o > 0; o >>= 1) t += __shfl_xor_sync(0xffffffffu, t, o);
        if (threadIdx.x == 0) sh[0] = t;
    }
    __syncthreads();
    float r = sh[0];
    __syncthreads();
    return r;
}

__device__ __forceinline__ void split1(float x, __nv_bfloat16 &h, __nv_bfloat16 &l) {
    h = __float2bfloat16(x);
    l = __float2bfloat16(x - __bfloat162float(h));
}
__device__ __forceinline__ uint32_t pack_bf2(float a, float b) {
    __nv_bfloat162 t(__float2bfloat16(a), __float2bfloat16(b));
    return *(uint32_t*)&t;
}

// FMA-pipe exp (no MUFU)
__device__ __forceinline__ float fexp(float x) {
    float y = x * 1.4426950408889634f;
    y = fmaxf(y, -126.0f);
    float fl = floorf(y);
    float f = y - fl;
    float p = 1.5252734e-5f;
    p = fmaf(p, f, 1.5403530e-4f);
    p = fmaf(p, f, 1.3333558e-3f);
    p = fmaf(p, f, 9.6181291e-3f);
    p = fmaf(p, f, 5.5504109e-2f);
    p = fmaf(p, f, 2.4022651e-1f);
    p = fmaf(p, f, 6.9314718e-1f);
    p = fmaf(p, f, 1.0f);
    return __int_as_float(__float_as_int(p) + (((int)fl) << 23));
}

// ---------------- all 6 bias squared-norms ----------------
__global__ void sqsum6(const float* bq, const float* bk, const float* bv,
                       const float* bo, const float* b1, const float* b2,
                       float* __restrict__ out) {
    const float* p;
    int n;
    switch (blockIdx.x) {
        case 0: p = bq; n = ED; break;
        case 1: p = bk; n = ED; break;
        case 2: p = bv; n = ED; break;
        case 3: p = bo; n = ED; break;
        case 4: p = b1; n = FD; break;
        default: p = b2; n = ED; break;
    }
    float s = 0.0f;
    for (int i = threadIdx.x; i < n; i += 256) { float x = p[i]; s += x * x; }
    s = blockSumF<256>(s);
    if (threadIdx.x == 0) out[blockIdx.x] = s;
}

// ---------------- split all 6 weights into concat hi/lo ----------------
__global__ void split_all(const float* Wq, const float* Wk, const float* Wv,
                          const float* Wo, const float* W1, const float* W2,
                          __nv_bfloat16* __restrict__ h, __nv_bfloat16* __restrict__ l) {
    const float* src; size_t off; int n4;
    switch (blockIdx.y) {
        case 0: src = Wq; off = WQ0; n4 = 65536;  break;
        case 1: src = Wk; off = WK0; n4 = 65536;  break;
        case 2: src = Wv; off = WV0; n4 = 65536;  break;
        case 3: src = Wo; off = WO0; n4 = 65536;  break;
        case 4: src = W1; off = W10; n4 = 262144; break;
        default: src = W2; off = W20; n4 = 262144; break;
    }
    int i = blockIdx.x * 256 + threadIdx.x;
    if (i < n4) {
        float4 v = ((const float4*)src)[i];
        __nv_bfloat16 h0,l0,h1,l1,h2,l2,h3,l3;
        split1(v.x, h0, l0); split1(v.y, h1, l1);
        split1(v.z, h2, l2); split1(v.w, h3, l3);
        __nv_bfloat162* hp = (__nv_bfloat162*)(h + off);
        __nv_bfloat162* lp = (__nv_bfloat162*)(l + off);
        hp[i*2]   = __nv_bfloat162(h0, h1);
        hp[i*2+1] = __nv_bfloat162(h2, h3);
        lp[i*2]   = __nv_bfloat162(l0, l1);
        lp[i*2+1] = __nv_bfloat162(l2, l3);
    }
}

// vector helpers
#define VOP4(dst, ex, ey, ez, ew) do { dst.x=(ex); dst.y=(ey); dst.z=(ez); dst.w=(ew); } while(0)
__device__ __forceinline__ float dot4(float4 a, float4 b) { return a.x*b.x + a.y*b.y + a.z*b.z + a.w*b.w; }
__device__ __forceinline__ float sq4(float4 a) { return dot4(a, a); }
__device__ __forceinline__ float4 scl4(float4 a, float s) { float4 r; VOP4(r, a.x*s, a.y*s, a.z*s, a.w*s); return r; }

// ---------------- ln block ----------------
template <int E, int T>
__global__ void __launch_bounds__(T) ln_kernel(
    const float* __restrict__ x, const float* __restrict__ g, const float* __restrict__ b,
    float* __restrict__ outf, __nv_bfloat16* __restrict__ oh, __nv_bfloat16* __restrict__ ol,
    float* __restrict__ out_norm, int do_projx)
{
    constexpr int V4 = E / (T * 4);
    const size_t row = blockIdx.x;
    const int tid = threadIdx.x;
    const float MAXN = maxnorm();
    const float4* xp = (const float4*)(x + row * E);
    const float4* gp = (const float4*)g;
    const float4* bp = (const float4*)b;
    float4 v[V4];
    float ss = 0.0f;
    #pragma unroll
    for (int i = 0; i < V4; i++) { v[i] = xp[tid*V4 + i]; ss += sq4(v[i]); }
    float n0 = sqrtf(blockSumF<T>(ss) + 1e-30f);
    float lf = atanhf(fminf(n0, MAXN)) / n0;
    float sm = 0.0f;
    #pragma unroll
    for (int i = 0; i < V4; i++) { v[i] = scl4(v[i], lf); sm += v[i].x + v[i].y + v[i].z + v[i].w; }
    float mu = blockSumF<T>(sm) * (1.0f / E);
    float vv = 0.0f;
    #pragma unroll
    for (int i = 0; i < V4; i++) {
        float4 d; VOP4(d, v[i].x-mu, v[i].y-mu, v[i].z-mu, v[i].w-mu);
        vv += sq4(d);
    }
    float var = blockSumF<T>(vv) * (1.0f / E);
    float inv = rsqrtf(var + 1e-5f);
    float s2 = 0.0f;
    #pragma unroll
    for (int i = 0; i < V4; i++) {
        float4 gg = gp[tid*V4 + i], bb = bp[tid*V4 + i];
        VOP4(v[i], (v[i].x-mu)*inv*gg.x + bb.x, (v[i].y-mu)*inv*gg.y + bb.y,
                   (v[i].z-mu)*inv*gg.z + bb.z, (v[i].w-mu)*inv*gg.w + bb.w);
        s2 += sq4(v[i]);
    }
    float ny = sqrtf(blockSumF<T>(s2) + 1e-30f);
    float ef = tanhf(ny) / ny;
    #pragma unroll
    for (int i = 0; i < V4; i++) v[i] = scl4(v[i], ef);
    if (do_projx) {
        float s3 = 0.0f;
        #pragma unroll
        for (int i = 0; i < V4; i++) s3 += sq4(v[i]);
        float n = sqrtf(blockSumF<T>(s3) + 1e-30f);
        if (n > MAXN) { float ps = MAXN / n;
            #pragma unroll
            for (int i = 0; i < V4; i++) v[i] = scl4(v[i], ps); }
    }
    float s4 = 0.0f;
    #pragma unroll
    for (int i = 0; i < V4; i++) {
        if (outf) ((float4*)(outf + row*E))[tid*V4 + i] = v[i];
        if (oh) {
            __nv_bfloat16 h0,l0,h1,l1,h2,l2,h3,l3;
            split1(v[i].x,h0,l0); split1(v[i].y,h1,l1); split1(v[i].z,h2,l2); split1(v[i].w,h3,l3);
            ((__nv_bfloat162*)(oh + row*E))[tid*V4*2 + i*2]   = __nv_bfloat162(h0,h1);
            ((__nv_bfloat162*)(oh + row*E))[tid*V4*2 + i*2+1] = __nv_bfloat162(h2,h3);
            ((__nv_bfloat162*)(ol + row*E))[tid*V4*2 + i*2]   = __nv_bfloat162(l0,l1);
            ((__nv_bfloat162*)(ol + row*E))[tid*V4*2 + i*2+1] = __nv_bfloat162(l2,l3);
        }
        s4 += sq4(v[i]);
    }
    float nf = sqrtf(blockSumF<T>(s4) + 1e-30f);
    if (tid == 0) out_norm[row] = nf;
}

// ---------------- expmap0 rows -> bf16 split + norm ----------------
template <int E, int T>
__global__ void __launch_bounds__(T) expmap_rows(
    const float* __restrict__ x, __nv_bfloat16* __restrict__ oh, __nv_bfloat16* __restrict__ ol,
    float* __restrict__ out_norm)
{
    constexpr int V4 = E / (T * 4);
    const size_t row = blockIdx.x;
    const int tid = threadIdx.x;
    const float4* xp = (const float4*)(x + row * E);
    float4 v[V4];
    float ss = 0.0f;
    #pragma unroll
    for (int i = 0; i < V4; i++) { v[i] = xp[tid*V4 + i]; ss += sq4(v[i]); }
    float n = sqrtf(blockSumF<T>(ss) + 1e-30f);
    float ef = tanhf(n) / n;
    float s2 = 0.0f;
    #pragma unroll
    for (int i = 0; i < V4; i++) {
        v[i] = scl4(v[i], ef);
        __nv_bfloat16 h0,l0,h1,l1,h2,l2,h3,l3;
        split1(v[i].x,h0,l0); split1(v[i].y,h1,l1); split1(v[i].z,h2,l2); split1(v[i].w,h3,l3);
        ((__nv_bfloat162*)(oh + row*E))[tid*V4*2 + i*2]   = __nv_bfloat162(h0,h1);
        ((__nv_bfloat162*)(oh + row*E))[tid*V4*2 + i*2+1] = __nv_bfloat162(h2,h3);
        ((__nv_bfloat162*)(ol + row*E))[tid*V4*2 + i*2]   = __nv_bfloat162(l0,l1);
        ((__nv_bfloat162*)(ol + row*E))[tid*V4*2 + i*2+1] = __nv_bfloat162(l2,l3);
        s2 += sq4(v[i]);
    }
    float nf = sqrtf(blockSumF<T>(s2) + 1e-30f);
    if (tid == 0) out_norm[row] = nf;
}

// ---------------- fused q/k/v manifold epilogue -> bf16 hi/lo (stride QKVW) ----------------
__global__ void __launch_bounds__(128) manlin_qkv(
    const float* __restrict__ qkvf, const float* __restrict__ xnb,
    const float* __restrict__ bq, const float* __restrict__ bk, const float* __restrict__ bv,
    __nv_bfloat16* __restrict__ oh, __nv_bfloat16* __restrict__ ol)
{
    const size_t row = blockIdx.x;
    const int seg = blockIdx.y;
    const int tid = threadIdx.x;
    const float MAXN = maxnorm();
    const float* bias = (seg == 0) ? bq : (seg == 1) ? bk : bv;
    const float* base = qkvf + row * (size_t)QKVW + seg * 512;
    float4 v = ((const float4*)base)[tid];
    float4 bvv = ((const float4*)bias)[tid];
    float mxn = sqrtf(blockSumF<128>(sq4(v)) + 1e-30f);
    float xn = xnb[row];
    float s = tanhf(mxn / xn * atanhf(fminf(xn, MAXN))) / mxn;
    v = scl4(v, s);
    float xy = blockSumF<128>(dot4(v, bvv));
    float x2 = blockSumF<128>(sq4(v));
    float y2 = g_b2[seg];
    float a = 1.0f + 2.0f*xy + y2;
    float c = 1.0f - x2;
    float invd = 1.0f / fmaxf(1.0f + 2.0f*xy + x2*y2, 1e-15f);
    VOP4(v, (a*v.x + c*bvv.x)*invd, (a*v.y + c*bvv.y)*invd,
            (a*v.z + c*bvv.z)*invd, (a*v.w + c*bvv.w)*invd);
    float zn = sqrtf(blockSumF<128>(sq4(v)) + 1e-30f);
    if (zn > MAXN) v = scl4(v, MAXN / zn);
    float n = sqrtf(blockSumF<128>(sq4(v)) + 1e-30f);
    float lf = atanhf(fminf(n, MAXN)) / n;
    v = scl4(v, lf);
    // write bf16 hi/lo at stride QKVW
    size_t ob = row * (size_t)QKVW + seg * 512;
    __nv_bfloat16 h0,l0,h1,l1,h2,l2,h3,l3;
    split1(v.x,h0,l0); split1(v.y,h1,l1); split1(v.z,h2,l2); split1(v.w,h3,l3);
    ((__nv_bfloat162*)(oh + ob))[tid*2]   = __nv_bfloat162(h0,h1);
    ((__nv_bfloat162*)(oh + ob))[tid*2+1] = __nv_bfloat162(h2,h3);
    ((__nv_bfloat162*)(ol + ob))[tid*2]   = __nv_bfloat162(l0,l1);
    ((__nv_bfloat162*)(ol + ob))[tid*2+1] = __nv_bfloat162(l2,l3);
}

// ---------------- man_linear epilogue (general) ----------------
template <int E, int T>
__global__ void __launch_bounds__(T) manlin_epi(
    const float* __restrict__ mx, int ldm, const float* __restrict__ xnb,
    const float* __restrict__ bias, int b2idx,
    const float* __restrict__ resid,
    float* __restrict__ outf, __nv_bfloat16* __restrict__ oh, __nv_bfloat16* __restrict__ ol,
    float* __restrict__ out_norm, int flags)
{
    constexpr int V4 = E / (T * 4);
    const size_t row = blockIdx.x;
    const int tid = threadIdx.x;
    const float MAXN = maxnorm();
    const float4* mp = (const float4*)(mx + row*(size_t)ldm);
    const float4* bp = (const float4*)bias;
    float4 v[V4], bv[V4];
    float ss = 0.0f;
    #pragma unroll
    for (int i = 0; i < V4; i++) { v[i] = mp[tid*V4 + i]; ss += sq4(v[i]); }
    float mxn = sqrtf(blockSumF<T>(ss) + 1e-30f);
    float xn = xnb[row];
    float s = tanhf(mxn / xn * atanhf(fminf(xn, MAXN))) / mxn;
    float dxy = 0.0f, dx2 = 0.0f;
    #pragma unroll
    for (int i = 0; i < V4; i++) {
        v[i] = scl4(v[i], s);
        bv[i] = bp[tid*V4 + i];
        dxy += dot4(v[i], bv[i]);
        dx2 += sq4(v[i]);
    }
    float xy = blockSumF<T>(dxy);
    float x2 = blockSumF<T>(dx2);
    float y2 = g_b2[b2idx];
    float a = 1.0f + 2.0f*xy + y2;
    float c = 1.0f - x2;
    float den = fmaxf(1.0f + 2.0f*xy + x2*y2, 1e-15f);
    float invd = 1.0f / den;
    float zz = 0.0f;
    #pragma unroll
    for (int i = 0; i < V4; i++) {
        VOP4(v[i], (a*v[i].x + c*bv[i].x)*invd, (a*v[i].y + c*bv[i].y)*invd,
                   (a*v[i].z + c*bv[i].z)*invd, (a*v[i].w + c*bv[i].w)*invd);
        zz += sq4(v[i]);
    }
    {
        float zn = sqrtf(blockSumF<T>(zz) + 1e-30f);
        if (zn > MAXN) { float ps = MAXN / zn;
            #pragma unroll
            for (int i = 0; i < V4; i++) v[i] = scl4(v[i], ps); }
    }
    if (flags & FLAG_MOBRELU) {
        float s0 = 0.0f;
        #pragma unroll
        for (int i = 0; i < V4; i++) s0 += sq4(v[i]);
        float n = sqrtf(blockSumF<T>(s0) + 1e-30f);
        float lf = atanhf(fminf(n, MAXN)) / n;
        float s1 = 0.0f;
        #pragma unroll
        for (int i = 0; i < V4; i++) {
            VOP4(v[i], fmaxf(lf*v[i].x, 0.0f), fmaxf(lf*v[i].y, 0.0f),
                       fmaxf(lf*v[i].z, 0.0f), fmaxf(lf*v[i].w, 0.0f));
            s1 += sq4(v[i]);
        }
        float nr = sqrtf(blockSumF<T>(s1) + 1e-30f);
        float ef = tanhf(nr) / nr;
        float s2 = 0.0f;
        #pragma unroll
        for (int i = 0; i < V4; i++) { v[i] = scl4(v[i], ef); s2 += sq4(v[i]); }
        float n2 = sqrtf(blockSumF<T>(s2) + 1e-30f);
        if (n2 > MAXN) { float ps = MAXN / n2;
            #pragma unroll
            for (int i = 0; i < V4; i++) v[i] = scl4(v[i], ps); }
    }
    if (flags & FLAG_RESID) {
        const float4* rp = (const float4*)(resid + row*E);
        float4 rv[V4];
        float d1 = 0.0f, d2 = 0.0f, d3 = 0.0f;
        #pragma unroll
        for (int i = 0; i < V4; i++) {
            rv[i] = rp[tid*V4 + i];
            d1 += dot4(v[i], rv[i]);
            d2 += sq4(rv[i]);
            d3 += sq4(v[i]);
        }
        float rxy = blockSumF<T>(d1);
        float ry2 = blockSumF<T>(d2);
        float rx2 = blockSumF<T>(d3);
        float ra = 1.0f + 2.0f*rxy + ry2;
        float rc = 1.0f - rx2;
        float rden = fmaxf(1.0f + 2.0f*rxy + rx2*ry2, 1e-15f);
        float rinv = 1.0f / rden;
        float s3 = 0.0f;
        #pragma unroll
        for (int i = 0; i < V4; i++) {
            VOP4(v[i], (ra*v[i].x + rc*rv[i].x)*rinv, (ra*v[i].y + rc*rv[i].y)*rinv,
                       (ra*v[i].z + rc*rv[i].z)*rinv, (ra*v[i].w + rc*rv[i].w)*rinv);
            s3 += sq4(v[i]);
        }
        float zn = sqrtf(blockSumF<T>(s3) + 1e-30f);
        if (zn > MAXN) { float ps = MAXN / zn;
            #pragma unroll
            for (int i = 0; i < V4; i++) v[i] = scl4(v[i], ps); }
    }
    if (flags & FLAG_LOGMAP) {
        float s4 = 0.0f;
        #pragma unroll
        for (int i = 0; i < V4; i++) s4 += sq4(v[i]);
        float n = sqrtf(blockSumF<T>(s4) + 1e-30f);
        float lf = atanhf(fminf(n, MAXN)) / n;
        #pragma unroll
        for (int i = 0; i < V4; i++) v[i] = scl4(v[i], lf);
    }
    float s5 = 0.0f;
    #pragma unroll
    for (int i = 0; i < V4; i++) {
        if (outf) ((float4*)(outf + row*(size_t)ldm))[tid*V4 + i] = v[i];
        if (oh) {
            __nv_bfloat16 h0,l0,h1,l1,h2,l2,h3,l3;
            split1(v[i].x,h0,l0); split1(v[i].y,h1,l1); split1(v[i].z,h2,l2); split1(v[i].w,h3,l3);
            ((__nv_bfloat162*)(oh + row*E))[tid*V4*2 + i*2]   = __nv_bfloat162(h0,h1);
            ((__nv_bfloat162*)(oh + row*E))[tid*V4*2 + i*2+1] = __nv_bfloat162(h2,h3);
            ((__nv_bfloat162*)(ol + row*E))[tid*V4*2 + i*2]   = __nv_bfloat162(l0,l1);
            ((__nv_bfloat162*)(ol + row*E))[tid*V4*2 + i*2+1] = __nv_bfloat162(l2,l3);
        }
        s5 += sq4(v[i]);
    }
    if (out_norm) {
        float nf = sqrtf(blockSumF<T>(s5) + 1e-30f);
        if (tid == 0) out_norm[row] = nf;
    }
}

// ---------------- MMA helpers (shared by GEMM + attention) ----------------
__device__ __forceinline__ void ldsm_x4(uint32_t &r0, uint32_t &r1, uint32_t &r2, uint32_t &r3, uint32_t addr) {
    asm volatile("ldmatrix.sync.aligned.m8n8.x4.shared.b16 {%0,%1,%2,%3}, [%4];"
                 : "=r"(r0), "=r"(r1), "=r"(r2), "=r"(r3) : "r"(addr));
}
__device__ __forceinline__ void ldsm_x2(uint32_t &r0, uint32_t &r1, uint32_t addr) {
    asm volatile("ldmatrix.sync.aligned.m8n8.x2.shared.b16 {%0,%1}, [%2];"
                 : "=r"(r0), "=r"(r1) : "r"(addr));
}
__device__ __forceinline__ void ldsm_x2t(uint32_t &r0, uint32_t &r1, uint32_t addr) {
    asm volatile("ldmatrix.sync.aligned.m8n8.x2.trans.shared.b16 {%0,%1}, [%2];"
                 : "=r"(r0), "=r"(r1) : "r"(addr));
}
__device__ __forceinline__ void mma16816(float* c, const uint32_t* a, const uint32_t* b) {
    asm volatile("mma.sync.aligned.m16n8k16.row.col.f32.bf16.bf16.f32 "
                 "{%0,%1,%2,%3}, {%4,%5,%6,%7}, {%8,%9}, {%0,%1,%2,%3};"
                 : "+f"(c[0]), "+f"(c[1]), "+f"(c[2]), "+f"(c[3])
                 : "r"(a[0]), "r"(a[1]), "r"(a[2]), "r"(a[3]), "r"(b[0]), "r"(b[1]));
}
#define CP_ASYNC16(dst, src) asm volatile("cp.async.cg.shared.global [%0], [%1], 16;" :: "r"(dst), "l"(src))

// ---------------- tensor-core attention: 1 CTA per (b,h), 8 warps x 16 queries ----------------
// smem: qh/ql/kh/kl/vh/vl tiles, each 128 rows x 64 bf16 (128B rows, chunk-XOR swizzle) = 96KB
#define ATT_SMEM 98304
__global__ void __launch_bounds__(256) attn_mma(
    const __nv_bfloat16* __restrict__ qh_g, const __nv_bfloat16* __restrict__ ql_g,
    float* __restrict__ o)
{
    extern __shared__ __nv_bfloat16 smbuf[];
    uint32_t smb = (uint32_t)__cvta_generic_to_shared(smbuf);
    const int tid = threadIdx.x;
    const int lane = tid & 31, w = tid >> 5;
    const int bh = blockIdx.x, b = bh >> 3, h = bh & 7;

    // load q,k,v hi/lo (6 tensors x 128 rows x 8 chunks of 16B)
    #pragma unroll
    for (int it = 0; it < 24; it++) {
        int idx = tid + (it << 8);
        int tensor = idx >> 10;
        int cid = idx & 1023;
        int r = cid >> 3, c = cid & 7;
        uint32_t dst = smb + tensor*16384 + r*128 + ((c ^ (r & 7)) << 4);
        const __nv_bfloat16* P = (tensor & 1) ? ql_g : qh_g;
        const __nv_bfloat16* src = P + ((size_t)r*BB + b)*QKVW + (size_t)(tensor>>1)*512 + h*HD + c*8;
        CP_ASYNC16(dst, src);
    }
    asm volatile("cp.async.commit_group;");
    asm volatile("cp.async.wait_group 0;");
    __syncthreads();

    const int quad = lane >> 3, r8 = lane & 7;

    // phase 1: scores[16 queries x 128 keys] per warp (bf16x2: qh*kh + qh*kl + ql*kh)
    float sc[16][4];
    #pragma unroll
    for (int n = 0; n < 16; n++)
        #pragma unroll
        for (int e = 0; e < 4; e++) sc[n][e] = 0.0f;

    #pragma unroll
    for (int kk = 0; kk < 4; kk++) {
        uint32_t qh_[4], ql_[4];
        int arow = w*16 + (quad & 1)*8 + r8;
        int achk = kk*2 + (quad >> 1);
        uint32_t aoff = (uint32_t)(arow*128 + ((achk ^ (arow & 7)) << 4));
        ldsm_x4(qh_[0], qh_[1], qh_[2], qh_[3], smb + aoff);
        ldsm_x4(ql_[0], ql_[1], ql_[2], ql_[3], smb + 16384 + aoff);
        #pragma unroll
        for (int n = 0; n < 16; n++) {
            int krow = n*8 + (lane & 7);
            int kchk = kk*2 + ((lane >> 3) & 1);
            uint32_t koff = (uint32_t)(krow*128 + ((kchk ^ (krow & 7)) << 4));
            uint32_t kb[2], kl[2];
            ldsm_x2(kb[0], kb[1], smb + 32768 + koff);
            ldsm_x2(kl[0], kl[1], smb + 49152 + koff);
            mma16816(sc[n], qh_, kb);
            mma16816(sc[n], qh_, kl);
            mma16816(sc[n], ql_, kb);
        }
    }

    // phase 2: softmax (rows g = lane>>2 and g+8; scale 1/8 inside exp)
    float m0 = -1e30f, m1 = -1e30f;
    #pragma unroll
    for (int n = 0; n < 16; n++) {
        m0 = fmaxf(m0, fmaxf(sc[n][0], sc[n][1]));
        m1 = fmaxf(m1, fmaxf(sc[n][2], sc[n][3]));
    }
    m0 = fmaxf(m0, __shfl_xor_sync(0xffffffffu, m0, 1));
    m0 = fmaxf(m0, __shfl_xor_sync(0xffffffffu, m0, 2));
    m1 = fmaxf(m1, __shfl_xor_sync(0xffffffffu, m1, 1));
    m1 = fmaxf(m1, __shfl_xor_sync(0xffffffffu, m1, 2));
    float l0 = 0.0f, l1 = 0.0f;
    #pragma unroll
    for (int n = 0; n < 16; n++) {
        sc[n][0] = fexp((sc[n][0] - m0) * 0.125f); l0 += sc[n][0];
        sc[n][1] = fexp((sc[n][1] - m0) * 0.125f); l0 += sc[n][1];
        sc[n][2] = fexp((sc[n][2] - m1) * 0.125f); l1 += sc[n][2];
        sc[n][3] = fexp((sc[n][3] - m1) * 0.125f); l1 += sc[n][3];
    }
    l0 += __shfl_xor_sync(0xffffffffu, l0, 1);
    l0 += __shfl_xor_sync(0xffffffffu, l0, 2);
    l1 += __shfl_xor_sync(0xffffffffu, l1, 1);
    l1 += __shfl_xor_sync(0xffffffffu, l1, 2);
    float inv0 = 1.0f / l0, inv1 = 1.0f / l1;

    // phase 3: O = P @ V (P split hi/lo, V split hi/lo: ph*vh + ph*vl + pl*vh)
    float oa[8][4];
    #pragma unroll
    for (int n = 0; n < 8; n++)
        #pragma unroll
        for (int e = 0; e < 4; e++) oa[n][e] = 0.0f;

    #pragma unroll
    for (int kt = 0; kt < 8; kt++) {
        uint32_t ph[4], pl[4];
        #pragma unroll
        for (int half = 0; half < 2; half++) {
            int n2 = 2*kt + half;
            float p0 = sc[n2][0], p1 = sc[n2][1], p2 = sc[n2][2], p3 = sc[n2][3];
            __nv_bfloat16 b0 = __float2bfloat16(p0), b1 = __float2bfloat16(p1);
            __nv_bfloat16 b2 = __float2bfloat16(p2), b3 = __float2bfloat16(p3);
            ph[half*2+0] = pack_bf2(p0, p1);   // rounds again identically
            ph[half*2+1] = pack_bf2(p2, p3);
            pl[half*2+0] = pack_bf2(p0 - __bfloat162float(b0), p1 - __bfloat162float(b1));
            pl[half*2+1] = pack_bf2(p2 - __bfloat162float(b2), p3 - __bfloat162float(b3));
        }
        // reorder to A-frag: a0=tile(2kt)c01, a1=tile(2kt)c23, a2=tile(2kt+1)c01, a3=tile(2kt+1)c23
        // (already in that order: half0 -> ph[0],ph[1]; half1 -> ph[2],ph[3])
        #pragma unroll
        for (int n = 0; n < 8; n++) {
            int vrow = kt*16 + (lane & 15);
            uint32_t voff = (uint32_t)(vrow*128 + ((n ^ (vrow & 7)) << 4));
            uint32_t vh[2], vl[2];
            ldsm_x2t(vh[0], vh[1], smb + 65536 + voff);
            ldsm_x2t(vl[0], vl[1], smb + 81920 + voff);
            mma16816(oa[n], ph, vh);
            mma16816(oa[n], ph, vl);
            mma16816(oa[n], pl, vh);
        }
    }

    // phase 4: scale by 1/l and write fp32 O
    int g = lane >> 2, t2 = (lane & 3) * 2;
    int t0 = w*16 + g;
    #pragma unroll
    for (int n = 0; n < 8; n++) {
        size_t base0 = ((size_t)t0*BB + b)*ED + (size_t)h*HD + n*8 + t2;
        size_t base1 = ((size_t)(t0+8)*BB + b)*ED + (size_t)h*HD + n*8 + t2;
        *(float2*)(o + base0) = make_float2(oa[n][0]*inv0, oa[n][1]*inv0);
        *(float2*)(o + base1) = make_float2(oa[n][2]*inv1, oa[n][3]*inv1);
    }
}

// ================= bf16x3 HMMA GEMM: 3-stage pipeline, 64B swizzled rows =================
#define BM 128
#define BN 128
#define BK 32
#define TEN_B   8192
#define STAGE_B (4*TEN_B)
#define GEMM_SMEM (3*STAGE_B)

__device__ __forceinline__ uint32_t saddr(int r, int colElem) {
    return (uint32_t)(r*64 + ((((colElem >> 3) ^ ((r >> 1) & 3))) << 4));
}

__global__ void __launch_bounds__(256, 2) gemm_bf16x3(
    const __nv_bfloat16* __restrict__ Ah, const __nv_bfloat16* __restrict__ Al,
    const __nv_bfloat16* __restrict__ Wh, const __nv_bfloat16* __restrict__ Wl,
    float* __restrict__ C, int M, int N, int K)
{
    extern __shared__ __nv_bfloat16 smbuf[];
    const int tid = threadIdx.x;
    const int lane = tid & 31, w = tid >> 5;
    const int wm = w & 1, wn = w >> 1;
    const int rowBase = blockIdx.y * BM;
    const int colBase = blockIdx.x * BN;
    uint32_t smbase = (uint32_t)__cvta_generic_to_shared(smbuf);

    float acc[4][4][4];
    #pragma unroll
    for (int i = 0; i < 4; i++)
        #pragma unroll
        for (int j = 0; j < 4; j++)
            #pragma unroll
            for (int e = 0; e < 4; e++) acc[i][j][e] = 0.0f;

    auto load_stage = [&](int st, int k0) {
        uint32_t base = smbase + st * STAGE_B;
        #pragma unroll
        for (int it = 0; it < 8; it++) {
            int idx = tid + (it << 8);
            int tensor = idx >> 9;
            int cid = idx & 511;
            int r = cid >> 2, c = cid & 3;
            uint32_t dst = base + tensor * TEN_B
                         + (uint32_t)(r*64 + ((c ^ ((r >> 1) & 3)) << 4));
            const __nv_bfloat16* src;
            if (tensor == 0)      src = Ah + (size_t)(rowBase + r) * K + k0 + c * 8;
            else if (tensor == 1) src = Al + (size_t)(rowBase + r) * K + k0 + c * 8;
            else if (tensor == 2) src = Wh + (size_t)(colBase + r) * K + k0 + c * 8;
            else                  src = Wl + (size_t)(colBase + r) * K + k0 + c * 8;
            CP_ASYNC16(dst, src);
        }
        asm volatile("cp.async.commit_group;");
    };

    auto compute_stage = [&](int st) {
        uint32_t base = smbase + st * STAGE_B;
        uint32_t aH = base;
        uint32_t aL = base + 1*TEN_B;
        uint32_t wH = base + 2*TEN_B;
        uint32_t wL = base + 3*TEN_B;
        const int quad = lane >> 3, r8 = lane & 7;
        #pragma unroll
        for (int kk = 0; kk < BK; kk += 16) {
            uint32_t ah[4][4], al[4][4], bh[4][2], bl[4][2];
            #pragma unroll
            for (int i = 0; i < 4; i++) {
                int row = wm*64 + i*16 + (quad & 1)*8 + r8;
                int col = kk + (quad >> 1)*8;
                uint32_t off = saddr(row, col);
                ldsm_x4(ah[i][0], ah[i][1], ah[i][2], ah[i][3], aH + off);
                ldsm_x4(al[i][0], al[i][1], al[i][2], al[i][3], aL + off);
            }
            #pragma unroll
            for (int j = 0; j < 4; j++) {
                int nr = wn*32 + j*8 + (lane & 7);
                int kc = kk + ((lane >> 3) & 1)*8;
                uint32_t off = saddr(nr, kc);
                ldsm_x2(bh[j][0], bh[j][1], wH + off);
                ldsm_x2(bl[j][0], bl[j][1], wL + off);
            }
            #pragma unroll
            for (int i = 0; i < 4; i++)
                #pragma unroll
                for (int j = 0; j < 4; j++) mma16816(acc[i][j], ah[i], bh[j]);
            #pragma unroll
            for (int i = 0; i < 4; i++)
                #pragma unroll
                for (int j = 0; j < 4; j++) mma16816(acc[i][j], ah[i], bl[j]);
            #pragma unroll
            for (int i = 0; i < 4; i++)
                #pragma unroll
                for (int j = 0; j < 4; j++) mma16816(acc[i][j], al[i], bh[j]);
        }
    };

    const int nkb = K / BK;
    load_stage(0, 0);
    load_stage(1, BK);
    for (int kb = 0; kb < nkb; kb++) {
        if (kb == nkb - 1) { asm volatile("cp.async.wait_group 0;"); }
        else               { asm volatile("cp.async.wait_group 1;"); }
        __syncthreads();
        if (kb + 2 < nkb) load_stage((kb + 2) % 3, (kb + 2) * BK);
        compute_stage(kb % 3);
    }

    const int g = lane >> 2, tg = lane & 3;
    #pragma unroll
    for (int i = 0; i < 4; i++) {
        int row = rowBase + wm*64 + i*16 + g;
        #pragma unroll
        for (int j = 0; j < 4; j++) {
            int col = colBase + wn*32 + j*8 + tg*2;
            *(float2*)(C + (size_t)row * N + col)       = make_float2(acc[i][j][0], acc[i][j][1]);
            *(float2*)(C + (size_t)(row + 8) * N + col) = make_float2(acc[i][j][2], acc[i][j][3]);
        }
    }
}

// ---------------- launch ----------------
extern "C" void kernel_launch(void* const* d_in, const int* in_sizes, int n_in,
                              void* d_out, int out_size)
{
    const float* x    = (const float*)d_in[0];
    const float* l1g  = (const float*)d_in[1];
    const float* l1b  = (const float*)d_in[2];
    const float* l2g  = (const float*)d_in[3];
    const float* l2b  = (const float*)d_in[4];
    const float* Wq   = (const float*)d_in[5];
    const float* bq   = (const float*)d_in[6];
    const float* Wk   = (const float*)d_in[7];
    const float* bk   = (const float*)d_in[8];
    const float* Wv   = (const float*)d_in[9];
    const float* bv   = (const float*)d_in[10];
    const float* Wo   = (const float*)d_in[11];
    const float* bo   = (const float*)d_in[12];
    const float* W1   = (const float*)d_in[13];
    const float* b1   = (const float*)d_in[14];
    const float* W2   = (const float*)d_in[15];
    const float* b2   = (const float*)d_in[16];
    float* out = (float*)d_out;

    float *qkv, *ob, *h1, *big, *n0, *no, *nh2, *nh3, *bsq;
    __nv_bfloat16 *xh, *xl, *wh, *wl;
    cudaGetSymbolAddress((void**)&qkv, g_qkv);
    cudaGetSymbolAddress((void**)&ob,  g_o);
    cudaGetSymbolAddress((void**)&h1,  g_h1);
    cudaGetSymbolAddress((void**)&big, g_big);
    cudaGetSymbolAddress((void**)&xh,  g_xh);
    cudaGetSymbolAddress((void**)&xl,  g_xl);
    cudaGetSymbolAddress((void**)&wh,  g_wh);
    cudaGetSymbolAddress((void**)&wl,  g_wl);
    cudaGetSymbolAddress((void**)&n0,  g_n0);
    cudaGetSymbolAddress((void**)&no,  g_no);
    cudaGetSymbolAddress((void**)&nh2, g_nh2);
    cudaGetSymbolAddress((void**)&nh3, g_nh3);
    cudaGetSymbolAddress((void**)&bsq, g_b2);

    cudaFuncSetAttribute(gemm_bf16x3, cudaFuncAttributeMaxDynamicSharedMemorySize, GEMM_SMEM);
    cudaFuncSetAttribute(attn_mma, cudaFuncAttributeMaxDynamicSharedMemorySize, ATT_SMEM);

    split_all<<<dim3(1024, 6), 256>>>(Wq, Wk, Wv, Wo, W1, W2, wh, wl);
    sqsum6<<<6, 256>>>(bq, bk, bv, bo, b1, b2, bsq);
    ln_kernel<ED, 128><<<NR, 128>>>(x, l1g, l1b, nullptr, xh, xl, n0, 0);

    gemm_bf16x3<<<dim3(QKVW/BN, NR/BM), 256, GEMM_SMEM>>>(xh, xl, wh + WQ0, wl + WQ0, qkv, NR, QKVW, ED);
    // q/k/v manifold epilogue -> bf16 hi/lo (overwrites xh/xl, which the QKV GEMM is done with)
    manlin_qkv<<<dim3(NR, 3), 128>>>(qkv, n0, bq, bk, bv, xh, xl);

    attn_mma<<<BB * NH, 256, ATT_SMEM>>>(xh, xl, ob);
    expmap_rows<ED, 128><<<NR, 128>>>(ob, xh, xl, no);

    gemm_bf16x3<<<dim3(ED/BN, NR/BM), 256, GEMM_SMEM>>>(xh, xl, wh + WO0, wl + WO0, big, NR, ED, ED);
    manlin_epi<ED, 128><<<NR, 128>>>(big, ED, no, bo, 3, x, h1, nullptr, nullptr, nullptr, FLAG_RESID);

    ln_kernel<ED, 128><<<NR, 128>>>(h1, l2g, l2b, nullptr, xh, xl, nh2, 1);

    gemm_bf16x3<<<dim3(FD/BN, NR/BM), 256, GEMM_SMEM>>>(xh, xl, wh + W10, wl + W10, big, NR, FD, ED);
    manlin_epi<FD, 256><<<NR, 256>>>(big, FD, nh2, b1, 4, nullptr, nullptr, xh, xl, nh3, FLAG_MOBRELU);

    gemm_bf16x3<<<dim3(ED/BN, NR/BM), 256, GEMM_SMEM>>>(xh, xl, wh + W20, wl + W20, qkv, NR, ED, FD);
    manlin_epi<ED, 128><<<NR, 128>>>(qkv, ED, nh3, b2, 5, h1, out, nullptr, nullptr, nullptr, FLAG_MOBRELU | FLAG_RESID);
}

// round 8
// speedup vs baseline: 7.8912x; 1.0455x over previous
#include <cuda_runtime.h>
#include <cuda_bf16.h>
#include <math.h>
#include <stdint.h>

// ---------------- problem constants ----------------
#define SEQ 128
#define BB  256
#define ED  512
#define FD  2048
#define NH  8
#define HD  64
#define NR  (SEQ*BB)   // 32768 rows
#define QKVW 1536      // fused qkv row width

static __device__ __forceinline__ float maxnorm() { return (float)(1.0 - 1e-5); }

// ---------------- scratch ----------------
__device__ float g_qkv[(size_t)NR*QKVW];
__device__ float g_o  [(size_t)NR*ED];
__device__ float g_h1 [(size_t)NR*ED];
__device__ float g_big[(size_t)NR*FD];
__device__ __nv_bfloat16 g_xh[(size_t)NR*FD];
__device__ __nv_bfloat16 g_xl[(size_t)NR*FD];
__device__ __nv_bfloat16 g_wh[(size_t)3*1024*1024];
__device__ __nv_bfloat16 g_wl[(size_t)3*1024*1024];
__device__ float g_n0 [NR];
__device__ float g_no [NR];
__device__ float g_nh2[NR];
__device__ float g_nh3[NR];
__device__ float g_b2 [8];

#define WQ0 0
#define WK0 262144
#define WV0 524288
#define WO0 786432
#define W10 1048576
#define W20 2097152

#define FLAG_LOGMAP  1
#define FLAG_MOBRELU 2
#define FLAG_RESID   4

// ---------------- block reduction (fp32, pairwise) ----------------
template <int T>
__device__ __forceinline__ float blockSumF(float v) {
    __shared__ float sh[T / 32];
    #pragma unroll
    for (int o = 16; o > 0; o >>= 1) v += __shfl_xor_sync(0xffffffffu, v, o);
    int lane = threadIdx.x & 31, w = threadIdx.x >> 5;
    if (lane == 0) sh[w] = v;
    __syncthreads();
    if (threadIdx.x < 32) {
        float t = (threadIdx.x < T / 32) ? sh[threadIdx.x] : 0.0f;
        #pragma unroll
        for (int o = 16; o > 0; o >>= 1) t += __shfl_xor_sync(0xffffffffu, t, o);
        if (threadIdx.x == 0) sh[0] = t;
    }
    __syncthreads();
    float r = sh[0];
    __syncthreads();
    return r;
}

__device__ __forceinline__ void split1(float x, __nv_bfloat16 &h, __nv_bfloat16 &l) {
    h = __float2bfloat16(x);
    l = __float2bfloat16(x - __bfloat162float(h));
}
__device__ __forceinline__ uint32_t pack_bf2(float a, float b) {
    __nv_bfloat162 t(__float2bfloat16(a), __float2bfloat16(b));
    return *(uint32_t*)&t;
}

// FMA-pipe exp (no MUFU)
__device__ __forceinline__ float fexp(float x) {
    float y = x * 1.4426950408889634f;
    y = fmaxf(y, -126.0f);
    float fl = floorf(y);
    float f = y - fl;
    float p = 1.5252734e-5f;
    p = fmaf(p, f, 1.5403530e-4f);
    p = fmaf(p, f, 1.3333558e-3f);
    p = fmaf(p, f, 9.6181291e-3f);
    p = fmaf(p, f, 5.5504109e-2f);
    p = fmaf(p, f, 2.4022651e-1f);
    p = fmaf(p, f, 6.9314718e-1f);
    p = fmaf(p, f, 1.0f);
    return __int_as_float(__float_as_int(p) + (((int)fl) << 23));
}

// ---------------- all 6 bias squared-norms ----------------
__global__ void sqsum6(const float* bq, const float* bk, const float* bv,
                       const float* bo, const float* b1, const float* b2,
                       float* __restrict__ out) {
    const float* p;
    int n;
    switch (blockIdx.x) {
        case 0: p = bq; n = ED; break;
        case 1: p = bk; n = ED; break;
        case 2: p = bv; n = ED; break;
        case 3: p = bo; n = ED; break;
        case 4: p = b1; n = FD; break;
        default: p = b2; n = ED; break;
    }
    float s = 0.0f;
    for (int i = threadIdx.x; i < n; i += 256) { float x = p[i]; s += x * x; }
    s = blockSumF<256>(s);
    if (threadIdx.x == 0) out[blockIdx.x] = s;
}

// ---------------- split all 6 weights into concat hi/lo ----------------
__global__ void split_all(const float* Wq, const float* Wk, const float* Wv,
                          const float* Wo, const float* W1, const float* W2,
                          __nv_bfloat16* __restrict__ h, __nv_bfloat16* __restrict__ l) {
    const float* src; size_t off; int n4;
    switch (blockIdx.y) {
        case 0: src = Wq; off = WQ0; n4 = 65536;  break;
        case 1: src = Wk; off = WK0; n4 = 65536;  break;
        case 2: src = Wv; off = WV0; n4 = 65536;  break;
        case 3: src = Wo; off = WO0; n4 = 65536;  break;
        case 4: src = W1; off = W10; n4 = 262144; break;
        default: src = W2; off = W20; n4 = 262144; break;
    }
    int i = blockIdx.x * 256 + threadIdx.x;
    if (i < n4) {
        float4 v = ((const float4*)src)[i];
        __nv_bfloat16 h0,l0,h1,l1,h2,l2,h3,l3;
        split1(v.x, h0, l0); split1(v.y, h1, l1);
        split1(v.z, h2, l2); split1(v.w, h3, l3);
        __nv_bfloat162* hp = (__nv_bfloat162*)(h + off);
        __nv_bfloat162* lp = (__nv_bfloat162*)(l + off);
        hp[i*2]   = __nv_bfloat162(h0, h1);
        hp[i*2+1] = __nv_bfloat162(h2, h3);
        lp[i*2]   = __nv_bfloat162(l0, l1);
        lp[i*2+1] = __nv_bfloat162(l2, l3);
    }
}

// vector helpers
#define VOP4(dst, ex, ey, ez, ew) do { dst.x=(ex); dst.y=(ey); dst.z=(ez); dst.w=(ew); } while(0)
__device__ __forceinline__ float dot4(float4 a, float4 b) { return a.x*b.x + a.y*b.y + a.z*b.z + a.w*b.w; }
__device__ __forceinline__ float sq4(float4 a) { return dot4(a, a); }
__device__ __forceinline__ float4 scl4(float4 a, float s) { float4 r; VOP4(r, a.x*s, a.y*s, a.z*s, a.w*s); return r; }

__device__ __forceinline__ void write_split4(float4 v, __nv_bfloat16* oh, __nv_bfloat16* ol, int idx2) {
    __nv_bfloat16 h0,l0,h1,l1,h2,l2,h3,l3;
    split1(v.x,h0,l0); split1(v.y,h1,l1); split1(v.z,h2,l2); split1(v.w,h3,l3);
    ((__nv_bfloat162*)oh)[idx2]   = __nv_bfloat162(h0,h1);
    ((__nv_bfloat162*)oh)[idx2+1] = __nv_bfloat162(h2,h3);
    ((__nv_bfloat162*)ol)[idx2]   = __nv_bfloat162(l0,l1);
    ((__nv_bfloat162*)ol)[idx2+1] = __nv_bfloat162(l2,l3);
}

// ---------------- ln block (used for ln1) ----------------
template <int E, int T>
__global__ void __launch_bounds__(T) ln_kernel(
    const float* __restrict__ x, const float* __restrict__ g, const float* __restrict__ b,
    float* __restrict__ outf, __nv_bfloat16* __restrict__ oh, __nv_bfloat16* __restrict__ ol,
    float* __restrict__ out_norm, int do_projx)
{
    constexpr int V4 = E / (T * 4);
    const size_t row = blockIdx.x;
    const int tid = threadIdx.x;
    const float MAXN = maxnorm();
    const float4* xp = (const float4*)(x + row * E);
    const float4* gp = (const float4*)g;
    const float4* bp = (const float4*)b;
    float4 v[V4];
    float ss = 0.0f;
    #pragma unroll
    for (int i = 0; i < V4; i++) { v[i] = xp[tid*V4 + i]; ss += sq4(v[i]); }
    float n0 = sqrtf(blockSumF<T>(ss) + 1e-30f);
    float lf = atanhf(fminf(n0, MAXN)) / n0;
    float sm = 0.0f;
    #pragma unroll
    for (int i = 0; i < V4; i++) { v[i] = scl4(v[i], lf); sm += v[i].x + v[i].y + v[i].z + v[i].w; }
    float mu = blockSumF<T>(sm) * (1.0f / E);
    float vv = 0.0f;
    #pragma unroll
    for (int i = 0; i < V4; i++) {
        float4 d; VOP4(d, v[i].x-mu, v[i].y-mu, v[i].z-mu, v[i].w-mu);
        vv += sq4(d);
    }
    float var = blockSumF<T>(vv) * (1.0f / E);
    float inv = rsqrtf(var + 1e-5f);
    float s2 = 0.0f;
    #pragma unroll
    for (int i = 0; i < V4; i++) {
        float4 gg = gp[tid*V4 + i], bb = bp[tid*V4 + i];
        VOP4(v[i], (v[i].x-mu)*inv*gg.x + bb.x, (v[i].y-mu)*inv*gg.y + bb.y,
                   (v[i].z-mu)*inv*gg.z + bb.z, (v[i].w-mu)*inv*gg.w + bb.w);
        s2 += sq4(v[i]);
    }
    float ny = sqrtf(blockSumF<T>(s2) + 1e-30f);
    float ef = tanhf(ny) / ny;
    #pragma unroll
    for (int i = 0; i < V4; i++) v[i] = scl4(v[i], ef);
    if (do_projx) {
        float s3 = 0.0f;
        #pragma unroll
        for (int i = 0; i < V4; i++) s3 += sq4(v[i]);
        float n = sqrtf(blockSumF<T>(s3) + 1e-30f);
        if (n > MAXN) { float ps = MAXN / n;
            #pragma unroll
            for (int i = 0; i < V4; i++) v[i] = scl4(v[i], ps); }
    }
    float s4 = 0.0f;
    #pragma unroll
    for (int i = 0; i < V4; i++) {
        if (outf) ((float4*)(outf + row*E))[tid*V4 + i] = v[i];
        if (oh) write_split4(v[i], oh + row*E, ol + row*E, tid*V4*2 + i*2);
        s4 += sq4(v[i]);
    }
    float nf = sqrtf(blockSumF<T>(s4) + 1e-30f);
    if (tid == 0) out_norm[row] = nf;
}

// ---------------- expmap0 rows -> bf16 split + norm ----------------
template <int E, int T>
__global__ void __launch_bounds__(T) expmap_rows(
    const float* __restrict__ x, __nv_bfloat16* __restrict__ oh, __nv_bfloat16* __restrict__ ol,
    float* __restrict__ out_norm)
{
    constexpr int V4 = E / (T * 4);
    const size_t row = blockIdx.x;
    const int tid = threadIdx.x;
    const float4* xp = (const float4*)(x + row * E);
    float4 v[V4];
    float ss = 0.0f;
    #pragma unroll
    for (int i = 0; i < V4; i++) { v[i] = xp[tid*V4 + i]; ss += sq4(v[i]); }
    float n = sqrtf(blockSumF<T>(ss) + 1e-30f);
    float ef = tanhf(n) / n;
    float s2 = 0.0f;
    #pragma unroll
    for (int i = 0; i < V4; i++) {
        v[i] = scl4(v[i], ef);
        write_split4(v[i], oh + row*E, ol + row*E, tid*V4*2 + i*2);
        s2 += sq4(v[i]);
    }
    float nf = sqrtf(blockSumF<T>(s2) + 1e-30f);
    if (tid == 0) out_norm[row] = nf;
}

// ---------------- fused q/k/v manifold epilogue -> bf16 hi/lo (stride QKVW) ----------------
__global__ void __launch_bounds__(128) manlin_qkv(
    const float* __restrict__ qkvf, const float* __restrict__ xnb,
    const float* __restrict__ bq, const float* __restrict__ bk, const float* __restrict__ bv,
    __nv_bfloat16* __restrict__ oh, __nv_bfloat16* __restrict__ ol)
{
    const size_t row = blockIdx.x;
    const int seg = blockIdx.y;
    const int tid = threadIdx.x;
    const float MAXN = maxnorm();
    const float* bias = (seg == 0) ? bq : (seg == 1) ? bk : bv;
    const float* base = qkvf + row * (size_t)QKVW + seg * 512;
    float4 v = ((const float4*)base)[tid];
    float4 bvv = ((const float4*)bias)[tid];
    float mxn = sqrtf(blockSumF<128>(sq4(v)) + 1e-30f);
    float xn = xnb[row];
    float s = tanhf(mxn / xn * atanhf(fminf(xn, MAXN))) / mxn;
    v = scl4(v, s);
    float xy = blockSumF<128>(dot4(v, bvv));
    float x2 = blockSumF<128>(sq4(v));
    float y2 = g_b2[seg];
    float a = 1.0f + 2.0f*xy + y2;
    float c = 1.0f - x2;
    float invd = 1.0f / fmaxf(1.0f + 2.0f*xy + x2*y2, 1e-15f);
    VOP4(v, (a*v.x + c*bvv.x)*invd, (a*v.y + c*bvv.y)*invd,
            (a*v.z + c*bvv.z)*invd, (a*v.w + c*bvv.w)*invd);
    float zn = sqrtf(blockSumF<128>(sq4(v)) + 1e-30f);
    if (zn > MAXN) v = scl4(v, MAXN / zn);
    float n = sqrtf(blockSumF<128>(sq4(v)) + 1e-30f);
    float lf = atanhf(fminf(n, MAXN)) / n;
    v = scl4(v, lf);
    size_t ob = row * (size_t)QKVW + seg * 512;
    write_split4(v, oh + ob, ol + ob, tid*2);
}

// ---------------- man_linear epilogue (general) ----------------
template <int E, int T>
__global__ void __launch_bounds__(T) manlin_epi(
    const float* __restrict__ mx, int ldm, const float* __restrict__ xnb,
    const float* __restrict__ bias, int b2idx,
    const float* __restrict__ resid,
    float* __restrict__ outf, __nv_bfloat16* __restrict__ oh, __nv_bfloat16* __restrict__ ol,
    float* __restrict__ out_norm, int flags)
{
    constexpr int V4 = E / (T * 4);
    const size_t row = blockIdx.x;
    const int tid = threadIdx.x;
    const float MAXN = maxnorm();
    const float4* mp = (const float4*)(mx + row*(size_t)ldm);
    const float4* bp = (const float4*)bias;
    float4 v[V4], bv[V4];
    float ss = 0.0f;
    #pragma unroll
    for (int i = 0; i < V4; i++) { v[i] = mp[tid*V4 + i]; ss += sq4(v[i]); }
    float mxn = sqrtf(blockSumF<T>(ss) + 1e-30f);
    float xn = xnb[row];
    float s = tanhf(mxn / xn * atanhf(fminf(xn, MAXN))) / mxn;
    float dxy = 0.0f, dx2 = 0.0f;
    #pragma unroll
    for (int i = 0; i < V4; i++) {
        v[i] = scl4(v[i], s);
        bv[i] = bp[tid*V4 + i];
        dxy += dot4(v[i], bv[i]);
        dx2 += sq4(v[i]);
    }
    float xy = blockSumF<T>(dxy);
    float x2 = blockSumF<T>(dx2);
    float y2 = g_b2[b2idx];
    float a = 1.0f + 2.0f*xy + y2;
    float c = 1.0f - x2;
    float den = fmaxf(1.0f + 2.0f*xy + x2*y2, 1e-15f);
    float invd = 1.0f / den;
    float zz = 0.0f;
    #pragma unroll
    for (int i = 0; i < V4; i++) {
        VOP4(v[i], (a*v[i].x + c*bv[i].x)*invd, (a*v[i].y + c*bv[i].y)*invd,
                   (a*v[i].z + c*bv[i].z)*invd, (a*v[i].w + c*bv[i].w)*invd);
        zz += sq4(v[i]);
    }
    {
        float zn = sqrtf(blockSumF<T>(zz) + 1e-30f);
        if (zn > MAXN) { float ps = MAXN / zn;
            #pragma unroll
            for (int i = 0; i < V4; i++) v[i] = scl4(v[i], ps); }
    }
    if (flags & FLAG_MOBRELU) {
        float s0 = 0.0f;
        #pragma unroll
        for (int i = 0; i < V4; i++) s0 += sq4(v[i]);
        float n = sqrtf(blockSumF<T>(s0) + 1e-30f);
        float lf = atanhf(fminf(n, MAXN)) / n;
        float s1 = 0.0f;
        #pragma unroll
        for (int i = 0; i < V4; i++) {
            VOP4(v[i], fmaxf(lf*v[i].x, 0.0f), fmaxf(lf*v[i].y, 0.0f),
                       fmaxf(lf*v[i].z, 0.0f), fmaxf(lf*v[i].w, 0.0f));
            s1 += sq4(v[i]);
        }
        float nr = sqrtf(blockSumF<T>(s1) + 1e-30f);
        float ef = tanhf(nr) / nr;
        float s2 = 0.0f;
        #pragma unroll
        for (int i = 0; i < V4; i++) { v[i] = scl4(v[i], ef); s2 += sq4(v[i]); }
        float n2 = sqrtf(blockSumF<T>(s2) + 1e-30f);
        if (n2 > MAXN) { float ps = MAXN / n2;
            #pragma unroll
            for (int i = 0; i < V4; i++) v[i] = scl4(v[i], ps); }
    }
    if (flags & FLAG_RESID) {
        const float4* rp = (const float4*)(resid + row*E);
        float4 rv[V4];
        float d1 = 0.0f, d2 = 0.0f, d3 = 0.0f;
        #pragma unroll
        for (int i = 0; i < V4; i++) {
            rv[i] = rp[tid*V4 + i];
            d1 += dot4(v[i], rv[i]);
            d2 += sq4(rv[i]);
            d3 += sq4(v[i]);
        }
        float rxy = blockSumF<T>(d1);
        float ry2 = blockSumF<T>(d2);
        float rx2 = blockSumF<T>(d3);
        float ra = 1.0f + 2.0f*rxy + ry2;
        float rc = 1.0f - rx2;
        float rden = fmaxf(1.0f + 2.0f*rxy + rx2*ry2, 1e-15f);
        float rinv = 1.0f / rden;
        float s3 = 0.0f;
        #pragma unroll
        for (int i = 0; i < V4; i++) {
            VOP4(v[i], (ra*v[i].x + rc*rv[i].x)*rinv, (ra*v[i].y + rc*rv[i].y)*rinv,
                       (ra*v[i].z + rc*rv[i].z)*rinv, (ra*v[i].w + rc*rv[i].w)*rinv);
            s3 += sq4(v[i]);
        }
        float zn = sqrtf(blockSumF<T>(s3) + 1e-30f);
        if (zn > MAXN) { float ps = MAXN / zn;
            #pragma unroll
            for (int i = 0; i < V4; i++) v[i] = scl4(v[i], ps); }
    }
    if (flags & FLAG_LOGMAP) {
        float s4 = 0.0f;
        #pragma unroll
        for (int i = 0; i < V4; i++) s4 += sq4(v[i]);
        float n = sqrtf(blockSumF<T>(s4) + 1e-30f);
        float lf = atanhf(fminf(n, MAXN)) / n;
        #pragma unroll
        for (int i = 0; i < V4; i++) v[i] = scl4(v[i], lf);
    }
    float s5 = 0.0f;
    #pragma unroll
    for (int i = 0; i < V4; i++) {
        if (outf) ((float4*)(outf + row*(size_t)ldm))[tid*V4 + i] = v[i];
        if (oh) write_split4(v[i], oh + row*E, ol + row*E, tid*V4*2 + i*2);
        s5 += sq4(v[i]);
    }
    if (out_norm) {
        float nf = sqrtf(blockSumF<T>(s5) + 1e-30f);
        if (tid == 0) out_norm[row] = nf;
    }
}

// ---------------- fused: manlin(Wo)+residual möbius  ->  ln2 -> bf16 splits ----------------
__global__ void __launch_bounds__(128) manlin_ln(
    const float* __restrict__ mx, const float* __restrict__ xnb,
    const float* __restrict__ bias, int b2idx, const float* __restrict__ resid,
    float* __restrict__ h1out,
    const float* __restrict__ g, const float* __restrict__ bln,
    __nv_bfloat16* __restrict__ oh, __nv_bfloat16* __restrict__ ol,
    float* __restrict__ out_norm)
{
    const size_t row = blockIdx.x;
    const int tid = threadIdx.x;
    const float MAXN = maxnorm();
    float4 v = ((const float4*)(mx + row*ED))[tid];
    float4 bvv = ((const float4*)bias)[tid];
    // man_linear
    float mxn = sqrtf(blockSumF<128>(sq4(v)) + 1e-30f);
    float xn = xnb[row];
    float s = tanhf(mxn / xn * atanhf(fminf(xn, MAXN))) / mxn;
    v = scl4(v, s);
    float xy = blockSumF<128>(dot4(v, bvv));
    float x2 = blockSumF<128>(sq4(v));
    float y2 = g_b2[b2idx];
    float a = 1.0f + 2.0f*xy + y2;
    float c = 1.0f - x2;
    float invd = 1.0f / fmaxf(1.0f + 2.0f*xy + x2*y2, 1e-15f);
    VOP4(v, (a*v.x + c*bvv.x)*invd, (a*v.y + c*bvv.y)*invd,
            (a*v.z + c*bvv.z)*invd, (a*v.w + c*bvv.w)*invd);
    {
        float zn = sqrtf(blockSumF<128>(sq4(v)) + 1e-30f);
        if (zn > MAXN) v = scl4(v, MAXN / zn);
    }
    // residual möbius add + projx
    {
        float4 rv = ((const float4*)(resid + row*ED))[tid];
        float rxy = blockSumF<128>(dot4(v, rv));
        float ry2 = blockSumF<128>(sq4(rv));
        float rx2 = blockSumF<128>(sq4(v));
        float ra = 1.0f + 2.0f*rxy + ry2;
        float rc = 1.0f - rx2;
        float rinv = 1.0f / fmaxf(1.0f + 2.0f*rxy + rx2*ry2, 1e-15f);
        VOP4(v, (ra*v.x + rc*rv.x)*rinv, (ra*v.y + rc*rv.y)*rinv,
                (ra*v.z + rc*rv.z)*rinv, (ra*v.w + rc*rv.w)*rinv);
        float zn = sqrtf(blockSumF<128>(sq4(v)) + 1e-30f);
        if (zn > MAXN) v = scl4(v, MAXN / zn);
    }
    // h1 written for the final residual
    ((float4*)(h1out + row*ED))[tid] = v;
    // ln2: logmap0 -> layernorm -> expmap0 -> projx
    float n0 = sqrtf(blockSumF<128>(sq4(v)) + 1e-30f);
    float lf = atanhf(fminf(n0, MAXN)) / n0;
    v = scl4(v, lf);
    float mu = blockSumF<128>(v.x + v.y + v.z + v.w) * (1.0f / ED);
    float4 d; VOP4(d, v.x-mu, v.y-mu, v.z-mu, v.w-mu);
    float var = blockSumF<128>(sq4(d)) * (1.0f / ED);
    float inv = rsqrtf(var + 1e-5f);
    float4 gg = ((const float4*)g)[tid], bb = ((const float4*)bln)[tid];
    VOP4(v, (v.x-mu)*inv*gg.x + bb.x, (v.y-mu)*inv*gg.y + bb.y,
            (v.z-mu)*inv*gg.z + bb.z, (v.w-mu)*inv*gg.w + bb.w);
    float ny = sqrtf(blockSumF<128>(sq4(v)) + 1e-30f);
    float ef = tanhf(ny) / ny;
    v = scl4(v, ef);
    {
        float n = sqrtf(blockSumF<128>(sq4(v)) + 1e-30f);
        if (n > MAXN) v = scl4(v, MAXN / n);
    }
    float nf = sqrtf(blockSumF<128>(sq4(v)) + 1e-30f);
    write_split4(v, oh + row*ED, ol + row*ED, tid*2);
    if (tid == 0) out_norm[row] = nf;
}

// ---------------- MMA helpers ----------------
__device__ __forceinline__ void ldsm_x4(uint32_t &r0, uint32_t &r1, uint32_t &r2, uint32_t &r3, uint32_t addr) {
    asm volatile("ldmatrix.sync.aligned.m8n8.x4.shared.b16 {%0,%1,%2,%3}, [%4];"
                 : "=r"(r0), "=r"(r1), "=r"(r2), "=r"(r3) : "r"(addr));
}
__device__ __forceinline__ void ldsm_x4t(uint32_t &r0, uint32_t &r1, uint32_t &r2, uint32_t &r3, uint32_t addr) {
    asm volatile("ldmatrix.sync.aligned.m8n8.x4.trans.shared.b16 {%0,%1,%2,%3}, [%4];"
                 : "=r"(r0), "=r"(r1), "=r"(r2), "=r"(r3) : "r"(addr));
}
__device__ __forceinline__ void mma16816(float* c, const uint32_t* a, const uint32_t* b) {
    asm volatile("mma.sync.aligned.m16n8k16.row.col.f32.bf16.bf16.f32 "
                 "{%0,%1,%2,%3}, {%4,%5,%6,%7}, {%8,%9}, {%0,%1,%2,%3};"
                 : "+f"(c[0]), "+f"(c[1]), "+f"(c[2]), "+f"(c[3])
                 : "r"(a[0]), "r"(a[1]), "r"(a[2]), "r"(a[3]), "r"(b[0]), "r"(b[1]));
}
#define CP_ASYNC16(dst, src) asm volatile("cp.async.cg.shared.global [%0], [%1], 16;" :: "r"(dst), "l"(src))

// ---------------- tensor-core attention ----------------
#define ATT_SMEM 98304
__global__ void __launch_bounds__(256) attn_mma(
    const __nv_bfloat16* __restrict__ qh_g, const __nv_bfloat16* __restrict__ ql_g,
    float* __restrict__ o)
{
    extern __shared__ __nv_bfloat16 smbuf[];
    uint32_t smb = (uint32_t)__cvta_generic_to_shared(smbuf);
    const int tid = threadIdx.x;
    const int lane = tid & 31, w = tid >> 5;
    const int bh = blockIdx.x, b = bh >> 3, h = bh & 7;

    #pragma unroll
    for (int it = 0; it < 24; it++) {
        int idx = tid + (it << 8);
        int tensor = idx >> 10;
        int cid = idx & 1023;
        int r = cid >> 3, c = cid & 7;
        uint32_t dst = smb + tensor*16384 + r*128 + ((c ^ (r & 7)) << 4);
        const __nv_bfloat16* P = (tensor & 1) ? ql_g : qh_g;
        const __nv_bfloat16* src = P + ((size_t)r*BB + b)*QKVW + (size_t)(tensor>>1)*512 + h*HD + c*8;
        CP_ASYNC16(dst, src);
    }
    asm volatile("cp.async.commit_group;");
    asm volatile("cp.async.wait_group 0;");
    __syncthreads();

    const int quad = lane >> 3, r8 = lane & 7;

    // phase 1: scores (K loads merged to x4: two n-tiles per ldmatrix)
    float sc[16][4];
    #pragma unroll
    for (int n = 0; n < 16; n++)
        #pragma unroll
        for (int e = 0; e < 4; e++) sc[n][e] = 0.0f;

    #pragma unroll
    for (int kk = 0; kk < 4; kk++) {
        uint32_t qh_[4], ql_[4];
        int arow = w*16 + (quad & 1)*8 + r8;
        int achk = kk*2 + (quad >> 1);
        uint32_t aoff = (uint32_t)(arow*128 + ((achk ^ (arow & 7)) << 4));
        ldsm_x4(qh_[0], qh_[1], qh_[2], qh_[3], smb + aoff);
        ldsm_x4(ql_[0], ql_[1], ql_[2], ql_[3], smb + 16384 + aoff);
        #pragma unroll
        for (int nn = 0; nn < 8; nn++) {
            int krow = nn*16 + (quad >> 1)*8 + r8;
            int kchk = kk*2 + (quad & 1);
            uint32_t koff = (uint32_t)(krow*128 + ((kchk ^ (krow & 7)) << 4));
            uint32_t kh0[2], kh1[2], kl0[2], kl1[2];
            { uint32_t a0,a1,a2,a3; ldsm_x4(a0,a1,a2,a3, smb + 32768 + koff);
              kh0[0]=a0; kh0[1]=a1; kh1[0]=a2; kh1[1]=a3; }
            { uint32_t a0,a1,a2,a3; ldsm_x4(a0,a1,a2,a3, smb + 49152 + koff);
              kl0[0]=a0; kl0[1]=a1; kl1[0]=a2; kl1[1]=a3; }
            mma16816(sc[2*nn],   qh_, kh0);
            mma16816(sc[2*nn],   qh_, kl0);
            mma16816(sc[2*nn],   ql_, kh0);
            mma16816(sc[2*nn+1], qh_, kh1);
            mma16816(sc[2*nn+1], qh_, kl1);
            mma16816(sc[2*nn+1], ql_, kh1);
        }
    }

    // phase 2: softmax
    float m0 = -1e30f, m1 = -1e30f;
    #pragma unroll
    for (int n = 0; n < 16; n++) {
        m0 = fmaxf(m0, fmaxf(sc[n][0], sc[n][1]));
        m1 = fmaxf(m1, fmaxf(sc[n][2], sc[n][3]));
    }
    m0 = fmaxf(m0, __shfl_xor_sync(0xffffffffu, m0, 1));
    m0 = fmaxf(m0, __shfl_xor_sync(0xffffffffu, m0, 2));
    m1 = fmaxf(m1, __shfl_xor_sync(0xffffffffu, m1, 1));
    m1 = fmaxf(m1, __shfl_xor_sync(0xffffffffu, m1, 2));
    float l0 = 0.0f, l1 = 0.0f;
    #pragma unroll
    for (int n = 0; n < 16; n++) {
        sc[n][0] = fexp((sc[n][0] - m0) * 0.125f); l0 += sc[n][0];
        sc[n][1] = fexp((sc[n][1] - m0) * 0.125f); l0 += sc[n][1];
        sc[n][2] = fexp((sc[n][2] - m1) * 0.125f); l1 += sc[n][2];
        sc[n][3] = fexp((sc[n][3] - m1) * 0.125f); l1 += sc[n][3];
    }
    l0 += __shfl_xor_sync(0xffffffffu, l0, 1);
    l0 += __shfl_xor_sync(0xffffffffu, l0, 2);
    l1 += __shfl_xor_sync(0xffffffffu, l1, 1);
    l1 += __shfl_xor_sync(0xffffffffu, l1, 2);
    float inv0 = 1.0f / l0, inv1 = 1.0f / l1;

    // phase 3: O = P @ V (V loads merged to x4.trans: two dim-tiles per ldmatrix)
    float oa[8][4];
    #pragma unroll
    for (int n = 0; n < 8; n++)
        #pragma unroll
        for (int e = 0; e < 4; e++) oa[n][e] = 0.0f;

    #pragma unroll
    for (int kt = 0; kt < 8; kt++) {
        uint32_t ph[4], pl[4];
        #pragma unroll
        for (int half = 0; half < 2; half++) {
            int n2 = 2*kt + half;
            float p0 = sc[n2][0], p1 = sc[n2][1], p2 = sc[n2][2], p3 = sc[n2][3];
            __nv_bfloat16 b0 = __float2bfloat16(p0), b1 = __float2bfloat16(p1);
            __nv_bfloat16 b2 = __float2bfloat16(p2), b3 = __float2bfloat16(p3);
            ph[half*2+0] = pack_bf2(p0, p1);
            ph[half*2+1] = pack_bf2(p2, p3);
            pl[half*2+0] = pack_bf2(p0 - __bfloat162float(b0), p1 - __bfloat162float(b1));
            pl[half*2+1] = pack_bf2(p2 - __bfloat162float(b2), p3 - __bfloat162float(b3));
        }
        #pragma unroll
        for (int nn = 0; nn < 4; nn++) {
            int vrow = kt*16 + (quad & 1)*8 + r8;
            int vchk = 2*nn + (quad >> 1);
            uint32_t voff = (uint32_t)(vrow*128 + ((vchk ^ (vrow & 7)) << 4));
            uint32_t vh0[2], vh1[2], vl0[2], vl1[2];
            { uint32_t a0,a1,a2,a3; ldsm_x4t(a0,a1,a2,a3, smb + 65536 + voff);
              vh0[0]=a0; vh0[1]=a1; vh1[0]=a2; vh1[1]=a3; }
            { uint32_t a0,a1,a2,a3; ldsm_x4t(a0,a1,a2,a3, smb + 81920 + voff);
              vl0[0]=a0; vl0[1]=a1; vl1[0]=a2; vl1[1]=a3; }
            mma16816(oa[2*nn],   ph, vh0);
            mma16816(oa[2*nn],   ph, vl0);
            mma16816(oa[2*nn],   pl, vh0);
            mma16816(oa[2*nn+1], ph, vh1);
            mma16816(oa[2*nn+1], ph, vl1);
            mma16816(oa[2*nn+1], pl, vh1);
        }
    }

    // phase 4: write
    int g = lane >> 2, t2 = (lane & 3) * 2;
    int t0 = w*16 + g;
    #pragma unroll
    for (int n = 0; n < 8; n++) {
        size_t base0 = ((size_t)t0*BB + b)*ED + (size_t)h*HD + n*8 + t2;
        size_t base1 = ((size_t)(t0+8)*BB + b)*ED + (size_t)h*HD + n*8 + t2;
        *(float2*)(o + base0) = make_float2(oa[n][0]*inv0, oa[n][1]*inv0);
        *(float2*)(o + base1) = make_float2(oa[n][2]*inv1, oa[n][3]*inv1);
    }
}

// ================= bf16x3 HMMA GEMM: 3-stage, 64B swizzled rows, B via x4 =================
#define BM 128
#define BN 128
#define BK 32
#define TEN_B   8192
#define STAGE_B (4*TEN_B)
#define GEMM_SMEM (3*STAGE_B)

__device__ __forceinline__ uint32_t saddr(int r, int colElem) {
    return (uint32_t)(r*64 + ((((colElem >> 3) ^ ((r >> 1) & 3))) << 4));
}

__global__ void __launch_bounds__(256, 2) gemm_bf16x3(
    const __nv_bfloat16* __restrict__ Ah, const __nv_bfloat16* __restrict__ Al,
    const __nv_bfloat16* __restrict__ Wh, const __nv_bfloat16* __restrict__ Wl,
    float* __restrict__ C, int M, int N, int K)
{
    extern __shared__ __nv_bfloat16 smbuf[];
    const int tid = threadIdx.x;
    const int lane = tid & 31, w = tid >> 5;
    const int wm = w & 1, wn = w >> 1;
    const int rowBase = blockIdx.y * BM;
    const int colBase = blockIdx.x * BN;
    uint32_t smbase = (uint32_t)__cvta_generic_to_shared(smbuf);

    float acc[4][4][4];
    #pragma unroll
    for (int i = 0; i < 4; i++)
        #pragma unroll
        for (int j = 0; j < 4; j++)
            #pragma unroll
            for (int e = 0; e < 4; e++) acc[i][j][e] = 0.0f;

    auto load_stage = [&](int st, int k0) {
        uint32_t base = smbase + st * STAGE_B;
        #pragma unroll
        for (int it = 0; it < 8; it++) {
            int idx = tid + (it << 8);
            int tensor = idx >> 9;
            int cid = idx & 511;
            int r = cid >> 2, c = cid & 3;
            uint32_t dst = base + tensor * TEN_B
                         + (uint32_t)(r*64 + ((c ^ ((r >> 1) & 3)) << 4));
            const __nv_bfloat16* src;
            if (tensor == 0)      src = Ah + (size_t)(rowBase + r) * K + k0 + c * 8;
            else if (tensor == 1) src = Al + (size_t)(rowBase + r) * K + k0 + c * 8;
            else if (tensor == 2) src = Wh + (size_t)(colBase + r) * K + k0 + c * 8;
            else                  src = Wl + (size_t)(colBase + r) * K + k0 + c * 8;
            CP_ASYNC16(dst, src);
        }
        asm volatile("cp.async.commit_group;");
    };

    auto compute_stage = [&](int st) {
        uint32_t base = smbase + st * STAGE_B;
        uint32_t aH = base;
        uint32_t aL = base + 1*TEN_B;
        uint32_t wH = base + 2*TEN_B;
        uint32_t wL = base + 3*TEN_B;
        const int quad = lane >> 3, r8 = lane & 7;
        #pragma unroll
        for (int kk = 0; kk < BK; kk += 16) {
            uint32_t ah[4][4], al[4][4], bh[4][2], bl[4][2];
            #pragma unroll
            for (int i = 0; i < 4; i++) {
                int row = wm*64 + i*16 + (quad & 1)*8 + r8;
                int col = kk + (quad >> 1)*8;
                uint32_t off = saddr(row, col);
                ldsm_x4(ah[i][0], ah[i][1], ah[i][2], ah[i][3], aH + off);
                ldsm_x4(al[i][0], al[i][1], al[i][2], al[i][3], aL + off);
            }
            #pragma unroll
            for (int jj = 0; jj < 2; jj++) {
                int nr = wn*32 + jj*16 + (quad >> 1)*8 + r8;
                int kc = kk + (quad & 1)*8;
                uint32_t off = saddr(nr, kc);
                uint32_t a0,a1,a2,a3;
                ldsm_x4(a0,a1,a2,a3, wH + off);
                bh[2*jj][0]=a0; bh[2*jj][1]=a1; bh[2*jj+1][0]=a2; bh[2*jj+1][1]=a3;
                ldsm_x4(a0,a1,a2,a3, wL + off);
                bl[2*jj][0]=a0; bl[2*jj][1]=a1; bl[2*jj+1][0]=a2; bl[2*jj+1][1]=a3;
            }
            #pragma unroll
            for (int i = 0; i < 4; i++)
                #pragma unroll
                for (int j = 0; j < 4; j++) mma16816(acc[i][j], ah[i], bh[j]);
            #pragma unroll
            for (int i = 0; i < 4; i++)
                #pragma unroll
                for (int j = 0; j < 4; j++) mma16816(acc[i][j], ah[i], bl[j]);
            #pragma unroll
            for (int i = 0; i < 4; i++)
                #pragma unroll
                for (int j = 0; j < 4; j++) mma16816(acc[i][j], al[i], bh[j]);
        }
    };

    const int nkb = K / BK;
    load_stage(0, 0);
    load_stage(1, BK);
    for (int kb = 0; kb < nkb; kb++) {
        if (kb == nkb - 1) { asm volatile("cp.async.wait_group 0;"); }
        else               { asm volatile("cp.async.wait_group 1;"); }
        __syncthreads();
        if (kb + 2 < nkb) load_stage((kb + 2) % 3, (kb + 2) * BK);
        compute_stage(kb % 3);
    }

    const int g = lane >> 2, tg = lane & 3;
    #pragma unroll
    for (int i = 0; i < 4; i++) {
        int row = rowBase + wm*64 + i*16 + g;
        #pragma unroll
        for (int j = 0; j < 4; j++) {
            int col = colBase + wn*32 + j*8 + tg*2;
            *(float2*)(C + (size_t)row * N + col)       = make_float2(acc[i][j][0], acc[i][j][1]);
            *(float2*)(C + (size_t)(row + 8) * N + col) = make_float2(acc[i][j][2], acc[i][j][3]);
        }
    }
}

// ---------------- launch ----------------
extern "C" void kernel_launch(void* const* d_in, const int* in_sizes, int n_in,
                              void* d_out, int out_size)
{
    const float* x    = (const float*)d_in[0];
    const float* l1g  = (const float*)d_in[1];
    const float* l1b  = (const float*)d_in[2];
    const float* l2g  = (const float*)d_in[3];
    const float* l2b  = (const float*)d_in[4];
    const float* Wq   = (const float*)d_in[5];
    const float* bq   = (const float*)d_in[6];
    const float* Wk   = (const float*)d_in[7];
    const float* bk   = (const float*)d_in[8];
    const float* Wv   = (const float*)d_in[9];
    const float* bv   = (const float*)d_in[10];
    const float* Wo   = (const float*)d_in[11];
    const float* bo   = (const float*)d_in[12];
    const float* W1   = (const float*)d_in[13];
    const float* b1   = (const float*)d_in[14];
    const float* W2   = (const float*)d_in[15];
    const float* b2   = (const float*)d_in[16];
    float* out = (float*)d_out;

    float *qkv, *ob, *h1, *big, *n0, *no, *nh2, *nh3, *bsq;
    __nv_bfloat16 *xh, *xl, *wh, *wl;
    cudaGetSymbolAddress((void**)&qkv, g_qkv);
    cudaGetSymbolAddress((void**)&ob,  g_o);
    cudaGetSymbolAddress((void**)&h1,  g_h1);
    cudaGetSymbolAddress((void**)&big, g_big);
    cudaGetSymbolAddress((void**)&xh,  g_xh);
    cudaGetSymbolAddress((void**)&xl,  g_xl);
    cudaGetSymbolAddress((void**)&wh,  g_wh);
    cudaGetSymbolAddress((void**)&wl,  g_wl);
    cudaGetSymbolAddress((void**)&n0,  g_n0);
    cudaGetSymbolAddress((void**)&no,  g_no);
    cudaGetSymbolAddress((void**)&nh2, g_nh2);
    cudaGetSymbolAddress((void**)&nh3, g_nh3);
    cudaGetSymbolAddress((void**)&bsq, g_b2);

    cudaFuncSetAttribute(gemm_bf16x3, cudaFuncAttributeMaxDynamicSharedMemorySize, GEMM_SMEM);
    cudaFuncSetAttribute(attn_mma, cudaFuncAttributeMaxDynamicSharedMemorySize, ATT_SMEM);

    split_all<<<dim3(1024, 6), 256>>>(Wq, Wk, Wv, Wo, W1, W2, wh, wl);
    sqsum6<<<6, 256>>>(bq, bk, bv, bo, b1, b2, bsq);
    ln_kernel<ED, 128><<<NR, 128>>>(x, l1g, l1b, nullptr, xh, xl, n0, 0);

    gemm_bf16x3<<<dim3(QKVW/BN, NR/BM), 256, GEMM_SMEM>>>(xh, xl, wh + WQ0, wl + WQ0, qkv, NR, QKVW, ED);
    manlin_qkv<<<dim3(NR, 3), 128>>>(qkv, n0, bq, bk, bv, xh, xl);

    attn_mma<<<BB * NH, 256, ATT_SMEM>>>(xh, xl, ob);
    expmap_rows<ED, 128><<<NR, 128>>>(ob, xh, xl, no);

    gemm_bf16x3<<<dim3(ED/BN, NR/BM), 256, GEMM_SMEM>>>(xh, xl, wh + WO0, wl + WO0, big, NR, ED, ED);
    // fused: manlin(Wo)+residual -> ln2 -> splits
    manlin_ln<<<NR, 128>>>(big, no, bo, 3, x, h1, l2g, l2b, xh, xl, nh2);

    gemm_bf16x3<<<dim3(FD/BN, NR/BM), 256, GEMM_SMEM>>>(xh, xl, wh + W10, wl + W10, big, NR, FD, ED);
    manlin_epi<FD, 256><<<NR, 256>>>(big, FD, nh2, b1, 4, nullptr, nullptr, xh, xl, nh3, FLAG_MOBRELU);

    gemm_bf16x3<<<dim3(ED/BN, NR/BM), 256, GEMM_SMEM>>>(xh, xl, wh + W20, wl + W20, qkv, NR, ED, FD);
    manlin_epi<ED, 128><<<NR, 128>>>(qkv, ED, nh3, b2, 5, h1, out, nullptr, nullptr, nullptr, FLAG_MOBRELU | FLAG_RESID);
}

// round 9
// speedup vs baseline: 8.9098x; 1.1291x over previous
#include <cuda_runtime.h>
#include <cuda_bf16.h>
#include <math.h>
#include <stdint.h>

// ---------------- problem constants ----------------
#define SEQ 128
#define BB  256
#define ED  512
#define FD  2048
#define NH  8
#define HD  64
#define NR  (SEQ*BB)   // 32768 rows
#define QKVW 1536      // fused qkv row width

static __device__ __forceinline__ float maxnorm() { return (float)(1.0 - 1e-5); }

// ---------------- scratch ----------------
__device__ float g_qkv[(size_t)NR*QKVW];
__device__ float g_o  [(size_t)NR*ED];
__device__ float g_h1 [(size_t)NR*ED];
__device__ float g_big[(size_t)NR*FD];
__device__ __nv_bfloat16 g_xh[(size_t)NR*FD];
__device__ __nv_bfloat16 g_xl[(size_t)NR*FD];
__device__ __nv_bfloat16 g_wh[(size_t)3*1024*1024];
__device__ __nv_bfloat16 g_wl[(size_t)3*1024*1024];
__device__ float g_n0 [NR];
__device__ float g_no [NR];
__device__ float g_nh2[NR];
__device__ float g_nh3[NR];
__device__ float g_b2 [8];

#define WQ0 0
#define WK0 262144
#define WV0 524288
#define WO0 786432
#define W10 1048576
#define W20 2097152

#define FLAG_LOGMAP  1
#define FLAG_MOBRELU 2
#define FLAG_RESID   4

// ---------------- reductions ----------------
template <int T>
__device__ __forceinline__ float blockSumF(float v) {
    __shared__ float sh[T / 32];
    #pragma unroll
    for (int o = 16; o > 0; o >>= 1) v += __shfl_xor_sync(0xffffffffu, v, o);
    int lane = threadIdx.x & 31, w = threadIdx.x >> 5;
    if (lane == 0) sh[w] = v;
    __syncthreads();
    if (threadIdx.x < 32) {
        float t = (threadIdx.x < T / 32) ? sh[threadIdx.x] : 0.0f;
        #pragma unroll
        for (int o = 16; o > 0; o >>= 1) t += __shfl_xor_sync(0xffffffffu, t, o);
        if (threadIdx.x == 0) sh[0] = t;
    }
    __syncthreads();
    float r = sh[0];
    __syncthreads();
    return r;
}
__device__ __forceinline__ float warpSumF(float v) {
    #pragma unroll
    for (int o = 16; o > 0; o >>= 1) v += __shfl_xor_sync(0xffffffffu, v, o);
    return v;
}

__device__ __forceinline__ void split1(float x, __nv_bfloat16 &h, __nv_bfloat16 &l) {
    h = __float2bfloat16(x);
    l = __float2bfloat16(x - __bfloat162float(h));
}
__device__ __forceinline__ uint32_t pack_bf2(float a, float b) {
    __nv_bfloat162 t(__float2bfloat16(a), __float2bfloat16(b));
    return *(uint32_t*)&t;
}

// FMA-pipe exp (no MUFU)
__device__ __forceinline__ float fexp(float x) {
    float y = x * 1.4426950408889634f;
    y = fmaxf(y, -126.0f);
    float fl = floorf(y);
    float f = y - fl;
    float p = 1.5252734e-5f;
    p = fmaf(p, f, 1.5403530e-4f);
    p = fmaf(p, f, 1.3333558e-3f);
    p = fmaf(p, f, 9.6181291e-3f);
    p = fmaf(p, f, 5.5504109e-2f);
    p = fmaf(p, f, 2.4022651e-1f);
    p = fmaf(p, f, 6.9314718e-1f);
    p = fmaf(p, f, 1.0f);
    return __int_as_float(__float_as_int(p) + (((int)fl) << 23));
}

// ---------------- all 6 bias squared-norms ----------------
__global__ void sqsum6(const float* bq, const float* bk, const float* bv,
                       const float* bo, const float* b1, const float* b2,
                       float* __restrict__ out) {
    const float* p;
    int n;
    switch (blockIdx.x) {
        case 0: p = bq; n = ED; break;
        case 1: p = bk; n = ED; break;
        case 2: p = bv; n = ED; break;
        case 3: p = bo; n = ED; break;
        case 4: p = b1; n = FD; break;
        default: p = b2; n = ED; break;
    }
    float s = 0.0f;
    for (int i = threadIdx.x; i < n; i += 256) { float x = p[i]; s += x * x; }
    s = blockSumF<256>(s);
    if (threadIdx.x == 0) out[blockIdx.x] = s;
}

// ---------------- split all 6 weights into concat hi/lo ----------------
__global__ void split_all(const float* Wq, const float* Wk, const float* Wv,
                          const float* Wo, const float* W1, const float* W2,
                          __nv_bfloat16* __restrict__ h, __nv_bfloat16* __restrict__ l) {
    const float* src; size_t off; int n4;
    switch (blockIdx.y) {
        case 0: src = Wq; off = WQ0; n4 = 65536;  break;
        case 1: src = Wk; off = WK0; n4 = 65536;  break;
        case 2: src = Wv; off = WV0; n4 = 65536;  break;
        case 3: src = Wo; off = WO0; n4 = 65536;  break;
        case 4: src = W1; off = W10; n4 = 262144; break;
        default: src = W2; off = W20; n4 = 262144; break;
    }
    int i = blockIdx.x * 256 + threadIdx.x;
    if (i < n4) {
        float4 v = ((const float4*)src)[i];
        __nv_bfloat16 h0,l0,h1,l1,h2,l2,h3,l3;
        split1(v.x, h0, l0); split1(v.y, h1, l1);
        split1(v.z, h2, l2); split1(v.w, h3, l3);
        __nv_bfloat162* hp = (__nv_bfloat162*)(h + off);
        __nv_bfloat162* lp = (__nv_bfloat162*)(l + off);
        hp[i*2]   = __nv_bfloat162(h0, h1);
        hp[i*2+1] = __nv_bfloat162(h2, h3);
        lp[i*2]   = __nv_bfloat162(l0, l1);
        lp[i*2+1] = __nv_bfloat162(l2, l3);
    }
}

// vector helpers
#define VOP4(dst, ex, ey, ez, ew) do { dst.x=(ex); dst.y=(ey); dst.z=(ez); dst.w=(ew); } while(0)
__device__ __forceinline__ float dot4(float4 a, float4 b) { return a.x*b.x + a.y*b.y + a.z*b.z + a.w*b.w; }
__device__ __forceinline__ float sq4(float4 a) { return dot4(a, a); }
__device__ __forceinline__ float4 scl4(float4 a, float s) { float4 r; VOP4(r, a.x*s, a.y*s, a.z*s, a.w*s); return r; }

__device__ __forceinline__ void write_split4(float4 v, __nv_bfloat16* oh, __nv_bfloat16* ol, int idx2) {
    __nv_bfloat16 h0,l0,h1,l1,h2,l2,h3,l3;
    split1(v.x,h0,l0); split1(v.y,h1,l1); split1(v.z,h2,l2); split1(v.w,h3,l3);
    ((__nv_bfloat162*)oh)[idx2]   = __nv_bfloat162(h0,h1);
    ((__nv_bfloat162*)oh)[idx2+1] = __nv_bfloat162(h2,h3);
    ((__nv_bfloat162*)ol)[idx2]   = __nv_bfloat162(l0,l1);
    ((__nv_bfloat162*)ol)[idx2+1] = __nv_bfloat162(l2,l3);
}

// ================= warp-per-row kernels (E=512, 16 floats/lane, no barriers) =================

// ---------------- ln1: expmap0(layernorm(logmap0(x))) -> bf16 splits + norm ----------------
__global__ void __launch_bounds__(256) ln1_w(
    const float* __restrict__ x, const float* __restrict__ g, const float* __restrict__ b,
    __nv_bfloat16* __restrict__ oh, __nv_bfloat16* __restrict__ ol,
    float* __restrict__ out_norm)
{
    const int lane = threadIdx.x & 31;
    const size_t row = blockIdx.x * 8 + (threadIdx.x >> 5);
    const float MAXN = maxnorm();
    const float4* xp = (const float4*)(x + row * ED);
    float4 v[4];
    float ss = 0.0f;
    #pragma unroll
    for (int i = 0; i < 4; i++) { v[i] = xp[lane + i*32]; ss += sq4(v[i]); }
    float n0 = sqrtf(warpSumF(ss) + 1e-30f);
    float lf = atanhf(fminf(n0, MAXN)) / n0;
    float sm = 0.0f;
    #pragma unroll
    for (int i = 0; i < 4; i++) { v[i] = scl4(v[i], lf); sm += v[i].x + v[i].y + v[i].z + v[i].w; }
    float mu = warpSumF(sm) * (1.0f / ED);
    float vv = 0.0f;
    #pragma unroll
    for (int i = 0; i < 4; i++) {
        float4 d; VOP4(d, v[i].x-mu, v[i].y-mu, v[i].z-mu, v[i].w-mu);
        vv += sq4(d);
    }
    float var = warpSumF(vv) * (1.0f / ED);
    float inv = rsqrtf(var + 1e-5f);
    float s2 = 0.0f;
    #pragma unroll
    for (int i = 0; i < 4; i++) {
        float4 gg = ((const float4*)g)[lane + i*32], bb = ((const float4*)b)[lane + i*32];
        VOP4(v[i], (v[i].x-mu)*inv*gg.x + bb.x, (v[i].y-mu)*inv*gg.y + bb.y,
                   (v[i].z-mu)*inv*gg.z + bb.z, (v[i].w-mu)*inv*gg.w + bb.w);
        s2 += sq4(v[i]);
    }
    float ny = sqrtf(warpSumF(s2) + 1e-30f);
    float ef = tanhf(ny) / ny;
    float s4 = 0.0f;
    #pragma unroll
    for (int i = 0; i < 4; i++) {
        v[i] = scl4(v[i], ef);
        write_split4(v[i], oh + row*ED, ol + row*ED, (lane + i*32)*2);
        s4 += sq4(v[i]);
    }
    float nf = sqrtf(warpSumF(s4) + 1e-30f);
    if (lane == 0) out_norm[row] = nf;
}

// ---------------- expmap0 rows -> bf16 splits + norm ----------------
__global__ void __launch_bounds__(256) expmap_w(
    const float* __restrict__ x, __nv_bfloat16* __restrict__ oh, __nv_bfloat16* __restrict__ ol,
    float* __restrict__ out_norm)
{
    const int lane = threadIdx.x & 31;
    const size_t row = blockIdx.x * 8 + (threadIdx.x >> 5);
    const float4* xp = (const float4*)(x + row * ED);
    float4 v[4];
    float ss = 0.0f;
    #pragma unroll
    for (int i = 0; i < 4; i++) { v[i] = xp[lane + i*32]; ss += sq4(v[i]); }
    float n = sqrtf(warpSumF(ss) + 1e-30f);
    float ef = tanhf(n) / n;
    float s2 = 0.0f;
    #pragma unroll
    for (int i = 0; i < 4; i++) {
        v[i] = scl4(v[i], ef);
        write_split4(v[i], oh + row*ED, ol + row*ED, (lane + i*32)*2);
        s2 += sq4(v[i]);
    }
    float nf = sqrtf(warpSumF(s2) + 1e-30f);
    if (lane == 0) out_norm[row] = nf;
}

// ---------------- q/k/v manifold epilogue -> bf16 splits (stride QKVW) ----------------
__global__ void __launch_bounds__(256) manlin_qkv_w(
    const float* __restrict__ qkvf, const float* __restrict__ xnb,
    const float* __restrict__ bq, const float* __restrict__ bk, const float* __restrict__ bv,
    __nv_bfloat16* __restrict__ oh, __nv_bfloat16* __restrict__ ol)
{
    const int lane = threadIdx.x & 31;
    const size_t row = blockIdx.x * 8 + (threadIdx.x >> 5);
    const int seg = blockIdx.y;
    const float MAXN = maxnorm();
    const float* bias = (seg == 0) ? bq : (seg == 1) ? bk : bv;
    const float4* base = (const float4*)(qkvf + row * (size_t)QKVW + seg * 512);
    float4 v[4], bvv[4];
    float ss = 0.0f;
    #pragma unroll
    for (int i = 0; i < 4; i++) {
        v[i] = base[lane + i*32];
        bvv[i] = ((const float4*)bias)[lane + i*32];
        ss += sq4(v[i]);
    }
    float mxn = sqrtf(warpSumF(ss) + 1e-30f);
    float xn = xnb[row];
    float s = tanhf(mxn / xn * atanhf(fminf(xn, MAXN))) / mxn;
    float dxy = 0.0f, dx2 = 0.0f;
    #pragma unroll
    for (int i = 0; i < 4; i++) {
        v[i] = scl4(v[i], s);
        dxy += dot4(v[i], bvv[i]);
        dx2 += sq4(v[i]);
    }
    float xy = warpSumF(dxy);
    float x2 = warpSumF(dx2);
    float y2 = g_b2[seg];
    float a = 1.0f + 2.0f*xy + y2;
    float c = 1.0f - x2;
    float invd = 1.0f / fmaxf(1.0f + 2.0f*xy + x2*y2, 1e-15f);
    float zz = 0.0f;
    #pragma unroll
    for (int i = 0; i < 4; i++) {
        VOP4(v[i], (a*v[i].x + c*bvv[i].x)*invd, (a*v[i].y + c*bvv[i].y)*invd,
                   (a*v[i].z + c*bvv[i].z)*invd, (a*v[i].w + c*bvv[i].w)*invd);
        zz += sq4(v[i]);
    }
    float zn = sqrtf(warpSumF(zz) + 1e-30f);
    if (zn > MAXN) {
        float ps = MAXN / zn;
        #pragma unroll
        for (int i = 0; i < 4; i++) v[i] = scl4(v[i], ps);
    }
    float s0 = 0.0f;
    #pragma unroll
    for (int i = 0; i < 4; i++) s0 += sq4(v[i]);
    float n = sqrtf(warpSumF(s0) + 1e-30f);
    float lf = atanhf(fminf(n, MAXN)) / n;
    size_t ob = row * (size_t)QKVW + seg * 512;
    #pragma unroll
    for (int i = 0; i < 4; i++) {
        v[i] = scl4(v[i], lf);
        write_split4(v[i], oh + ob, ol + ob, (lane + i*32)*2);
    }
}

// ---------------- fused: manlin(Wo)+residual -> ln2 -> splits ----------------
__global__ void __launch_bounds__(256) manlin_ln_w(
    const float* __restrict__ mx, const float* __restrict__ xnb,
    const float* __restrict__ bias, int b2idx, const float* __restrict__ resid,
    float* __restrict__ h1out,
    const float* __restrict__ g, const float* __restrict__ bln,
    __nv_bfloat16* __restrict__ oh, __nv_bfloat16* __restrict__ ol,
    float* __restrict__ out_norm)
{
    const int lane = threadIdx.x & 31;
    const size_t row = blockIdx.x * 8 + (threadIdx.x >> 5);
    const float MAXN = maxnorm();
    float4 v[4], bvv[4];
    float ss = 0.0f;
    #pragma unroll
    for (int i = 0; i < 4; i++) {
        v[i] = ((const float4*)(mx + row*ED))[lane + i*32];
        bvv[i] = ((const float4*)bias)[lane + i*32];
        ss += sq4(v[i]);
    }
    float mxn = sqrtf(warpSumF(ss) + 1e-30f);
    float xn = xnb[row];
    float s = tanhf(mxn / xn * atanhf(fminf(xn, MAXN))) / mxn;
    float dxy = 0.0f, dx2 = 0.0f;
    #pragma unroll
    for (int i = 0; i < 4; i++) {
        v[i] = scl4(v[i], s);
        dxy += dot4(v[i], bvv[i]);
        dx2 += sq4(v[i]);
    }
    float xy = warpSumF(dxy);
    float x2 = warpSumF(dx2);
    float y2 = g_b2[b2idx];
    float a = 1.0f + 2.0f*xy + y2;
    float c = 1.0f - x2;
    float invd = 1.0f / fmaxf(1.0f + 2.0f*xy + x2*y2, 1e-15f);
    float zz = 0.0f;
    #pragma unroll
    for (int i = 0; i < 4; i++) {
        VOP4(v[i], (a*v[i].x + c*bvv[i].x)*invd, (a*v[i].y + c*bvv[i].y)*invd,
                   (a*v[i].z + c*bvv[i].z)*invd, (a*v[i].w + c*bvv[i].w)*invd);
        zz += sq4(v[i]);
    }
    {
        float zn = sqrtf(warpSumF(zz) + 1e-30f);
        if (zn > MAXN) { float ps = MAXN / zn;
            #pragma unroll
            for (int i = 0; i < 4; i++) v[i] = scl4(v[i], ps); }
    }
    // residual möbius add + projx
    {
        float d1 = 0.0f, d2 = 0.0f, d3 = 0.0f;
        float4 rv[4];
        #pragma unroll
        for (int i = 0; i < 4; i++) {
            rv[i] = ((const float4*)(resid + row*ED))[lane + i*32];
            d1 += dot4(v[i], rv[i]);
            d2 += sq4(rv[i]);
            d3 += sq4(v[i]);
        }
        float rxy = warpSumF(d1);
        float ry2 = warpSumF(d2);
        float rx2 = warpSumF(d3);
        float ra = 1.0f + 2.0f*rxy + ry2;
        float rc = 1.0f - rx2;
        float rinv = 1.0f / fmaxf(1.0f + 2.0f*rxy + rx2*ry2, 1e-15f);
        float s3 = 0.0f;
        #pragma unroll
        for (int i = 0; i < 4; i++) {
            VOP4(v[i], (ra*v[i].x + rc*rv[i].x)*rinv, (ra*v[i].y + rc*rv[i].y)*rinv,
                       (ra*v[i].z + rc*rv[i].z)*rinv, (ra*v[i].w + rc*rv[i].w)*rinv);
            s3 += sq4(v[i]);
        }
        float zn = sqrtf(warpSumF(s3) + 1e-30f);
        if (zn > MAXN) { float ps = MAXN / zn;
            #pragma unroll
            for (int i = 0; i < 4; i++) v[i] = scl4(v[i], ps); }
    }
    // write h1 for the final residual
    #pragma unroll
    for (int i = 0; i < 4; i++) ((float4*)(h1out + row*ED))[lane + i*32] = v[i];
    // ln2
    float s0 = 0.0f;
    #pragma unroll
    for (int i = 0; i < 4; i++) s0 += sq4(v[i]);
    float n0 = sqrtf(warpSumF(s0) + 1e-30f);
    float lf = atanhf(fminf(n0, MAXN)) / n0;
    float sm = 0.0f;
    #pragma unroll
    for (int i = 0; i < 4; i++) { v[i] = scl4(v[i], lf); sm += v[i].x + v[i].y + v[i].z + v[i].w; }
    float mu = warpSumF(sm) * (1.0f / ED);
    float vv = 0.0f;
    #pragma unroll
    for (int i = 0; i < 4; i++) {
        float4 d; VOP4(d, v[i].x-mu, v[i].y-mu, v[i].z-mu, v[i].w-mu);
        vv += sq4(d);
    }
    float var = warpSumF(vv) * (1.0f / ED);
    float inv = rsqrtf(var + 1e-5f);
    float s2 = 0.0f;
    #pragma unroll
    for (int i = 0; i < 4; i++) {
        float4 gg = ((const float4*)g)[lane + i*32], bb = ((const float4*)bln)[lane + i*32];
        VOP4(v[i], (v[i].x-mu)*inv*gg.x + bb.x, (v[i].y-mu)*inv*gg.y + bb.y,
                   (v[i].z-mu)*inv*gg.z + bb.z, (v[i].w-mu)*inv*gg.w + bb.w);
        s2 += sq4(v[i]);
    }
    float ny = sqrtf(warpSumF(s2) + 1e-30f);
    float ef = tanhf(ny) / ny;
    #pragma unroll
    for (int i = 0; i < 4; i++) v[i] = scl4(v[i], ef);
    {
        float s3 = 0.0f;
        #pragma unroll
        for (int i = 0; i < 4; i++) s3 += sq4(v[i]);
        float n = sqrtf(warpSumF(s3) + 1e-30f);
        if (n > MAXN) { float ps = MAXN / n;
            #pragma unroll
            for (int i = 0; i < 4; i++) v[i] = scl4(v[i], ps); }
    }
    float s4 = 0.0f;
    #pragma unroll
    for (int i = 0; i < 4; i++) {
        write_split4(v[i], oh + row*ED, ol + row*ED, (lane + i*32)*2);
        s4 += sq4(v[i]);
    }
    float nf = sqrtf(warpSumF(s4) + 1e-30f);
    if (lane == 0) out_norm[row] = nf;
}

// ---------------- final: manlin(W2) + mob_relu + residual -> fp32 out ----------------
__global__ void __launch_bounds__(256) manlin_final_w(
    const float* __restrict__ mx, const float* __restrict__ xnb,
    const float* __restrict__ bias, int b2idx, const float* __restrict__ resid,
    float* __restrict__ outf)
{
    const int lane = threadIdx.x & 31;
    const size_t row = blockIdx.x * 8 + (threadIdx.x >> 5);
    const float MAXN = maxnorm();
    float4 v[4], bvv[4];
    float ss = 0.0f;
    #pragma unroll
    for (int i = 0; i < 4; i++) {
        v[i] = ((const float4*)(mx + row*ED))[lane + i*32];
        bvv[i] = ((const float4*)bias)[lane + i*32];
        ss += sq4(v[i]);
    }
    float mxn = sqrtf(warpSumF(ss) + 1e-30f);
    float xn = xnb[row];
    float s = tanhf(mxn / xn * atanhf(fminf(xn, MAXN))) / mxn;
    float dxy = 0.0f, dx2 = 0.0f;
    #pragma unroll
    for (int i = 0; i < 4; i++) {
        v[i] = scl4(v[i], s);
        dxy += dot4(v[i], bvv[i]);
        dx2 += sq4(v[i]);
    }
    float xy = warpSumF(dxy);
    float x2 = warpSumF(dx2);
    float y2 = g_b2[b2idx];
    float a = 1.0f + 2.0f*xy + y2;
    float c = 1.0f - x2;
    float invd = 1.0f / fmaxf(1.0f + 2.0f*xy + x2*y2, 1e-15f);
    float zz = 0.0f;
    #pragma unroll
    for (int i = 0; i < 4; i++) {
        VOP4(v[i], (a*v[i].x + c*bvv[i].x)*invd, (a*v[i].y + c*bvv[i].y)*invd,
                   (a*v[i].z + c*bvv[i].z)*invd, (a*v[i].w + c*bvv[i].w)*invd);
        zz += sq4(v[i]);
    }
    {
        float zn = sqrtf(warpSumF(zz) + 1e-30f);
        if (zn > MAXN) { float ps = MAXN / zn;
            #pragma unroll
            for (int i = 0; i < 4; i++) v[i] = scl4(v[i], ps); }
    }
    // mob_relu: logmap0 -> relu -> expmap0 -> projx
    {
        float s0 = 0.0f;
        #pragma unroll
        for (int i = 0; i < 4; i++) s0 += sq4(v[i]);
        float n = sqrtf(warpSumF(s0) + 1e-30f);
        float lf = atanhf(fminf(n, MAXN)) / n;
        float s1 = 0.0f;
        #pragma unroll
        for (int i = 0; i < 4; i++) {
            VOP4(v[i], fmaxf(lf*v[i].x, 0.0f), fmaxf(lf*v[i].y, 0.0f),
                       fmaxf(lf*v[i].z, 0.0f), fmaxf(lf*v[i].w, 0.0f));
            s1 += sq4(v[i]);
        }
        float nr = sqrtf(warpSumF(s1) + 1e-30f);
        float ef = tanhf(nr) / nr;
        float s2 = 0.0f;
        #pragma unroll
        for (int i = 0; i < 4; i++) { v[i] = scl4(v[i], ef); s2 += sq4(v[i]); }
        float n2 = sqrtf(warpSumF(s2) + 1e-30f);
        if (n2 > MAXN) { float ps = MAXN / n2;
            #pragma unroll
            for (int i = 0; i < 4; i++) v[i] = scl4(v[i], ps); }
    }
    // residual möbius add + projx
    {
        float d1 = 0.0f, d2 = 0.0f, d3 = 0.0f;
        float4 rv[4];
        #pragma unroll
        for (int i = 0; i < 4; i++) {
            rv[i] = ((const float4*)(resid + row*ED))[lane + i*32];
            d1 += dot4(v[i], rv[i]);
            d2 += sq4(rv[i]);
            d3 += sq4(v[i]);
        }
        float rxy = warpSumF(d1);
        float ry2 = warpSumF(d2);
        float rx2 = warpSumF(d3);
        float ra = 1.0f + 2.0f*rxy + ry2;
        float rc = 1.0f - rx2;
        float rinv = 1.0f / fmaxf(1.0f + 2.0f*rxy + rx2*ry2, 1e-15f);
        float s3 = 0.0f;
        #pragma unroll
        for (int i = 0; i < 4; i++) {
            VOP4(v[i], (ra*v[i].x + rc*rv[i].x)*rinv, (ra*v[i].y + rc*rv[i].y)*rinv,
                       (ra*v[i].z + rc*rv[i].z)*rinv, (ra*v[i].w + rc*rv[i].w)*rinv);
            s3 += sq4(v[i]);
        }
        float zn = sqrtf(warpSumF(s3) + 1e-30f);
        if (zn > MAXN) { float ps = MAXN / zn;
            #pragma unroll
            for (int i = 0; i < 4; i++) v[i] = scl4(v[i], ps); }
    }
    #pragma unroll
    for (int i = 0; i < 4; i++) ((float4*)(outf + row*ED))[lane + i*32] = v[i];
}

// ---------------- fc1 epilogue (FD wide, block version) ----------------
template <int E, int T>
__global__ void __launch_bounds__(T) manlin_epi(
    const float* __restrict__ mx, int ldm, const float* __restrict__ xnb,
    const float* __restrict__ bias, int b2idx,
    const float* __restrict__ resid,
    float* __restrict__ outf, __nv_bfloat16* __restrict__ oh, __nv_bfloat16* __restrict__ ol,
    float* __restrict__ out_norm, int flags)
{
    constexpr int V4 = E / (T * 4);
    const size_t row = blockIdx.x;
    const int tid = threadIdx.x;
    const float MAXN = maxnorm();
    const float4* mp = (const float4*)(mx + row*(size_t)ldm);
    const float4* bp = (const float4*)bias;
    float4 v[V4], bv[V4];
    float ss = 0.0f;
    #pragma unroll
    for (int i = 0; i < V4; i++) { v[i] = mp[tid*V4 + i]; ss += sq4(v[i]); }
    float mxn = sqrtf(blockSumF<T>(ss) + 1e-30f);
    float xn = xnb[row];
    float s = tanhf(mxn / xn * atanhf(fminf(xn, MAXN))) / mxn;
    float dxy = 0.0f, dx2 = 0.0f;
    #pragma unroll
    for (int i = 0; i < V4; i++) {
        v[i] = scl4(v[i], s);
        bv[i] = bp[tid*V4 + i];
        dxy += dot4(v[i], bv[i]);
        dx2 += sq4(v[i]);
    }
    float xy = blockSumF<T>(dxy);
    float x2 = blockSumF<T>(dx2);
    float y2 = g_b2[b2idx];
    float a = 1.0f + 2.0f*xy + y2;
    float c = 1.0f - x2;
    float den = fmaxf(1.0f + 2.0f*xy + x2*y2, 1e-15f);
    float invd = 1.0f / den;
    float zz = 0.0f;
    #pragma unroll
    for (int i = 0; i < V4; i++) {
        VOP4(v[i], (a*v[i].x + c*bv[i].x)*invd, (a*v[i].y + c*bv[i].y)*invd,
                   (a*v[i].z + c*bv[i].z)*invd, (a*v[i].w + c*bv[i].w)*invd);
        zz += sq4(v[i]);
    }
    {
        float zn = sqrtf(blockSumF<T>(zz) + 1e-30f);
        if (zn > MAXN) { float ps = MAXN / zn;
            #pragma unroll
            for (int i = 0; i < V4; i++) v[i] = scl4(v[i], ps); }
    }
    if (flags & FLAG_MOBRELU) {
        float s0 = 0.0f;
        #pragma unroll
        for (int i = 0; i < V4; i++) s0 += sq4(v[i]);
        float n = sqrtf(blockSumF<T>(s0) + 1e-30f);
        float lf = atanhf(fminf(n, MAXN)) / n;
        float s1 = 0.0f;
        #pragma unroll
        for (int i = 0; i < V4; i++) {
            VOP4(v[i], fmaxf(lf*v[i].x, 0.0f), fmaxf(lf*v[i].y, 0.0f),
                       fmaxf(lf*v[i].z, 0.0f), fmaxf(lf*v[i].w, 0.0f));
            s1 += sq4(v[i]);
        }
        float nr = sqrtf(blockSumF<T>(s1) + 1e-30f);
        float ef = tanhf(nr) / nr;
        float s2 = 0.0f;
        #pragma unroll
        for (int i = 0; i < V4; i++) { v[i] = scl4(v[i], ef); s2 += sq4(v[i]); }
        float n2 = sqrtf(blockSumF<T>(s2) + 1e-30f);
        if (n2 > MAXN) { float ps = MAXN / n2;
            #pragma unroll
            for (int i = 0; i < V4; i++) v[i] = scl4(v[i], ps); }
    }
    float s5 = 0.0f;
    #pragma unroll
    for (int i = 0; i < V4; i++) {
        if (outf) ((float4*)(outf + row*(size_t)ldm))[tid*V4 + i] = v[i];
        if (oh) write_split4(v[i], oh + row*E, ol + row*E, tid*V4*2 + i*2);
        s5 += sq4(v[i]);
    }
    if (out_norm) {
        float nf = sqrtf(blockSumF<T>(s5) + 1e-30f);
        if (tid == 0) out_norm[row] = nf;
    }
}

// ---------------- MMA helpers ----------------
__device__ __forceinline__ void ldsm_x4(uint32_t &r0, uint32_t &r1, uint32_t &r2, uint32_t &r3, uint32_t addr) {
    asm volatile("ldmatrix.sync.aligned.m8n8.x4.shared.b16 {%0,%1,%2,%3}, [%4];"
                 : "=r"(r0), "=r"(r1), "=r"(r2), "=r"(r3) : "r"(addr));
}
__device__ __forceinline__ void ldsm_x4t(uint32_t &r0, uint32_t &r1, uint32_t &r2, uint32_t &r3, uint32_t addr) {
    asm volatile("ldmatrix.sync.aligned.m8n8.x4.trans.shared.b16 {%0,%1,%2,%3}, [%4];"
                 : "=r"(r0), "=r"(r1), "=r"(r2), "=r"(r3) : "r"(addr));
}
__device__ __forceinline__ void mma16816(float* c, const uint32_t* a, const uint32_t* b) {
    asm volatile("mma.sync.aligned.m16n8k16.row.col.f32.bf16.bf16.f32 "
                 "{%0,%1,%2,%3}, {%4,%5,%6,%7}, {%8,%9}, {%0,%1,%2,%3};"
                 : "+f"(c[0]), "+f"(c[1]), "+f"(c[2]), "+f"(c[3])
                 : "r"(a[0]), "r"(a[1]), "r"(a[2]), "r"(a[3]), "r"(b[0]), "r"(b[1]));
}
#define CP_ASYNC16(dst, src) asm volatile("cp.async.cg.shared.global [%0], [%1], 16;" :: "r"(dst), "l"(src))

// ---------------- tensor-core attention ----------------
#define ATT_SMEM 98304
__global__ void __launch_bounds__(256) attn_mma(
    const __nv_bfloat16* __restrict__ qh_g, const __nv_bfloat16* __restrict__ ql_g,
    float* __restrict__ o)
{
    extern __shared__ __nv_bfloat16 smbuf[];
    uint32_t smb = (uint32_t)__cvta_generic_to_shared(smbuf);
    const int tid = threadIdx.x;
    const int lane = tid & 31, w = tid >> 5;
    const int bh = blockIdx.x, b = bh >> 3, h = bh & 7;

    #pragma unroll
    for (int it = 0; it < 24; it++) {
        int idx = tid + (it << 8);
        int tensor = idx >> 10;
        int cid = idx & 1023;
        int r = cid >> 3, c = cid & 7;
        uint32_t dst = smb + tensor*16384 + r*128 + ((c ^ (r & 7)) << 4);
        const __nv_bfloat16* P = (tensor & 1) ? ql_g : qh_g;
        const __nv_bfloat16* src = P + ((size_t)r*BB + b)*QKVW + (size_t)(tensor>>1)*512 + h*HD + c*8;
        CP_ASYNC16(dst, src);
    }
    asm volatile("cp.async.commit_group;");
    asm volatile("cp.async.wait_group 0;");
    __syncthreads();

    const int quad = lane >> 3, r8 = lane & 7;

    float sc[16][4];
    #pragma unroll
    for (int n = 0; n < 16; n++)
        #pragma unroll
        for (int e = 0; e < 4; e++) sc[n][e] = 0.0f;

    #pragma unroll
    for (int kk = 0; kk < 4; kk++) {
        uint32_t qh_[4], ql_[4];
        int arow = w*16 + (quad & 1)*8 + r8;
        int achk = kk*2 + (quad >> 1);
        uint32_t aoff = (uint32_t)(arow*128 + ((achk ^ (arow & 7)) << 4));
        ldsm_x4(qh_[0], qh_[1], qh_[2], qh_[3], smb + aoff);
        ldsm_x4(ql_[0], ql_[1], ql_[2], ql_[3], smb + 16384 + aoff);
        #pragma unroll
        for (int nn = 0; nn < 8; nn++) {
            int krow = nn*16 + (quad >> 1)*8 + r8;
            int kchk = kk*2 + (quad & 1);
            uint32_t koff = (uint32_t)(krow*128 + ((kchk ^ (krow & 7)) << 4));
            uint32_t kh0[2], kh1[2], kl0[2], kl1[2];
            { uint32_t a0,a1,a2,a3; ldsm_x4(a0,a1,a2,a3, smb + 32768 + koff);
              kh0[0]=a0; kh0[1]=a1; kh1[0]=a2; kh1[1]=a3; }
            { uint32_t a0,a1,a2,a3; ldsm_x4(a0,a1,a2,a3, smb + 49152 + koff);
              kl0[0]=a0; kl0[1]=a1; kl1[0]=a2; kl1[1]=a3; }
            mma16816(sc[2*nn],   qh_, kh0);
            mma16816(sc[2*nn],   qh_, kl0);
            mma16816(sc[2*nn],   ql_, kh0);
            mma16816(sc[2*nn+1], qh_, kh1);
            mma16816(sc[2*nn+1], qh_, kl1);
            mma16816(sc[2*nn+1], ql_, kh1);
        }
    }

    float m0 = -1e30f, m1 = -1e30f;
    #pragma unroll
    for (int n = 0; n < 16; n++) {
        m0 = fmaxf(m0, fmaxf(sc[n][0], sc[n][1]));
        m1 = fmaxf(m1, fmaxf(sc[n][2], sc[n][3]));
    }
    m0 = fmaxf(m0, __shfl_xor_sync(0xffffffffu, m0, 1));
    m0 = fmaxf(m0, __shfl_xor_sync(0xffffffffu, m0, 2));
    m1 = fmaxf(m1, __shfl_xor_sync(0xffffffffu, m1, 1));
    m1 = fmaxf(m1, __shfl_xor_sync(0xffffffffu, m1, 2));
    float l0 = 0.0f, l1 = 0.0f;
    #pragma unroll
    for (int n = 0; n < 16; n++) {
        sc[n][0] = fexp((sc[n][0] - m0) * 0.125f); l0 += sc[n][0];
        sc[n][1] = fexp((sc[n][1] - m0) * 0.125f); l0 += sc[n][1];
        sc[n][2] = fexp((sc[n][2] - m1) * 0.125f); l1 += sc[n][2];
        sc[n][3] = fexp((sc[n][3] - m1) * 0.125f); l1 += sc[n][3];
    }
    l0 += __shfl_xor_sync(0xffffffffu, l0, 1);
    l0 += __shfl_xor_sync(0xffffffffu, l0, 2);
    l1 += __shfl_xor_sync(0xffffffffu, l1, 1);
    l1 += __shfl_xor_sync(0xffffffffu, l1, 2);
    float inv0 = 1.0f / l0, inv1 = 1.0f / l1;

    float oa[8][4];
    #pragma unroll
    for (int n = 0; n < 8; n++)
        #pragma unroll
        for (int e = 0; e < 4; e++) oa[n][e] = 0.0f;

    #pragma unroll
    for (int kt = 0; kt < 8; kt++) {
        uint32_t ph[4], pl[4];
        #pragma unroll
        for (int half = 0; half < 2; half++) {
            int n2 = 2*kt + half;
            float p0 = sc[n2][0], p1 = sc[n2][1], p2 = sc[n2][2], p3 = sc[n2][3];
            __nv_bfloat16 b0 = __float2bfloat16(p0), b1 = __float2bfloat16(p1);
            __nv_bfloat16 b2 = __float2bfloat16(p2), b3 = __float2bfloat16(p3);
            ph[half*2+0] = pack_bf2(p0, p1);
            ph[half*2+1] = pack_bf2(p2, p3);
            pl[half*2+0] = pack_bf2(p0 - __bfloat162float(b0), p1 - __bfloat162float(b1));
            pl[half*2+1] = pack_bf2(p2 - __bfloat162float(b2), p3 - __bfloat162float(b3));
        }
        #pragma unroll
        for (int nn = 0; nn < 4; nn++) {
            int vrow = kt*16 + (quad & 1)*8 + r8;
            int vchk = 2*nn + (quad >> 1);
            uint32_t voff = (uint32_t)(vrow*128 + ((vchk ^ (vrow & 7)) << 4));
            uint32_t vh0[2], vh1[2], vl0[2], vl1[2];
            { uint32_t a0,a1,a2,a3; ldsm_x4t(a0,a1,a2,a3, smb + 65536 + voff);
              vh0[0]=a0; vh0[1]=a1; vh1[0]=a2; vh1[1]=a3; }
            { uint32_t a0,a1,a2,a3; ldsm_x4t(a0,a1,a2,a3, smb + 81920 + voff);
              vl0[0]=a0; vl0[1]=a1; vl1[0]=a2; vl1[1]=a3; }
            mma16816(oa[2*nn],   ph, vh0);
            mma16816(oa[2*nn],   ph, vl0);
            mma16816(oa[2*nn],   pl, vh0);
            mma16816(oa[2*nn+1], ph, vh1);
            mma16816(oa[2*nn+1], ph, vl1);
            mma16816(oa[2*nn+1], pl, vh1);
        }
    }

    int g = lane >> 2, t2 = (lane & 3) * 2;
    int t0 = w*16 + g;
    #pragma unroll
    for (int n = 0; n < 8; n++) {
        size_t base0 = ((size_t)t0*BB + b)*ED + (size_t)h*HD + n*8 + t2;
        size_t base1 = ((size_t)(t0+8)*BB + b)*ED + (size_t)h*HD + n*8 + t2;
        *(float2*)(o + base0) = make_float2(oa[n][0]*inv0, oa[n][1]*inv0);
        *(float2*)(o + base1) = make_float2(oa[n][2]*inv1, oa[n][3]*inv1);
    }
}

// ================= bf16x3 HMMA GEMM =================
#define BM 128
#define BN 128
#define BK 32
#define TEN_B   8192
#define STAGE_B (4*TEN_B)
#define GEMM_SMEM (3*STAGE_B)

__device__ __forceinline__ uint32_t saddr(int r, int colElem) {
    return (uint32_t)(r*64 + ((((colElem >> 3) ^ ((r >> 1) & 3))) << 4));
}

__global__ void __launch_bounds__(256, 2) gemm_bf16x3(
    const __nv_bfloat16* __restrict__ Ah, const __nv_bfloat16* __restrict__ Al,
    const __nv_bfloat16* __restrict__ Wh, const __nv_bfloat16* __restrict__ Wl,
    float* __restrict__ C, int M, int N, int K)
{
    extern __shared__ __nv_bfloat16 smbuf[];
    const int tid = threadIdx.x;
    const int lane = tid & 31, w = tid >> 5;
    const int wm = w & 1, wn = w >> 1;
    const int rowBase = blockIdx.y * BM;
    const int colBase = blockIdx.x * BN;
    uint32_t smbase = (uint32_t)__cvta_generic_to_shared(smbuf);

    float acc[4][4][4];
    #pragma unroll
    for (int i = 0; i < 4; i++)
        #pragma unroll
        for (int j = 0; j < 4; j++)
            #pragma unroll
            for (int e = 0; e < 4; e++) acc[i][j][e] = 0.0f;

    auto load_stage = [&](int st, int k0) {
        uint32_t base = smbase + st * STAGE_B;
        #pragma unroll
        for (int it = 0; it < 8; it++) {
            int idx = tid + (it << 8);
            int tensor = idx >> 9;
            int cid = idx & 511;
            int r = cid >> 2, c = cid & 3;
            uint32_t dst = base + tensor * TEN_B
                         + (uint32_t)(r*64 + ((c ^ ((r >> 1) & 3)) << 4));
            const __nv_bfloat16* src;
            if (tensor == 0)      src = Ah + (size_t)(rowBase + r) * K + k0 + c * 8;
            else if (tensor == 1) src = Al + (size_t)(rowBase + r) * K + k0 + c * 8;
            else if (tensor == 2) src = Wh + (size_t)(colBase + r) * K + k0 + c * 8;
            else                  src = Wl + (size_t)(colBase + r) * K + k0 + c * 8;
            CP_ASYNC16(dst, src);
        }
        asm volatile("cp.async.commit_group;");
    };

    auto compute_stage = [&](int st) {
        uint32_t base = smbase + st * STAGE_B;
        uint32_t aH = base;
        uint32_t aL = base + 1*TEN_B;
        uint32_t wH = base + 2*TEN_B;
        uint32_t wL = base + 3*TEN_B;
        const int quad = lane >> 3, r8 = lane & 7;
        #pragma unroll
        for (int kk = 0; kk < BK; kk += 16) {
            uint32_t ah[4][4], al[4][4], bh[4][2], bl[4][2];
            #pragma unroll
            for (int i = 0; i < 4; i++) {
                int row = wm*64 + i*16 + (quad & 1)*8 + r8;
                int col = kk + (quad >> 1)*8;
                uint32_t off = saddr(row, col);
                ldsm_x4(ah[i][0], ah[i][1], ah[i][2], ah[i][3], aH + off);
                ldsm_x4(al[i][0], al[i][1], al[i][2], al[i][3], aL + off);
            }
            #pragma unroll
            for (int jj = 0; jj < 2; jj++) {
                int nr = wn*32 + jj*16 + (quad >> 1)*8 + r8;
                int kc = kk + (quad & 1)*8;
                uint32_t off = saddr(nr, kc);
                uint32_t a0,a1,a2,a3;
                ldsm_x4(a0,a1,a2,a3, wH + off);
                bh[2*jj][0]=a0; bh[2*jj][1]=a1; bh[2*jj+1][0]=a2; bh[2*jj+1][1]=a3;
                ldsm_x4(a0,a1,a2,a3, wL + off);
                bl[2*jj][0]=a0; bl[2*jj][1]=a1; bl[2*jj+1][0]=a2; bl[2*jj+1][1]=a3;
            }
            #pragma unroll
            for (int i = 0; i < 4; i++)
                #pragma unroll
                for (int j = 0; j < 4; j++) mma16816(acc[i][j], ah[i], bh[j]);
            #pragma unroll
            for (int i = 0; i < 4; i++)
                #pragma unroll
                for (int j = 0; j < 4; j++) mma16816(acc[i][j], ah[i], bl[j]);
            #pragma unroll
            for (int i = 0; i < 4; i++)
                #pragma unroll
                for (int j = 0; j < 4; j++) mma16816(acc[i][j], al[i], bh[j]);
        }
    };

    const int nkb = K / BK;
    load_stage(0, 0);
    load_stage(1, BK);
    for (int kb = 0; kb < nkb; kb++) {
        if (kb == nkb - 1) { asm volatile("cp.async.wait_group 0;"); }
        else               { asm volatile("cp.async.wait_group 1;"); }
        __syncthreads();
        if (kb + 2 < nkb) load_stage((kb + 2) % 3, (kb + 2) * BK);
        compute_stage(kb % 3);
    }

    const int g = lane >> 2, tg = lane & 3;
    #pragma unroll
    for (int i = 0; i < 4; i++) {
        int row = rowBase + wm*64 + i*16 + g;
        #pragma unroll
        for (int j = 0; j < 4; j++) {
            int col = colBase + wn*32 + j*8 + tg*2;
            *(float2*)(C + (size_t)row * N + col)       = make_float2(acc[i][j][0], acc[i][j][1]);
            *(float2*)(C + (size_t)(row + 8) * N + col) = make_float2(acc[i][j][2], acc[i][j][3]);
        }
    }
}

// ---------------- launch ----------------
extern "C" void kernel_launch(void* const* d_in, const int* in_sizes, int n_in,
                              void* d_out, int out_size)
{
    const float* x    = (const float*)d_in[0];
    const float* l1g  = (const float*)d_in[1];
    const float* l1b  = (const float*)d_in[2];
    const float* l2g  = (const float*)d_in[3];
    const float* l2b  = (const float*)d_in[4];
    const float* Wq   = (const float*)d_in[5];
    const float* bq   = (const float*)d_in[6];
    const float* Wk   = (const float*)d_in[7];
    const float* bk   = (const float*)d_in[8];
    const float* Wv   = (const float*)d_in[9];
    const float* bv   = (const float*)d_in[10];
    const float* Wo   = (const float*)d_in[11];
    const float* bo   = (const float*)d_in[12];
    const float* W1   = (const float*)d_in[13];
    const float* b1   = (const float*)d_in[14];
    const float* W2   = (const float*)d_in[15];
    const float* b2   = (const float*)d_in[16];
    float* out = (float*)d_out;

    float *qkv, *ob, *h1, *big, *n0, *no, *nh2, *nh3, *bsq;
    __nv_bfloat16 *xh, *xl, *wh, *wl;
    cudaGetSymbolAddress((void**)&qkv, g_qkv);
    cudaGetSymbolAddress((void**)&ob,  g_o);
    cudaGetSymbolAddress((void**)&h1,  g_h1);
    cudaGetSymbolAddress((void**)&big, g_big);
    cudaGetSymbolAddress((void**)&xh,  g_xh);
    cudaGetSymbolAddress((void**)&xl,  g_xl);
    cudaGetSymbolAddress((void**)&wh,  g_wh);
    cudaGetSymbolAddress((void**)&wl,  g_wl);
    cudaGetSymbolAddress((void**)&n0,  g_n0);
    cudaGetSymbolAddress((void**)&no,  g_no);
    cudaGetSymbolAddress((void**)&nh2, g_nh2);
    cudaGetSymbolAddress((void**)&nh3, g_nh3);
    cudaGetSymbolAddress((void**)&bsq, g_b2);

    cudaFuncSetAttribute(gemm_bf16x3, cudaFuncAttributeMaxDynamicSharedMemorySize, GEMM_SMEM);
    cudaFuncSetAttribute(attn_mma, cudaFuncAttributeMaxDynamicSharedMemorySize, ATT_SMEM);

    split_all<<<dim3(1024, 6), 256>>>(Wq, Wk, Wv, Wo, W1, W2, wh, wl);
    sqsum6<<<6, 256>>>(bq, bk, bv, bo, b1, b2, bsq);
    ln1_w<<<NR/8, 256>>>(x, l1g, l1b, xh, xl, n0);

    gemm_bf16x3<<<dim3(QKVW/BN, NR/BM), 256, GEMM_SMEM>>>(xh, xl, wh + WQ0, wl + WQ0, qkv, NR, QKVW, ED);
    manlin_qkv_w<<<dim3(NR/8, 3), 256>>>(qkv, n0, bq, bk, bv, xh, xl);

    attn_mma<<<BB * NH, 256, ATT_SMEM>>>(xh, xl, ob);
    expmap_w<<<NR/8, 256>>>(ob, xh, xl, no);

    gemm_bf16x3<<<dim3(ED/BN, NR/BM), 256, GEMM_SMEM>>>(xh, xl, wh + WO0, wl + WO0, big, NR, ED, ED);
    manlin_ln_w<<<NR/8, 256>>>(big, no, bo, 3, x, h1, l2g, l2b, xh, xl, nh2);

    gemm_bf16x3<<<dim3(FD/BN, NR/BM), 256, GEMM_SMEM>>>(xh, xl, wh + W10, wl + W10, big, NR, FD, ED);
    manlin_epi<FD, 256><<<NR, 256>>>(big, FD, nh2, b1, 4, nullptr, nullptr, xh, xl, nh3, FLAG_MOBRELU);

    gemm_bf16x3<<<dim3(ED/BN, NR/BM), 256, GEMM_SMEM>>>(xh, xl, wh + W20, wl + W20, qkv, NR, ED, FD);
    manlin_final_w<<<NR/8, 256>>>(qkv, nh3, b2, 5, h1, out);
}

// round 10
// speedup vs baseline: 9.3819x; 1.0530x over previous
#include <cuda_runtime.h>
#include <cuda_bf16.h>
#include <math.h>
#include <stdint.h>

// ---------------- problem constants ----------------
#define SEQ 128
#define BB  256
#define ED  512
#define FD  2048
#define NH  8
#define HD  64
#define NR  (SEQ*BB)   // 32768 rows
#define QKVW 1536      // fused qkv row width

static __device__ __forceinline__ float maxnorm() { return (float)(1.0 - 1e-5); }

// ---------------- scratch ----------------
__device__ float g_qkv[(size_t)NR*QKVW];
__device__ float g_o  [(size_t)NR*ED];
__device__ float g_h1 [(size_t)NR*ED];
__device__ float g_big[(size_t)NR*FD];
__device__ __nv_bfloat16 g_xh[(size_t)NR*FD];
__device__ __nv_bfloat16 g_xl[(size_t)NR*FD];
__device__ __nv_bfloat16 g_wh[(size_t)3*1024*1024];
__device__ __nv_bfloat16 g_wl[(size_t)3*1024*1024];
__device__ float g_n0 [NR];
__device__ float g_no [NR];
__device__ float g_nh2[NR];
__device__ float g_nh3[NR];
__device__ float g_b2 [8];

#define WQ0 0
#define WK0 262144
#define WV0 524288
#define WO0 786432
#define W10 1048576
#define W20 2097152

// ---------------- reductions ----------------
template <int T>
__device__ __forceinline__ float blockSumF(float v) {
    __shared__ float sh[T / 32];
    #pragma unroll
    for (int o = 16; o > 0; o >>= 1) v += __shfl_xor_sync(0xffffffffu, v, o);
    int lane = threadIdx.x & 31, w = threadIdx.x >> 5;
    if (lane == 0) sh[w] = v;
    __syncthreads();
    if (threadIdx.x < 32) {
        float t = (threadIdx.x < T / 32) ? sh[threadIdx.x] : 0.0f;
        #pragma unroll
        for (int o = 16; o > 0; o >>= 1) t += __shfl_xor_sync(0xffffffffu, t, o);
        if (threadIdx.x == 0) sh[0] = t;
    }
    __syncthreads();
    float r = sh[0];
    __syncthreads();
    return r;
}
__device__ __forceinline__ float warpSumF(float v) {
    #pragma unroll
    for (int o = 16; o > 0; o >>= 1) v += __shfl_xor_sync(0xffffffffu, v, o);
    return v;
}

__device__ __forceinline__ void split1(float x, __nv_bfloat16 &h, __nv_bfloat16 &l) {
    h = __float2bfloat16(x);
    l = __float2bfloat16(x - __bfloat162float(h));
}
__device__ __forceinline__ uint32_t pack_bf2(float a, float b) {
    __nv_bfloat162 t(__float2bfloat16(a), __float2bfloat16(b));
    return *(uint32_t*)&t;
}

// FMA-pipe exp (no MUFU)
__device__ __forceinline__ float fexp(float x) {
    float y = x * 1.4426950408889634f;
    y = fmaxf(y, -126.0f);
    float fl = floorf(y);
    float f = y - fl;
    float p = 1.5252734e-5f;
    p = fmaf(p, f, 1.5403530e-4f);
    p = fmaf(p, f, 1.3333558e-3f);
    p = fmaf(p, f, 9.6181291e-3f);
    p = fmaf(p, f, 5.5504109e-2f);
    p = fmaf(p, f, 2.4022651e-1f);
    p = fmaf(p, f, 6.9314718e-1f);
    p = fmaf(p, f, 1.0f);
    return __int_as_float(__float_as_int(p) + (((int)fl) << 23));
}

// ---------------- split all 6 weights + bias sq-norms (idle blocks) ----------------
__global__ void split_all(const float* Wq, const float* Wk, const float* Wv,
                          const float* Wo, const float* W1, const float* W2,
                          const float* bq, const float* bk, const float* bv,
                          const float* bo, const float* b1, const float* b2,
                          __nv_bfloat16* __restrict__ h, __nv_bfloat16* __restrict__ l,
                          float* __restrict__ bsq) {
    // bias sq-norm tasks on blocks that have no split work
    int task = -1;
    if (blockIdx.x == 1023 && blockIdx.y < 4) task = blockIdx.y;
    else if (blockIdx.x == 1022 && blockIdx.y >= 4) task = 2 + blockIdx.y;  // y=4->6? no
    if (blockIdx.x == 1022 && blockIdx.y < 2) task = 4 + blockIdx.y;
    if (task >= 0 && task < 6) {
        const float* p; int n;
        switch (task) {
            case 0: p = bq; n = ED; break;
            case 1: p = bk; n = ED; break;
            case 2: p = bv; n = ED; break;
            case 3: p = bo; n = ED; break;
            case 4: p = b1; n = FD; break;
            default: p = b2; n = ED; break;
        }
        float s = 0.0f;
        for (int i = threadIdx.x; i < n; i += 256) { float x = p[i]; s += x * x; }
        s = blockSumF<256>(s);
        if (threadIdx.x == 0) bsq[task] = s;
    }
    const float* src; size_t off; int n4;
    switch (blockIdx.y) {
        case 0: src = Wq; off = WQ0; n4 = 65536;  break;
        case 1: src = Wk; off = WK0; n4 = 65536;  break;
        case 2: src = Wv; off = WV0; n4 = 65536;  break;
        case 3: src = Wo; off = WO0; n4 = 65536;  break;
        case 4: src = W1; off = W10; n4 = 262144; break;
        default: src = W2; off = W20; n4 = 262144; break;
    }
    int i = blockIdx.x * 256 + threadIdx.x;
    if (i < n4) {
        float4 v = ((const float4*)src)[i];
        __nv_bfloat16 h0,l0,h1,l1,h2,l2,h3,l3;
        split1(v.x, h0, l0); split1(v.y, h1, l1);
        split1(v.z, h2, l2); split1(v.w, h3, l3);
        __nv_bfloat162* hp = (__nv_bfloat162*)(h + off);
        __nv_bfloat162* lp = (__nv_bfloat162*)(l + off);
        hp[i*2]   = __nv_bfloat162(h0, h1);
        hp[i*2+1] = __nv_bfloat162(h2, h3);
        lp[i*2]   = __nv_bfloat162(l0, l1);
        lp[i*2+1] = __nv_bfloat162(l2, l3);
    }
}

// vector helpers
#define VOP4(dst, ex, ey, ez, ew) do { dst.x=(ex); dst.y=(ey); dst.z=(ez); dst.w=(ew); } while(0)
__device__ __forceinline__ float dot4(float4 a, float4 b) { return a.x*b.x + a.y*b.y + a.z*b.z + a.w*b.w; }
__device__ __forceinline__ float sq4(float4 a) { return dot4(a, a); }
__device__ __forceinline__ float4 scl4(float4 a, float s) { float4 r; VOP4(r, a.x*s, a.y*s, a.z*s, a.w*s); return r; }

__device__ __forceinline__ void write_split4(float4 v, __nv_bfloat16* oh, __nv_bfloat16* ol, int idx2) {
    __nv_bfloat16 h0,l0,h1,l1,h2,l2,h3,l3;
    split1(v.x,h0,l0); split1(v.y,h1,l1); split1(v.z,h2,l2); split1(v.w,h3,l3);
    ((__nv_bfloat162*)oh)[idx2]   = __nv_bfloat162(h0,h1);
    ((__nv_bfloat162*)oh)[idx2+1] = __nv_bfloat162(h2,h3);
    ((__nv_bfloat162*)ol)[idx2]   = __nv_bfloat162(l0,l1);
    ((__nv_bfloat162*)ol)[idx2+1] = __nv_bfloat162(l2,l3);
}

// ================= warp-per-row kernels =================

// ---------------- ln1 ----------------
__global__ void __launch_bounds__(256) ln1_w(
    const float* __restrict__ x, const float* __restrict__ g, const float* __restrict__ b,
    __nv_bfloat16* __restrict__ oh, __nv_bfloat16* __restrict__ ol,
    float* __restrict__ out_norm)
{
    const int lane = threadIdx.x & 31;
    const size_t row = blockIdx.x * 8 + (threadIdx.x >> 5);
    const float MAXN = maxnorm();
    const float4* xp = (const float4*)(x + row * ED);
    float4 v[4];
    float ss = 0.0f;
    #pragma unroll
    for (int i = 0; i < 4; i++) { v[i] = xp[lane + i*32]; ss += sq4(v[i]); }
    float n0 = sqrtf(warpSumF(ss) + 1e-30f);
    float lf = atanhf(fminf(n0, MAXN)) / n0;
    float sm = 0.0f;
    #pragma unroll
    for (int i = 0; i < 4; i++) { v[i] = scl4(v[i], lf); sm += v[i].x + v[i].y + v[i].z + v[i].w; }
    float mu = warpSumF(sm) * (1.0f / ED);
    float vv = 0.0f;
    #pragma unroll
    for (int i = 0; i < 4; i++) {
        float4 d; VOP4(d, v[i].x-mu, v[i].y-mu, v[i].z-mu, v[i].w-mu);
        vv += sq4(d);
    }
    float var = warpSumF(vv) * (1.0f / ED);
    float inv = rsqrtf(var + 1e-5f);
    float s2 = 0.0f;
    #pragma unroll
    for (int i = 0; i < 4; i++) {
        float4 gg = ((const float4*)g)[lane + i*32], bb = ((const float4*)b)[lane + i*32];
        VOP4(v[i], (v[i].x-mu)*inv*gg.x + bb.x, (v[i].y-mu)*inv*gg.y + bb.y,
                   (v[i].z-mu)*inv*gg.z + bb.z, (v[i].w-mu)*inv*gg.w + bb.w);
        s2 += sq4(v[i]);
    }
    float ny = sqrtf(warpSumF(s2) + 1e-30f);
    float ef = tanhf(ny) / ny;
    float s4 = 0.0f;
    #pragma unroll
    for (int i = 0; i < 4; i++) {
        v[i] = scl4(v[i], ef);
        write_split4(v[i], oh + row*ED, ol + row*ED, (lane + i*32)*2);
        s4 += sq4(v[i]);
    }
    float nf = sqrtf(warpSumF(s4) + 1e-30f);
    if (lane == 0) out_norm[row] = nf;
}

// ---------------- expmap0 ----------------
__global__ void __launch_bounds__(256) expmap_w(
    const float* __restrict__ x, __nv_bfloat16* __restrict__ oh, __nv_bfloat16* __restrict__ ol,
    float* __restrict__ out_norm)
{
    const int lane = threadIdx.x & 31;
    const size_t row = blockIdx.x * 8 + (threadIdx.x >> 5);
    const float4* xp = (const float4*)(x + row * ED);
    float4 v[4];
    float ss = 0.0f;
    #pragma unroll
    for (int i = 0; i < 4; i++) { v[i] = xp[lane + i*32]; ss += sq4(v[i]); }
    float n = sqrtf(warpSumF(ss) + 1e-30f);
    float ef = tanhf(n) / n;
    float s2 = 0.0f;
    #pragma unroll
    for (int i = 0; i < 4; i++) {
        v[i] = scl4(v[i], ef);
        write_split4(v[i], oh + row*ED, ol + row*ED, (lane + i*32)*2);
        s2 += sq4(v[i]);
    }
    float nf = sqrtf(warpSumF(s2) + 1e-30f);
    if (lane == 0) out_norm[row] = nf;
}

// ---------------- q/k/v manifold epilogue ----------------
__global__ void __launch_bounds__(256) manlin_qkv_w(
    const float* __restrict__ qkvf, const float* __restrict__ xnb,
    const float* __restrict__ bq, const float* __restrict__ bk, const float* __restrict__ bv,
    __nv_bfloat16* __restrict__ oh, __nv_bfloat16* __restrict__ ol)
{
    const int lane = threadIdx.x & 31;
    const size_t row = blockIdx.x * 8 + (threadIdx.x >> 5);
    const int seg = blockIdx.y;
    const float MAXN = maxnorm();
    const float* bias = (seg == 0) ? bq : (seg == 1) ? bk : bv;
    const float4* base = (const float4*)(qkvf + row * (size_t)QKVW + seg * 512);
    float4 v[4], bvv[4];
    float ss = 0.0f;
    #pragma unroll
    for (int i = 0; i < 4; i++) {
        v[i] = base[lane + i*32];
        bvv[i] = ((const float4*)bias)[lane + i*32];
        ss += sq4(v[i]);
    }
    float mxn = sqrtf(warpSumF(ss) + 1e-30f);
    float xn = xnb[row];
    float s = tanhf(mxn / xn * atanhf(fminf(xn, MAXN))) / mxn;
    float dxy = 0.0f, dx2 = 0.0f;
    #pragma unroll
    for (int i = 0; i < 4; i++) {
        v[i] = scl4(v[i], s);
        dxy += dot4(v[i], bvv[i]);
        dx2 += sq4(v[i]);
    }
    float xy = warpSumF(dxy);
    float x2 = warpSumF(dx2);
    float y2 = g_b2[seg];
    float a = 1.0f + 2.0f*xy + y2;
    float c = 1.0f - x2;
    float invd = 1.0f / fmaxf(1.0f + 2.0f*xy + x2*y2, 1e-15f);
    float zz = 0.0f;
    #pragma unroll
    for (int i = 0; i < 4; i++) {
        VOP4(v[i], (a*v[i].x + c*bvv[i].x)*invd, (a*v[i].y + c*bvv[i].y)*invd,
                   (a*v[i].z + c*bvv[i].z)*invd, (a*v[i].w + c*bvv[i].w)*invd);
        zz += sq4(v[i]);
    }
    float zn = sqrtf(warpSumF(zz) + 1e-30f);
    if (zn > MAXN) {
        float ps = MAXN / zn;
        #pragma unroll
        for (int i = 0; i < 4; i++) v[i] = scl4(v[i], ps);
    }
    float s0 = 0.0f;
    #pragma unroll
    for (int i = 0; i < 4; i++) s0 += sq4(v[i]);
    float n = sqrtf(warpSumF(s0) + 1e-30f);
    float lf = atanhf(fminf(n, MAXN)) / n;
    size_t ob = row * (size_t)QKVW + seg * 512;
    #pragma unroll
    for (int i = 0; i < 4; i++) {
        v[i] = scl4(v[i], lf);
        write_split4(v[i], oh + ob, ol + ob, (lane + i*32)*2);
    }
}

// ---------------- fused: manlin(Wo)+residual -> ln2 -> splits ----------------
__global__ void __launch_bounds__(256) manlin_ln_w(
    const float* __restrict__ mx, const float* __restrict__ xnb,
    const float* __restrict__ bias, int b2idx, const float* __restrict__ resid,
    float* __restrict__ h1out,
    const float* __restrict__ g, const float* __restrict__ bln,
    __nv_bfloat16* __restrict__ oh, __nv_bfloat16* __restrict__ ol,
    float* __restrict__ out_norm)
{
    const int lane = threadIdx.x & 31;
    const size_t row = blockIdx.x * 8 + (threadIdx.x >> 5);
    const float MAXN = maxnorm();
    float4 v[4], bvv[4];
    float ss = 0.0f;
    #pragma unroll
    for (int i = 0; i < 4; i++) {
        v[i] = ((const float4*)(mx + row*ED))[lane + i*32];
        bvv[i] = ((const float4*)bias)[lane + i*32];
        ss += sq4(v[i]);
    }
    float mxn = sqrtf(warpSumF(ss) + 1e-30f);
    float xn = xnb[row];
    float s = tanhf(mxn / xn * atanhf(fminf(xn, MAXN))) / mxn;
    float dxy = 0.0f, dx2 = 0.0f;
    #pragma unroll
    for (int i = 0; i < 4; i++) {
        v[i] = scl4(v[i], s);
        dxy += dot4(v[i], bvv[i]);
        dx2 += sq4(v[i]);
    }
    float xy = warpSumF(dxy);
    float x2 = warpSumF(dx2);
    float y2 = g_b2[b2idx];
    float a = 1.0f + 2.0f*xy + y2;
    float c = 1.0f - x2;
    float invd = 1.0f / fmaxf(1.0f + 2.0f*xy + x2*y2, 1e-15f);
    float zz = 0.0f;
    #pragma unroll
    for (int i = 0; i < 4; i++) {
        VOP4(v[i], (a*v[i].x + c*bvv[i].x)*invd, (a*v[i].y + c*bvv[i].y)*invd,
                   (a*v[i].z + c*bvv[i].z)*invd, (a*v[i].w + c*bvv[i].w)*invd);
        zz += sq4(v[i]);
    }
    {
        float zn = sqrtf(warpSumF(zz) + 1e-30f);
        if (zn > MAXN) { float ps = MAXN / zn;
            #pragma unroll
            for (int i = 0; i < 4; i++) v[i] = scl4(v[i], ps); }
    }
    {
        float d1 = 0.0f, d2 = 0.0f, d3 = 0.0f;
        float4 rv[4];
        #pragma unroll
        for (int i = 0; i < 4; i++) {
            rv[i] = ((const float4*)(resid + row*ED))[lane + i*32];
            d1 += dot4(v[i], rv[i]);
            d2 += sq4(rv[i]);
            d3 += sq4(v[i]);
        }
        float rxy = warpSumF(d1);
        float ry2 = warpSumF(d2);
        float rx2 = warpSumF(d3);
        float ra = 1.0f + 2.0f*rxy + ry2;
        float rc = 1.0f - rx2;
        float rinv = 1.0f / fmaxf(1.0f + 2.0f*rxy + rx2*ry2, 1e-15f);
        float s3 = 0.0f;
        #pragma unroll
        for (int i = 0; i < 4; i++) {
            VOP4(v[i], (ra*v[i].x + rc*rv[i].x)*rinv, (ra*v[i].y + rc*rv[i].y)*rinv,
                       (ra*v[i].z + rc*rv[i].z)*rinv, (ra*v[i].w + rc*rv[i].w)*rinv);
            s3 += sq4(v[i]);
        }
        float zn = sqrtf(warpSumF(s3) + 1e-30f);
        if (zn > MAXN) { float ps = MAXN / zn;
            #pragma unroll
            for (int i = 0; i < 4; i++) v[i] = scl4(v[i], ps); }
    }
    #pragma unroll
    for (int i = 0; i < 4; i++) ((float4*)(h1out + row*ED))[lane + i*32] = v[i];
    float s0 = 0.0f;
    #pragma unroll
    for (int i = 0; i < 4; i++) s0 += sq4(v[i]);
    float n0 = sqrtf(warpSumF(s0) + 1e-30f);
    float lf = atanhf(fminf(n0, MAXN)) / n0;
    float sm = 0.0f;
    #pragma unroll
    for (int i = 0; i < 4; i++) { v[i] = scl4(v[i], lf); sm += v[i].x + v[i].y + v[i].z + v[i].w; }
    float mu = warpSumF(sm) * (1.0f / ED);
    float vv = 0.0f;
    #pragma unroll
    for (int i = 0; i < 4; i++) {
        float4 d; VOP4(d, v[i].x-mu, v[i].y-mu, v[i].z-mu, v[i].w-mu);
        vv += sq4(d);
    }
    float var = warpSumF(vv) * (1.0f / ED);
    float inv = rsqrtf(var + 1e-5f);
    float s2 = 0.0f;
    #pragma unroll
    for (int i = 0; i < 4; i++) {
        float4 gg = ((const float4*)g)[lane + i*32], bb = ((const float4*)bln)[lane + i*32];
        VOP4(v[i], (v[i].x-mu)*inv*gg.x + bb.x, (v[i].y-mu)*inv*gg.y + bb.y,
                   (v[i].z-mu)*inv*gg.z + bb.z, (v[i].w-mu)*inv*gg.w + bb.w);
        s2 += sq4(v[i]);
    }
    float ny = sqrtf(warpSumF(s2) + 1e-30f);
    float ef = tanhf(ny) / ny;
    #pragma unroll
    for (int i = 0; i < 4; i++) v[i] = scl4(v[i], ef);
    {
        float s3 = 0.0f;
        #pragma unroll
        for (int i = 0; i < 4; i++) s3 += sq4(v[i]);
        float n = sqrtf(warpSumF(s3) + 1e-30f);
        if (n > MAXN) { float ps = MAXN / n;
            #pragma unroll
            for (int i = 0; i < 4; i++) v[i] = scl4(v[i], ps); }
    }
    float s4 = 0.0f;
    #pragma unroll
    for (int i = 0; i < 4; i++) {
        write_split4(v[i], oh + row*ED, ol + row*ED, (lane + i*32)*2);
        s4 += sq4(v[i]);
    }
    float nf = sqrtf(warpSumF(s4) + 1e-30f);
    if (lane == 0) out_norm[row] = nf;
}

// ---------------- fc1 epilogue: warp-per-row over FD=2048 (64 floats/lane) ----------------
__global__ void __launch_bounds__(128) manlin_fc1_w(
    const float* __restrict__ mx, const float* __restrict__ xnb,
    const float* __restrict__ bias,
    __nv_bfloat16* __restrict__ oh, __nv_bfloat16* __restrict__ ol,
    float* __restrict__ out_norm)
{
    const int lane = threadIdx.x & 31;
    const size_t row = blockIdx.x * 4 + (threadIdx.x >> 5);
    const float MAXN = maxnorm();
    const float4* mp = (const float4*)(mx + row * (size_t)FD);
    const float4* bp = (const float4*)bias;
    float4 v[16];
    float ss = 0.0f;
    #pragma unroll
    for (int i = 0; i < 16; i++) { v[i] = mp[lane + i*32]; ss += sq4(v[i]); }
    float mxn = sqrtf(warpSumF(ss) + 1e-30f);
    float xn = xnb[row];
    float s = tanhf(mxn / xn * atanhf(fminf(xn, MAXN))) / mxn;
    float dxy = 0.0f, dx2 = 0.0f;
    #pragma unroll
    for (int i = 0; i < 16; i++) {
        v[i] = scl4(v[i], s);
        dxy += dot4(v[i], bp[lane + i*32]);
        dx2 += sq4(v[i]);
    }
    float xy = warpSumF(dxy);
    float x2 = warpSumF(dx2);
    float y2 = g_b2[4];
    float a = 1.0f + 2.0f*xy + y2;
    float c = 1.0f - x2;
    float invd = 1.0f / fmaxf(1.0f + 2.0f*xy + x2*y2, 1e-15f);
    float zz = 0.0f;
    #pragma unroll
    for (int i = 0; i < 16; i++) {
        float4 bv = bp[lane + i*32];
        VOP4(v[i], (a*v[i].x + c*bv.x)*invd, (a*v[i].y + c*bv.y)*invd,
                   (a*v[i].z + c*bv.z)*invd, (a*v[i].w + c*bv.w)*invd);
        zz += sq4(v[i]);
    }
    {
        float zn = sqrtf(warpSumF(zz) + 1e-30f);
        if (zn > MAXN) { float ps = MAXN / zn;
            #pragma unroll
            for (int i = 0; i < 16; i++) v[i] = scl4(v[i], ps); }
    }
    // mob_relu: logmap0 -> relu -> expmap0 -> projx
    float s0 = 0.0f;
    #pragma unroll
    for (int i = 0; i < 16; i++) s0 += sq4(v[i]);
    float n = sqrtf(warpSumF(s0) + 1e-30f);
    float lf = atanhf(fminf(n, MAXN)) / n;
    float s1 = 0.0f;
    #pragma unroll
    for (int i = 0; i < 16; i++) {
        VOP4(v[i], fmaxf(lf*v[i].x, 0.0f), fmaxf(lf*v[i].y, 0.0f),
                   fmaxf(lf*v[i].z, 0.0f), fmaxf(lf*v[i].w, 0.0f));
        s1 += sq4(v[i]);
    }
    float nr = sqrtf(warpSumF(s1) + 1e-30f);
    float ef = tanhf(nr) / nr;
    float s2 = 0.0f;
    #pragma unroll
    for (int i = 0; i < 16; i++) { v[i] = scl4(v[i], ef); s2 += sq4(v[i]); }
    {
        float n2 = sqrtf(warpSumF(s2) + 1e-30f);
        if (n2 > MAXN) { float ps = MAXN / n2;
            #pragma unroll
            for (int i = 0; i < 16; i++) v[i] = scl4(v[i], ps); }
    }
    float s5 = 0.0f;
    #pragma unroll
    for (int i = 0; i < 16; i++) {
        write_split4(v[i], oh + row*(size_t)FD, ol + row*(size_t)FD, (lane + i*32)*2);
        s5 += sq4(v[i]);
    }
    float nf = sqrtf(warpSumF(s5) + 1e-30f);
    if (lane == 0) out_norm[row] = nf;
}

// ---------------- final: manlin(W2) + mob_relu + residual -> fp32 out ----------------
__global__ void __launch_bounds__(256) manlin_final_w(
    const float* __restrict__ mx, const float* __restrict__ xnb,
    const float* __restrict__ bias, int b2idx, const float* __restrict__ resid,
    float* __restrict__ outf)
{
    const int lane = threadIdx.x & 31;
    const size_t row = blockIdx.x * 8 + (threadIdx.x >> 5);
    const float MAXN = maxnorm();
    float4 v[4], bvv[4];
    float ss = 0.0f;
    #pragma unroll
    for (int i = 0; i < 4; i++) {
        v[i] = ((const float4*)(mx + row*ED))[lane + i*32];
        bvv[i] = ((const float4*)bias)[lane + i*32];
        ss += sq4(v[i]);
    }
    float mxn = sqrtf(warpSumF(ss) + 1e-30f);
    float xn = xnb[row];
    float s = tanhf(mxn / xn * atanhf(fminf(xn, MAXN))) / mxn;
    float dxy = 0.0f, dx2 = 0.0f;
    #pragma unroll
    for (int i = 0; i < 4; i++) {
        v[i] = scl4(v[i], s);
        dxy += dot4(v[i], bvv[i]);
        dx2 += sq4(v[i]);
    }
    float xy = warpSumF(dxy);
    float x2 = warpSumF(dx2);
    float y2 = g_b2[b2idx];
    float a = 1.0f + 2.0f*xy + y2;
    float c = 1.0f - x2;
    float invd = 1.0f / fmaxf(1.0f + 2.0f*xy + x2*y2, 1e-15f);
    float zz = 0.0f;
    #pragma unroll
    for (int i = 0; i < 4; i++) {
        VOP4(v[i], (a*v[i].x + c*bvv[i].x)*invd, (a*v[i].y + c*bvv[i].y)*invd,
                   (a*v[i].z + c*bvv[i].z)*invd, (a*v[i].w + c*bvv[i].w)*invd);
        zz += sq4(v[i]);
    }
    {
        float zn = sqrtf(warpSumF(zz) + 1e-30f);
        if (zn > MAXN) { float ps = MAXN / zn;
            #pragma unroll
            for (int i = 0; i < 4; i++) v[i] = scl4(v[i], ps); }
    }
    {
        float s0 = 0.0f;
        #pragma unroll
        for (int i = 0; i < 4; i++) s0 += sq4(v[i]);
        float n = sqrtf(warpSumF(s0) + 1e-30f);
        float lf = atanhf(fminf(n, MAXN)) / n;
        float s1 = 0.0f;
        #pragma unroll
        for (int i = 0; i < 4; i++) {
            VOP4(v[i], fmaxf(lf*v[i].x, 0.0f), fmaxf(lf*v[i].y, 0.0f),
                       fmaxf(lf*v[i].z, 0.0f), fmaxf(lf*v[i].w, 0.0f));
            s1 += sq4(v[i]);
        }
        float nr = sqrtf(warpSumF(s1) + 1e-30f);
        float ef = tanhf(nr) / nr;
        float s2 = 0.0f;
        #pragma unroll
        for (int i = 0; i < 4; i++) { v[i] = scl4(v[i], ef); s2 += sq4(v[i]); }
        float n2 = sqrtf(warpSumF(s2) + 1e-30f);
        if (n2 > MAXN) { float ps = MAXN / n2;
            #pragma unroll
            for (int i = 0; i < 4; i++) v[i] = scl4(v[i], ps); }
    }
    {
        float d1 = 0.0f, d2 = 0.0f, d3 = 0.0f;
        float4 rv[4];
        #pragma unroll
        for (int i = 0; i < 4; i++) {
            rv[i] = ((const float4*)(resid + row*ED))[lane + i*32];
            d1 += dot4(v[i], rv[i]);
            d2 += sq4(rv[i]);
            d3 += sq4(v[i]);
        }
        float rxy = warpSumF(d1);
        float ry2 = warpSumF(d2);
        float rx2 = warpSumF(d3);
        float ra = 1.0f + 2.0f*rxy + ry2;
        float rc = 1.0f - rx2;
        float rinv = 1.0f / fmaxf(1.0f + 2.0f*rxy + rx2*ry2, 1e-15f);
        float s3 = 0.0f;
        #pragma unroll
        for (int i = 0; i < 4; i++) {
            VOP4(v[i], (ra*v[i].x + rc*rv[i].x)*rinv, (ra*v[i].y + rc*rv[i].y)*rinv,
                       (ra*v[i].z + rc*rv[i].z)*rinv, (ra*v[i].w + rc*rv[i].w)*rinv);
            s3 += sq4(v[i]);
        }
        float zn = sqrtf(warpSumF(s3) + 1e-30f);
        if (zn > MAXN) { float ps = MAXN / zn;
            #pragma unroll
            for (int i = 0; i < 4; i++) v[i] = scl4(v[i], ps); }
    }
    #pragma unroll
    for (int i = 0; i < 4; i++) ((float4*)(outf + row*ED))[lane + i*32] = v[i];
}

// ---------------- MMA helpers ----------------
__device__ __forceinline__ void ldsm_x4(uint32_t &r0, uint32_t &r1, uint32_t &r2, uint32_t &r3, uint32_t addr) {
    asm volatile("ldmatrix.sync.aligned.m8n8.x4.shared.b16 {%0,%1,%2,%3}, [%4];"
                 : "=r"(r0), "=r"(r1), "=r"(r2), "=r"(r3) : "r"(addr));
}
__device__ __forceinline__ void ldsm_x4t(uint32_t &r0, uint32_t &r1, uint32_t &r2, uint32_t &r3, uint32_t addr) {
    asm volatile("ldmatrix.sync.aligned.m8n8.x4.trans.shared.b16 {%0,%1,%2,%3}, [%4];"
                 : "=r"(r0), "=r"(r1), "=r"(r2), "=r"(r3) : "r"(addr));
}
__device__ __forceinline__ void mma16816(float* c, const uint32_t* a, const uint32_t* b) {
    asm volatile("mma.sync.aligned.m16n8k16.row.col.f32.bf16.bf16.f32 "
                 "{%0,%1,%2,%3}, {%4,%5,%6,%7}, {%8,%9}, {%0,%1,%2,%3};"
                 : "+f"(c[0]), "+f"(c[1]), "+f"(c[2]), "+f"(c[3])
                 : "r"(a[0]), "r"(a[1]), "r"(a[2]), "r"(a[3]), "r"(b[0]), "r"(b[1]));
}
#define CP_ASYNC16(dst, src) asm volatile("cp.async.cg.shared.global [%0], [%1], 16;" :: "r"(dst), "l"(src))

// ---------------- tensor-core attention ----------------
#define ATT_SMEM 98304
__global__ void __launch_bounds__(256) attn_mma(
    const __nv_bfloat16* __restrict__ qh_g, const __nv_bfloat16* __restrict__ ql_g,
    float* __restrict__ o)
{
    extern __shared__ __nv_bfloat16 smbuf[];
    uint32_t smb = (uint32_t)__cvta_generic_to_shared(smbuf);
    const int tid = threadIdx.x;
    const int lane = tid & 31, w = tid >> 5;
    const int bh = blockIdx.x, b = bh >> 3, h = bh & 7;

    #pragma unroll
    for (int it = 0; it < 24; it++) {
        int idx = tid + (it << 8);
        int tensor = idx >> 10;
        int cid = idx & 1023;
        int r = cid >> 3, c = cid & 7;
        uint32_t dst = smb + tensor*16384 + r*128 + ((c ^ (r & 7)) << 4);
        const __nv_bfloat16* P = (tensor & 1) ? ql_g : qh_g;
        const __nv_bfloat16* src = P + ((size_t)r*BB + b)*QKVW + (size_t)(tensor>>1)*512 + h*HD + c*8;
        CP_ASYNC16(dst, src);
    }
    asm volatile("cp.async.commit_group;");
    asm volatile("cp.async.wait_group 0;");
    __syncthreads();

    const int quad = lane >> 3, r8 = lane & 7;

    float sc[16][4];
    #pragma unroll
    for (int n = 0; n < 16; n++)
        #pragma unroll
        for (int e = 0; e < 4; e++) sc[n][e] = 0.0f;

    #pragma unroll
    for (int kk = 0; kk < 4; kk++) {
        uint32_t qh_[4], ql_[4];
        int arow = w*16 + (quad & 1)*8 + r8;
        int achk = kk*2 + (quad >> 1);
        uint32_t aoff = (uint32_t)(arow*128 + ((achk ^ (arow & 7)) << 4));
        ldsm_x4(qh_[0], qh_[1], qh_[2], qh_[3], smb + aoff);
        ldsm_x4(ql_[0], ql_[1], ql_[2], ql_[3], smb + 16384 + aoff);
        #pragma unroll
        for (int nn = 0; nn < 8; nn++) {
            int krow = nn*16 + (quad >> 1)*8 + r8;
            int kchk = kk*2 + (quad & 1);
            uint32_t koff = (uint32_t)(krow*128 + ((kchk ^ (krow & 7)) << 4));
            uint32_t kh0[2], kh1[2], kl0[2], kl1[2];
            { uint32_t a0,a1,a2,a3; ldsm_x4(a0,a1,a2,a3, smb + 32768 + koff);
              kh0[0]=a0; kh0[1]=a1; kh1[0]=a2; kh1[1]=a3; }
            { uint32_t a0,a1,a2,a3; ldsm_x4(a0,a1,a2,a3, smb + 49152 + koff);
              kl0[0]=a0; kl0[1]=a1; kl1[0]=a2; kl1[1]=a3; }
            mma16816(sc[2*nn],   qh_, kh0);
            mma16816(sc[2*nn],   qh_, kl0);
            mma16816(sc[2*nn],   ql_, kh0);
            mma16816(sc[2*nn+1], qh_, kh1);
            mma16816(sc[2*nn+1], qh_, kl1);
            mma16816(sc[2*nn+1], ql_, kh1);
        }
    }

    float m0 = -1e30f, m1 = -1e30f;
    #pragma unroll
    for (int n = 0; n < 16; n++) {
        m0 = fmaxf(m0, fmaxf(sc[n][0], sc[n][1]));
        m1 = fmaxf(m1, fmaxf(sc[n][2], sc[n][3]));
    }
    m0 = fmaxf(m0, __shfl_xor_sync(0xffffffffu, m0, 1));
    m0 = fmaxf(m0, __shfl_xor_sync(0xffffffffu, m0, 2));
    m1 = fmaxf(m1, __shfl_xor_sync(0xffffffffu, m1, 1));
    m1 = fmaxf(m1, __shfl_xor_sync(0xffffffffu, m1, 2));
    float l0 = 0.0f, l1 = 0.0f;
    #pragma unroll
    for (int n = 0; n < 16; n++) {
        sc[n][0] = fexp((sc[n][0] - m0) * 0.125f); l0 += sc[n][0];
        sc[n][1] = fexp((sc[n][1] - m0) * 0.125f); l0 += sc[n][1];
        sc[n][2] = fexp((sc[n][2] - m1) * 0.125f); l1 += sc[n][2];
        sc[n][3] = fexp((sc[n][3] - m1) * 0.125f); l1 += sc[n][3];
    }
    l0 += __shfl_xor_sync(0xffffffffu, l0, 1);
    l0 += __shfl_xor_sync(0xffffffffu, l0, 2);
    l1 += __shfl_xor_sync(0xffffffffu, l1, 1);
    l1 += __shfl_xor_sync(0xffffffffu, l1, 2);
    float inv0 = 1.0f / l0, inv1 = 1.0f / l1;

    float oa[8][4];
    #pragma unroll
    for (int n = 0; n < 8; n++)
        #pragma unroll
        for (int e = 0; e < 4; e++) oa[n][e] = 0.0f;

    #pragma unroll
    for (int kt = 0; kt < 8; kt++) {
        uint32_t ph[4], pl[4];
        #pragma unroll
        for (int half = 0; half < 2; half++) {
            int n2 = 2*kt + half;
            float p0 = sc[n2][0], p1 = sc[n2][1], p2 = sc[n2][2], p3 = sc[n2][3];
            __nv_bfloat16 b0 = __float2bfloat16(p0), b1 = __float2bfloat16(p1);
            __nv_bfloat16 b2 = __float2bfloat16(p2), b3 = __float2bfloat16(p3);
            ph[half*2+0] = pack_bf2(p0, p1);
            ph[half*2+1] = pack_bf2(p2, p3);
            pl[half*2+0] = pack_bf2(p0 - __bfloat162float(b0), p1 - __bfloat162float(b1));
            pl[half*2+1] = pack_bf2(p2 - __bfloat162float(b2), p3 - __bfloat162float(b3));
        }
        #pragma unroll
        for (int nn = 0; nn < 4; nn++) {
            int vrow = kt*16 + (quad & 1)*8 + r8;
            int vchk = 2*nn + (quad >> 1);
            uint32_t voff = (uint32_t)(vrow*128 + ((vchk ^ (vrow & 7)) << 4));
            uint32_t vh0[2], vh1[2], vl0[2], vl1[2];
            { uint32_t a0,a1,a2,a3; ldsm_x4t(a0,a1,a2,a3, smb + 65536 + voff);
              vh0[0]=a0; vh0[1]=a1; vh1[0]=a2; vh1[1]=a3; }
            { uint32_t a0,a1,a2,a3; ldsm_x4t(a0,a1,a2,a3, smb + 81920 + voff);
              vl0[0]=a0; vl0[1]=a1; vl1[0]=a2; vl1[1]=a3; }
            mma16816(oa[2*nn],   ph, vh0);
            mma16816(oa[2*nn],   ph, vl0);
            mma16816(oa[2*nn],   pl, vh0);
            mma16816(oa[2*nn+1], ph, vh1);
            mma16816(oa[2*nn+1], ph, vl1);
            mma16816(oa[2*nn+1], pl, vh1);
        }
    }

    int g = lane >> 2, t2 = (lane & 3) * 2;
    int t0 = w*16 + g;
    #pragma unroll
    for (int n = 0; n < 8; n++) {
        size_t base0 = ((size_t)t0*BB + b)*ED + (size_t)h*HD + n*8 + t2;
        size_t base1 = ((size_t)(t0+8)*BB + b)*ED + (size_t)h*HD + n*8 + t2;
        *(float2*)(o + base0) = make_float2(oa[n][0]*inv0, oa[n][1]*inv0);
        *(float2*)(o + base1) = make_float2(oa[n][2]*inv1, oa[n][3]*inv1);
    }
}

// ================= bf16x3 HMMA GEMM =================
#define BM 128
#define BN 128
#define BK 32
#define TEN_B   8192
#define STAGE_B (4*TEN_B)
#define GEMM_SMEM (3*STAGE_B)

__device__ __forceinline__ uint32_t saddr(int r, int colElem) {
    return (uint32_t)(r*64 + ((((colElem >> 3) ^ ((r >> 1) & 3))) << 4));
}

__global__ void __launch_bounds__(256, 2) gemm_bf16x3(
    const __nv_bfloat16* __restrict__ Ah, const __nv_bfloat16* __restrict__ Al,
    const __nv_bfloat16* __restrict__ Wh, const __nv_bfloat16* __restrict__ Wl,
    float* __restrict__ C, int M, int N, int K)
{
    extern __shared__ __nv_bfloat16 smbuf[];
    const int tid = threadIdx.x;
    const int lane = tid & 31, w = tid >> 5;
    const int wm = w & 1, wn = w >> 1;
    const int rowBase = blockIdx.y * BM;
    const int colBase = blockIdx.x * BN;
    uint32_t smbase = (uint32_t)__cvta_generic_to_shared(smbuf);

    float acc[4][4][4];
    #pragma unroll
    for (int i = 0; i < 4; i++)
        #pragma unroll
        for (int j = 0; j < 4; j++)
            #pragma unroll
            for (int e = 0; e < 4; e++) acc[i][j][e] = 0.0f;

    auto load_stage = [&](int st, int k0) {
        uint32_t base = smbase + st * STAGE_B;
        #pragma unroll
        for (int it = 0; it < 8; it++) {
            int idx = tid + (it << 8);
            int tensor = idx >> 9;
            int cid = idx & 511;
            int r = cid >> 2, c = cid & 3;
            uint32_t dst = base + tensor * TEN_B
                         + (uint32_t)(r*64 + ((c ^ ((r >> 1) & 3)) << 4));
            const __nv_bfloat16* src;
            if (tensor == 0)      src = Ah + (size_t)(rowBase + r) * K + k0 + c * 8;
            else if (tensor == 1) src = Al + (size_t)(rowBase + r) * K + k0 + c * 8;
            else if (tensor == 2) src = Wh + (size_t)(colBase + r) * K + k0 + c * 8;
            else                  src = Wl + (size_t)(colBase + r) * K + k0 + c * 8;
            CP_ASYNC16(dst, src);
        }
        asm volatile("cp.async.commit_group;");
    };

    auto compute_stage = [&](int st) {
        uint32_t base = smbase + st * STAGE_B;
        uint32_t aH = base;
        uint32_t aL = base + 1*TEN_B;
        uint32_t wH = base + 2*TEN_B;
        uint32_t wL = base + 3*TEN_B;
        const int quad = lane >> 3, r8 = lane & 7;
        #pragma unroll
        for (int kk = 0; kk < BK; kk += 16) {
            uint32_t ah[4][4], al[4][4], bh[4][2], bl[4][2];
            #pragma unroll
            for (int i = 0; i < 4; i++) {
                int row = wm*64 + i*16 + (quad & 1)*8 + r8;
                int col = kk + (quad >> 1)*8;
                uint32_t off = saddr(row, col);
                ldsm_x4(ah[i][0], ah[i][1], ah[i][2], ah[i][3], aH + off);
                ldsm_x4(al[i][0], al[i][1], al[i][2], al[i][3], aL + off);
            }
            #pragma unroll
            for (int jj = 0; jj < 2; jj++) {
                int nr = wn*32 + jj*16 + (quad >> 1)*8 + r8;
                int kc = kk + (quad & 1)*8;
                uint32_t off = saddr(nr, kc);
                uint32_t a0,a1,a2,a3;
                ldsm_x4(a0,a1,a2,a3, wH + off);
                bh[2*jj][0]=a0; bh[2*jj][1]=a1; bh[2*jj+1][0]=a2; bh[2*jj+1][1]=a3;
                ldsm_x4(a0,a1,a2,a3, wL + off);
                bl[2*jj][0]=a0; bl[2*jj][1]=a1; bl[2*jj+1][0]=a2; bl[2*jj+1][1]=a3;
            }
            #pragma unroll
            for (int i = 0; i < 4; i++)
                #pragma unroll
                for (int j = 0; j < 4; j++) mma16816(acc[i][j], ah[i], bh[j]);
            #pragma unroll
            for (int i = 0; i < 4; i++)
                #pragma unroll
                for (int j = 0; j < 4; j++) mma16816(acc[i][j], ah[i], bl[j]);
            #pragma unroll
            for (int i = 0; i < 4; i++)
                #pragma unroll
                for (int j = 0; j < 4; j++) mma16816(acc[i][j], al[i], bh[j]);
        }
    };

    const int nkb = K / BK;
    load_stage(0, 0);
    load_stage(1, BK);
    for (int kb = 0; kb < nkb; kb++) {
        if (kb == nkb - 1) { asm volatile("cp.async.wait_group 0;"); }
        else               { asm volatile("cp.async.wait_group 1;"); }
        __syncthreads();
        if (kb + 2 < nkb) load_stage((kb + 2) % 3, (kb + 2) * BK);
        compute_stage(kb % 3);
    }

    const int g = lane >> 2, tg = lane & 3;
    #pragma unroll
    for (int i = 0; i < 4; i++) {
        int row = rowBase + wm*64 + i*16 + g;
        #pragma unroll
        for (int j = 0; j < 4; j++) {
            int col = colBase + wn*32 + j*8 + tg*2;
            *(float2*)(C + (size_t)row * N + col)       = make_float2(acc[i][j][0], acc[i][j][1]);
            *(float2*)(C + (size_t)(row + 8) * N + col) = make_float2(acc[i][j][2], acc[i][j][3]);
        }
    }
}

// ---------------- launch ----------------
extern "C" void kernel_launch(void* const* d_in, const int* in_sizes, int n_in,
                              void* d_out, int out_size)
{
    const float* x    = (const float*)d_in[0];
    const float* l1g  = (const float*)d_in[1];
    const float* l1b  = (const float*)d_in[2];
    const float* l2g  = (const float*)d_in[3];
    const float* l2b  = (const float*)d_in[4];
    const float* Wq   = (const float*)d_in[5];
    const float* bq   = (const float*)d_in[6];
    const float* Wk   = (const float*)d_in[7];
    const float* bk   = (const float*)d_in[8];
    const float* Wv   = (const float*)d_in[9];
    const float* bv   = (const float*)d_in[10];
    const float* Wo   = (const float*)d_in[11];
    const float* bo   = (const float*)d_in[12];
    const float* W1   = (const float*)d_in[13];
    const float* b1   = (const float*)d_in[14];
    const float* W2   = (const float*)d_in[15];
    const float* b2   = (const float*)d_in[16];
    float* out = (float*)d_out;

    float *qkv, *ob, *h1, *big, *n0, *no, *nh2, *nh3, *bsq;
    __nv_bfloat16 *xh, *xl, *wh, *wl;
    cudaGetSymbolAddress((void**)&qkv, g_qkv);
    cudaGetSymbolAddress((void**)&ob,  g_o);
    cudaGetSymbolAddress((void**)&h1,  g_h1);
    cudaGetSymbolAddress((void**)&big, g_big);
    cudaGetSymbolAddress((void**)&xh,  g_xh);
    cudaGetSymbolAddress((void**)&xl,  g_xl);
    cudaGetSymbolAddress((void**)&wh,  g_wh);
    cudaGetSymbolAddress((void**)&wl,  g_wl);
    cudaGetSymbolAddress((void**)&n0,  g_n0);
    cudaGetSymbolAddress((void**)&no,  g_no);
    cudaGetSymbolAddress((void**)&nh2, g_nh2);
    cudaGetSymbolAddress((void**)&nh3, g_nh3);
    cudaGetSymbolAddress((void**)&bsq, g_b2);

    cudaFuncSetAttribute(gemm_bf16x3, cudaFuncAttributeMaxDynamicSharedMemorySize, GEMM_SMEM);
    cudaFuncSetAttribute(attn_mma, cudaFuncAttributeMaxDynamicSharedMemorySize, ATT_SMEM);

    split_all<<<dim3(1024, 6), 256>>>(Wq, Wk, Wv, Wo, W1, W2,
                                      bq, bk, bv, bo, b1, b2, wh, wl, bsq);
    ln1_w<<<NR/8, 256>>>(x, l1g, l1b, xh, xl, n0);

    gemm_bf16x3<<<dim3(QKVW/BN, NR/BM), 256, GEMM_SMEM>>>(xh, xl, wh + WQ0, wl + WQ0, qkv, NR, QKVW, ED);
    manlin_qkv_w<<<dim3(NR/8, 3), 256>>>(qkv, n0, bq, bk, bv, xh, xl);

    attn_mma<<<BB * NH, 256, ATT_SMEM>>>(xh, xl, ob);
    expmap_w<<<NR/8, 256>>>(ob, xh, xl, no);

    gemm_bf16x3<<<dim3(ED/BN, NR/BM), 256, GEMM_SMEM>>>(xh, xl, wh + WO0, wl + WO0, big, NR, ED, ED);
    manlin_ln_w<<<NR/8, 256>>>(big, no, bo, 3, x, h1, l2g, l2b, xh, xl, nh2);

    gemm_bf16x3<<<dim3(FD/BN, NR/BM), 256, GEMM_SMEM>>>(xh, xl, wh + W10, wl + W10, big, NR, FD, ED);
    manlin_fc1_w<<<NR/4, 128>>>(big, nh2, b1, xh, xl, nh3);

    gemm_bf16x3<<<dim3(ED/BN, NR/BM), 256, GEMM_SMEM>>>(xh, xl, wh + W20, wl + W20, qkv, NR, ED, FD);
    manlin_final_w<<<NR/8, 256>>>(qkv, nh3, b2, 5, h1, out);
}